// round 1
// baseline (speedup 1.0000x reference)
#include <cuda_runtime.h>
#include <cuda_bf16.h>
#include <math.h>

// Problem dims (fixed by reference)
#define Bn 32
#define Dn 512
#define Tn 32
#define Nn 64
#define Hn 8
#define DKn 64
#define FFn 2048
#define MTOT (Bn * Nn * Tn)          // 65536 token rows
#define SCALE_F 0.022097086912079608f // (DK*T)^-0.5 = 1/sqrt(2048)
#define LN_EPS 1e-5f

// ------------------------------------------------------------------
// Scratch (device globals; allocation-free per harness rules)
// ------------------------------------------------------------------
__device__ float g_XR[(size_t)MTOT * Dn];   // xr  (B,N,T,D) row-major tokens
__device__ float g_Qm[(size_t)MTOT * Dn];
__device__ float g_Km[(size_t)MTOT * Dn];
__device__ float g_Vm[(size_t)MTOT * Dn];
__device__ float g_ATT[(size_t)MTOT * Dn];
__device__ float g_Y1[(size_t)MTOT * Dn];   // xr + attn_out@Wo + bo
__device__ float g_X1[(size_t)MTOT * Dn];   // layernorm output
__device__ float g_H[(size_t)MTOT * FFn];   // FFN hidden
__device__ float g_FF[(size_t)MTOT * Dn];   // x1 + ffn (pre-transpose)
__device__ float2 g_part[Bn * 32];
__device__ float2 g_stats[Bn];

// ------------------------------------------------------------------
// prep: x (B,D,T,N) -> XR (B,N,T,D)   [tiled transpose per (b,t)]
// ------------------------------------------------------------------
__global__ void prep_xr(const float* __restrict__ x, float* __restrict__ XR) {
    __shared__ float tile[32][33];
    int bt = blockIdx.z;
    int b = bt >> 5, t = bt & 31;
    int d0 = blockIdx.x * 32, n0 = blockIdx.y * 32;
    size_t bbase = (size_t)b * (Dn * Tn * Nn);
#pragma unroll
    for (int i = 0; i < 4; i++) {
        int d = d0 + threadIdx.y + i * 8;
        tile[threadIdx.y + i * 8][threadIdx.x] =
            x[bbase + (size_t)d * (Tn * Nn) + t * Nn + n0 + threadIdx.x];
    }
    __syncthreads();
#pragma unroll
    for (int i = 0; i < 4; i++) {
        int n = n0 + threadIdx.y + i * 8;
        XR[bbase + (size_t)n * (Tn * Dn) + t * Dn + d0 + threadIdx.x] =
            tile[threadIdx.x][threadIdx.y + i * 8];
    }
}

// ------------------------------------------------------------------
// out transpose: FF (B,N,T,D) -> out (B,D,T,N)
// ------------------------------------------------------------------
__global__ void out_tr(const float* __restrict__ FF, float* __restrict__ out) {
    __shared__ float tile[32][33];
    int bt = blockIdx.z;
    int b = bt >> 5, t = bt & 31;
    int d0 = blockIdx.x * 32, n0 = blockIdx.y * 32;
    size_t bbase = (size_t)b * (Dn * Tn * Nn);
#pragma unroll
    for (int i = 0; i < 4; i++) {
        int n = n0 + threadIdx.y + i * 8;
        tile[threadIdx.y + i * 8][threadIdx.x] =
            FF[bbase + (size_t)n * (Tn * Dn) + t * Dn + d0 + threadIdx.x];
    }
    __syncthreads();
#pragma unroll
    for (int i = 0; i < 4; i++) {
        int d = d0 + threadIdx.y + i * 8;
        out[bbase + (size_t)d * (Tn * Nn) + t * Nn + n0 + threadIdx.x] =
            tile[threadIdx.x][threadIdx.y + i * 8];
    }
}

// ------------------------------------------------------------------
// Generic NT SGEMM: C[M x N] = A[M x K] * W[N x K]^T (+pe on A)(+bias)(relu)(+resid)
// 128x128 block tile, BK=8, 256 threads, 8x8 per thread.
// ------------------------------------------------------------------
template <bool PE, bool BIAS, bool RELU, bool RESID>
__global__ void __launch_bounds__(256, 2)
gemm_nt(const float* __restrict__ A, const float* __restrict__ W,
        const float* __restrict__ bias, const float* __restrict__ Rsd,
        const float* __restrict__ pe, float* __restrict__ C,
        int Ncols, int K) {
    __shared__ float As[8][128];
    __shared__ float Ws[8][128];

    const int tid = threadIdx.x;
    const int rowBase = blockIdx.y * 128;
    const int colBase = blockIdx.x * 128;
    const int lr = tid >> 1;          // 0..127
    const int lc = (tid & 1) * 4;     // 0 or 4
    const int tm = (tid >> 4) * 8;
    const int tn = (tid & 15) * 8;

    float acc[8][8];
#pragma unroll
    for (int i = 0; i < 8; i++)
#pragma unroll
        for (int j = 0; j < 8; j++) acc[i][j] = 0.f;

    const float* Aptr = A + (size_t)(rowBase + lr) * K + lc;
    const float* Wptr = W + (size_t)(colBase + lr) * K + lc;
    const float* peptr = nullptr;
    if (PE) {
        int n = ((rowBase + lr) >> 5) & 63;  // row = b*2048 + n*32 + t
        peptr = pe + n * Dn + lc;
    }

    for (int k0 = 0; k0 < K; k0 += 8) {
        float4 av = *(const float4*)(Aptr + k0);
        float4 wv = *(const float4*)(Wptr + k0);
        if (PE) {
            float4 p = *(const float4*)(peptr + k0);
            av.x += p.x; av.y += p.y; av.z += p.z; av.w += p.w;
        }
        __syncthreads();
        As[lc + 0][lr] = av.x; As[lc + 1][lr] = av.y;
        As[lc + 2][lr] = av.z; As[lc + 3][lr] = av.w;
        Ws[lc + 0][lr] = wv.x; Ws[lc + 1][lr] = wv.y;
        Ws[lc + 2][lr] = wv.z; Ws[lc + 3][lr] = wv.w;
        __syncthreads();
#pragma unroll
        for (int kk = 0; kk < 8; kk++) {
            float a[8], bb[8];
            *(float4*)(a)      = *(const float4*)&As[kk][tm];
            *(float4*)(a + 4)  = *(const float4*)&As[kk][tm + 4];
            *(float4*)(bb)     = *(const float4*)&Ws[kk][tn];
            *(float4*)(bb + 4) = *(const float4*)&Ws[kk][tn + 4];
#pragma unroll
            for (int i = 0; i < 8; i++)
#pragma unroll
                for (int j = 0; j < 8; j++) acc[i][j] = fmaf(a[i], bb[j], acc[i][j]);
        }
    }

#pragma unroll
    for (int i = 0; i < 8; i++) {
        size_t row = (size_t)(rowBase + tm + i);
#pragma unroll
        for (int j = 0; j < 8; j += 4) {
            int col = colBase + tn + j;
            float4 v = make_float4(acc[i][j], acc[i][j + 1], acc[i][j + 2], acc[i][j + 3]);
            if (BIAS) {
                float4 bv = *(const float4*)&bias[col];
                v.x += bv.x; v.y += bv.y; v.z += bv.z; v.w += bv.w;
            }
            if (RELU) {
                v.x = fmaxf(v.x, 0.f); v.y = fmaxf(v.y, 0.f);
                v.z = fmaxf(v.z, 0.f); v.w = fmaxf(v.w, 0.f);
            }
            if (RESID) {
                float4 rv = *(const float4*)&Rsd[row * Ncols + col];
                v.x += rv.x; v.y += rv.y; v.z += rv.z; v.w += rv.w;
            }
            *(float4*)&C[row * Ncols + col] = v;
        }
    }
}

// ------------------------------------------------------------------
// Attention: one block per (b,h). S = Q K^T * scale; softmax*hw + adj; O = S V.
// Feature dim f = t*DK+dk handled in 32 chunks of 64.
// ------------------------------------------------------------------
__global__ void __launch_bounds__(256)
attn_kernel(const float* __restrict__ Qm, const float* __restrict__ Km,
            const float* __restrict__ Vm, const float* __restrict__ adj,
            const float* __restrict__ hw, float* __restrict__ ATT) {
    __shared__ float bufA[64][68];  // phase1: Q^T [dk][n] ; phase2: V [m][dk]
    __shared__ float bufB[64][68];  // phase1: K^T [dk][m] ; then S [n][m]

    const int b = blockIdx.x >> 3;
    const int h = blockIdx.x & 7;
    const int tid = threadIdx.x;
    const int ty = tid >> 4;   // 0..15 -> n block
    const int tx = tid & 15;   // 0..15 -> m/dk block
    const int dkl = tid & 63;
    const int nl0 = tid >> 6;  // 0..3

    const size_t base = ((size_t)b * 2048) * Dn + h * DKn;

    float acc[4][4];
#pragma unroll
    for (int i = 0; i < 4; i++)
#pragma unroll
        for (int j = 0; j < 4; j++) acc[i][j] = 0.f;

    // ---- phase 1: scores accumulation over 32 feature chunks ----
    for (int t0 = 0; t0 < 32; t0++) {
        __syncthreads();
        for (int nn = nl0; nn < 64; nn += 4) {
            size_t off = base + (size_t)(nn * 32 + t0) * Dn + dkl;
            bufA[dkl][nn] = Qm[off];
            bufB[dkl][nn] = Km[off];
        }
        __syncthreads();
#pragma unroll 8
        for (int dk = 0; dk < 64; dk++) {
            float4 q = *(const float4*)&bufA[dk][ty * 4];
            float4 k = *(const float4*)&bufB[dk][tx * 4];
            acc[0][0] = fmaf(q.x, k.x, acc[0][0]); acc[0][1] = fmaf(q.x, k.y, acc[0][1]);
            acc[0][2] = fmaf(q.x, k.z, acc[0][2]); acc[0][3] = fmaf(q.x, k.w, acc[0][3]);
            acc[1][0] = fmaf(q.y, k.x, acc[1][0]); acc[1][1] = fmaf(q.y, k.y, acc[1][1]);
            acc[1][2] = fmaf(q.y, k.z, acc[1][2]); acc[1][3] = fmaf(q.y, k.w, acc[1][3]);
            acc[2][0] = fmaf(q.z, k.x, acc[2][0]); acc[2][1] = fmaf(q.z, k.y, acc[2][1]);
            acc[2][2] = fmaf(q.z, k.z, acc[2][2]); acc[2][3] = fmaf(q.z, k.w, acc[2][3]);
            acc[3][0] = fmaf(q.w, k.x, acc[3][0]); acc[3][1] = fmaf(q.w, k.y, acc[3][1]);
            acc[3][2] = fmaf(q.w, k.z, acc[3][2]); acc[3][3] = fmaf(q.w, k.w, acc[3][3]);
        }
    }

    // stash S (scaled) into bufB
    __syncthreads();
#pragma unroll
    for (int i = 0; i < 4; i++)
#pragma unroll
        for (int j = 0; j < 4; j++)
            bufB[ty * 4 + i][tx * 4 + j] = acc[i][j] * SCALE_F;
    __syncthreads();

    // ---- softmax (each warp owns 8 rows) ----
    {
        const int w = tid >> 5, lane = tid & 31;
        const float hwv = hw[h];
        for (int rr = 0; rr < 8; rr++) {
            int row = w * 8 + rr;
            float v0 = bufB[row][lane];
            float v1 = bufB[row][lane + 32];
            float mx = fmaxf(v0, v1);
#pragma unroll
            for (int o = 16; o; o >>= 1) mx = fmaxf(mx, __shfl_xor_sync(0xffffffffu, mx, o));
            float e0 = __expf(v0 - mx), e1 = __expf(v1 - mx);
            float s = e0 + e1;
#pragma unroll
            for (int o = 16; o; o >>= 1) s += __shfl_xor_sync(0xffffffffu, s, o);
            float inv = 1.f / s;
            size_t ab = (size_t)h * 4096 + row * 64;
            bufB[row][lane]      = e0 * inv * hwv + adj[ab + lane];
            bufB[row][lane + 32] = e1 * inv * hwv + adj[ab + 32 + lane];
        }
    }

    // ---- phase 2: O = attn @ V, per feature chunk ----
    for (int t0 = 0; t0 < 32; t0++) {
        __syncthreads();
        for (int mm = nl0; mm < 64; mm += 4) {
            bufA[mm][dkl] = Vm[base + (size_t)(mm * 32 + t0) * Dn + dkl];
        }
        __syncthreads();
        float o2[4][4];
#pragma unroll
        for (int i = 0; i < 4; i++)
#pragma unroll
            for (int j = 0; j < 4; j++) o2[i][j] = 0.f;
#pragma unroll 8
        for (int m = 0; m < 64; m++) {
            float4 v = *(const float4*)&bufA[m][tx * 4];
            float s0 = bufB[ty * 4 + 0][m];
            float s1 = bufB[ty * 4 + 1][m];
            float s2 = bufB[ty * 4 + 2][m];
            float s3 = bufB[ty * 4 + 3][m];
            o2[0][0] = fmaf(s0, v.x, o2[0][0]); o2[0][1] = fmaf(s0, v.y, o2[0][1]);
            o2[0][2] = fmaf(s0, v.z, o2[0][2]); o2[0][3] = fmaf(s0, v.w, o2[0][3]);
            o2[1][0] = fmaf(s1, v.x, o2[1][0]); o2[1][1] = fmaf(s1, v.y, o2[1][1]);
            o2[1][2] = fmaf(s1, v.z, o2[1][2]); o2[1][3] = fmaf(s1, v.w, o2[1][3]);
            o2[2][0] = fmaf(s2, v.x, o2[2][0]); o2[2][1] = fmaf(s2, v.y, o2[2][1]);
            o2[2][2] = fmaf(s2, v.z, o2[2][2]); o2[2][3] = fmaf(s2, v.w, o2[2][3]);
            o2[3][0] = fmaf(s3, v.x, o2[3][0]); o2[3][1] = fmaf(s3, v.y, o2[3][1]);
            o2[3][2] = fmaf(s3, v.z, o2[3][2]); o2[3][3] = fmaf(s3, v.w, o2[3][3]);
        }
#pragma unroll
        for (int i = 0; i < 4; i++) {
            int n = ty * 4 + i;
            size_t off = base + (size_t)(n * 32 + t0) * Dn + tx * 4;
            *(float4*)&ATT[off] = make_float4(o2[i][0], o2[i][1], o2[i][2], o2[i][3]);
        }
    }
}

// ------------------------------------------------------------------
// LayerNorm over (N,T,D) per batch sample: two-stage deterministic reduction
// ------------------------------------------------------------------
__global__ void ln_partial(const float* __restrict__ Y1, float2* __restrict__ part) {
    const int c = blockIdx.x, b = blockIdx.y;
    const float* p = Y1 + (size_t)b * 1048576 + (size_t)c * 32768;
    float s = 0.f, s2 = 0.f;
    for (int i = threadIdx.x; i < 32768; i += 256) {
        float v = p[i];
        s += v; s2 += v * v;
    }
    __shared__ float rs[256], rs2[256];
    rs[threadIdx.x] = s; rs2[threadIdx.x] = s2;
    __syncthreads();
    for (int o = 128; o; o >>= 1) {
        if (threadIdx.x < o) {
            rs[threadIdx.x] += rs[threadIdx.x + o];
            rs2[threadIdx.x] += rs2[threadIdx.x + o];
        }
        __syncthreads();
    }
    if (threadIdx.x == 0) part[b * 32 + c] = make_float2(rs[0], rs2[0]);
}

__global__ void ln_final(const float2* __restrict__ part, float2* __restrict__ stats) {
    int b = threadIdx.x;
    if (b < Bn) {
        float s = 0.f, s2 = 0.f;
        for (int c = 0; c < 32; c++) {
            float2 p = part[b * 32 + c];
            s += p.x; s2 += p.y;
        }
        const float invN = 1.0f / 1048576.0f;
        float mean = s * invN;
        float var = s2 * invN - mean * mean;
        stats[b] = make_float2(mean, rsqrtf(var + LN_EPS));
    }
}

__global__ void ln_apply(const float* __restrict__ Y1, const float2* __restrict__ stats,
                         const float* __restrict__ g1, const float* __restrict__ be1,
                         float* __restrict__ X1) {
    size_t e = ((size_t)blockIdx.x * blockDim.x + threadIdx.x) * 4;
    float2 st = stats[e >> 20];
    size_t gi = e & 1048575;  // (n*T + t)*D + d
    float4 y = *(const float4*)&Y1[e];
    float4 g = *(const float4*)&g1[gi];
    float4 be = *(const float4*)&be1[gi];
    float4 o;
    o.x = (y.x - st.x) * st.y * g.x + be.x;
    o.y = (y.y - st.x) * st.y * g.y + be.y;
    o.z = (y.z - st.x) * st.y * g.z + be.z;
    o.w = (y.w - st.x) * st.y * g.w + be.w;
    *(float4*)&X1[e] = o;
}

// ------------------------------------------------------------------
// launch
// ------------------------------------------------------------------
extern "C" void kernel_launch(void* const* d_in, const int* in_sizes, int n_in,
                              void* d_out, int out_size) {
    const float* x   = (const float*)d_in[0];
    const float* Wq  = (const float*)d_in[1];
    const float* bq  = (const float*)d_in[2];
    const float* Wk  = (const float*)d_in[3];
    const float* bk  = (const float*)d_in[4];
    const float* Wv  = (const float*)d_in[5];
    const float* bv  = (const float*)d_in[6];
    const float* Wo  = (const float*)d_in[7];
    const float* bo  = (const float*)d_in[8];
    const float* W1  = (const float*)d_in[9];
    const float* b1  = (const float*)d_in[10];
    const float* W2  = (const float*)d_in[11];
    const float* b2  = (const float*)d_in[12];
    const float* g1  = (const float*)d_in[13];
    const float* be1 = (const float*)d_in[14];
    const float* adj = (const float*)d_in[15];
    const float* hw  = (const float*)d_in[16];
    const float* pe  = (const float*)d_in[17];
    float* out = (float*)d_out;

    void *pXR, *pQ, *pK, *pV, *pATT, *pY1, *pX1, *pH, *pFF, *pPart, *pStats;
    cudaGetSymbolAddress(&pXR, g_XR);
    cudaGetSymbolAddress(&pQ, g_Qm);
    cudaGetSymbolAddress(&pK, g_Km);
    cudaGetSymbolAddress(&pV, g_Vm);
    cudaGetSymbolAddress(&pATT, g_ATT);
    cudaGetSymbolAddress(&pY1, g_Y1);
    cudaGetSymbolAddress(&pX1, g_X1);
    cudaGetSymbolAddress(&pH, g_H);
    cudaGetSymbolAddress(&pFF, g_FF);
    cudaGetSymbolAddress(&pPart, g_part);
    cudaGetSymbolAddress(&pStats, g_stats);
    float* XR = (float*)pXR;
    float* Qm = (float*)pQ;
    float* Km = (float*)pK;
    float* Vm = (float*)pV;
    float* ATT = (float*)pATT;
    float* Y1 = (float*)pY1;
    float* X1 = (float*)pX1;
    float* Hh = (float*)pH;
    float* FFo = (float*)pFF;
    float2* part = (float2*)pPart;
    float2* stats = (float2*)pStats;

    dim3 trGrid(16, 2, Bn * Tn);
    dim3 trBlk(32, 8);

    // 1. transpose input -> XR
    prep_xr<<<trGrid, trBlk>>>(x, XR);

    // 2. QKV projections (PE fused into A-load for Q,K)
    dim3 gD(Dn / 128, MTOT / 128);
    gemm_nt<true, true, false, false><<<gD, 256>>>(XR, Wq, bq, nullptr, pe, Qm, Dn, Dn);
    gemm_nt<true, true, false, false><<<gD, 256>>>(XR, Wk, bk, nullptr, pe, Km, Dn, Dn);
    gemm_nt<false, true, false, false><<<gD, 256>>>(XR, Wv, bv, nullptr, nullptr, Vm, Dn, Dn);

    // 3. attention
    attn_kernel<<<Bn * Hn, 256>>>(Qm, Km, Vm, adj, hw, ATT);

    // 4. output projection + residual (xr + y)
    gemm_nt<false, true, false, true><<<gD, 256>>>(ATT, Wo, bo, XR, nullptr, Y1, Dn, Dn);

    // 5. layernorm over (N,T,D) per batch
    ln_partial<<<dim3(32, Bn), 256>>>(Y1, part);
    ln_final<<<1, 32>>>(part, stats);
    ln_apply<<<(MTOT * Dn / 4) / 256, 256>>>(Y1, stats, g1, be1, X1);

    // 6. FFN
    dim3 gFF(FFn / 128, MTOT / 128);
    gemm_nt<false, true, true, false><<<gFF, 256>>>(X1, W1, b1, nullptr, nullptr, Hh, FFn, Dn);
    gemm_nt<false, true, false, true><<<gD, 256>>>(Hh, W2, b2, X1, nullptr, FFo, Dn, FFn);

    // 7. transpose to output layout (B,D,T,N)
    out_tr<<<trGrid, trBlk>>>(FFo, out);
}

// round 3
// speedup vs baseline: 1.6915x; 1.6915x over previous
#include <cuda_runtime.h>
#include <cuda_bf16.h>
#include <cstdint>
#include <math.h>

// Problem dims
#define Bn 32
#define Dn 512
#define Tn 32
#define Nn 64
#define Hn 8
#define DKn 64
#define FFn 2048
#define MTOT (Bn * Nn * Tn)
#define SCALE_F 0.022097086912079608f
#define LN_EPS 1e-5f

// ------------------------------------------------------------------
// Scratch
// ------------------------------------------------------------------
__device__ float g_XR[(size_t)MTOT * Dn];
__device__ float g_Qm[(size_t)MTOT * Dn];
__device__ float g_Km[(size_t)MTOT * Dn];
__device__ float g_Vm[(size_t)MTOT * Dn];
__device__ float g_Y1[(size_t)MTOT * Dn];
__device__ float g_X1[(size_t)MTOT * Dn];
__device__ float g_FF[(size_t)MTOT * Dn];
__device__ __nv_bfloat16 g_XRh[(size_t)MTOT * Dn], g_XRl[(size_t)MTOT * Dn];
__device__ __nv_bfloat16 g_XPEh[(size_t)MTOT * Dn], g_XPEl[(size_t)MTOT * Dn];
__device__ __nv_bfloat16 g_ATTh[(size_t)MTOT * Dn], g_ATTl[(size_t)MTOT * Dn];
__device__ __nv_bfloat16 g_X1h[(size_t)MTOT * Dn], g_X1l[(size_t)MTOT * Dn];
__device__ __nv_bfloat16 g_Hh[(size_t)MTOT * FFn], g_Hl[(size_t)MTOT * FFn];
__device__ __nv_bfloat16 g_Wqh[Dn * Dn], g_Wql[Dn * Dn];
__device__ __nv_bfloat16 g_Wkh[Dn * Dn], g_Wkl[Dn * Dn];
__device__ __nv_bfloat16 g_Wvh[Dn * Dn], g_Wvl[Dn * Dn];
__device__ __nv_bfloat16 g_Woh[Dn * Dn], g_Wol[Dn * Dn];
__device__ __nv_bfloat16 g_W1h[FFn * Dn], g_W1l[FFn * Dn];
__device__ __nv_bfloat16 g_W2h[Dn * FFn], g_W2l[Dn * FFn];
__device__ float2 g_part[Bn * 32];
__device__ float2 g_stats[Bn];

// ------------------------------------------------------------------
// PTX helpers (compute_100-safe: cp.async + ldmatrix + mma.sync only)
// ------------------------------------------------------------------
__device__ __forceinline__ uint32_t smem_u32(const void* p) {
    uint32_t a;
    asm("{ .reg .u64 t; cvta.to.shared.u64 t, %1; cvt.u32.u64 %0, t; }" : "=r"(a) : "l"(p));
    return a;
}
__device__ __forceinline__ void cpasync16(uint32_t dst, const void* src) {
    asm volatile("cp.async.cg.shared.global [%0], [%1], 16;" :: "r"(dst), "l"(src));
}
#define CP_COMMIT() asm volatile("cp.async.commit_group;" ::: "memory")
#define CP_WAIT2() asm volatile("cp.async.wait_group 2;" ::: "memory")

#define LDSM4(r0, r1, r2, r3, addr) \
    asm volatile("ldmatrix.sync.aligned.m8n8.x4.shared.b16 {%0,%1,%2,%3}, [%4];" \
                 : "=r"(r0), "=r"(r1), "=r"(r2), "=r"(r3) : "r"(addr))

#define MMA_BF16(d, a, b) \
    asm volatile("mma.sync.aligned.m16n8k16.row.col.f32.bf16.bf16.f32 " \
                 "{%0,%1,%2,%3}, {%4,%5,%6,%7}, {%8,%9}, {%0,%1,%2,%3};" \
                 : "+f"((d)[0]), "+f"((d)[1]), "+f"((d)[2]), "+f"((d)[3]) \
                 : "r"((a)[0]), "r"((a)[1]), "r"((a)[2]), "r"((a)[3]), \
                   "r"((b)[0]), "r"((b)[1]))

__device__ __forceinline__ void split2(float a, float b, __nv_bfloat162& h, __nv_bfloat162& l) {
    h = __floats2bfloat162_rn(a, b);
    l = __floats2bfloat162_rn(a - __low2float(h), b - __high2float(h));
}

// ------------------------------------------------------------------
// prep: x (B,D,T,N) -> XR fp32, XRh/l, XPEh/l = xr + pe
// ------------------------------------------------------------------
__global__ void prep_xr(const float* __restrict__ x, const float* __restrict__ pe,
                        float* __restrict__ XR,
                        __nv_bfloat16* __restrict__ XRh, __nv_bfloat16* __restrict__ XRl,
                        __nv_bfloat16* __restrict__ XPEh, __nv_bfloat16* __restrict__ XPEl) {
    __shared__ float tile[32][33];
    int bt = blockIdx.z;
    int b = bt >> 5, t = bt & 31;
    int d0 = blockIdx.x * 32, n0 = blockIdx.y * 32;
    size_t bbase = (size_t)b * (Dn * Tn * Nn);
#pragma unroll
    for (int i = 0; i < 4; i++) {
        int d = d0 + threadIdx.y + i * 8;
        tile[threadIdx.y + i * 8][threadIdx.x] =
            x[bbase + (size_t)d * (Tn * Nn) + t * Nn + n0 + threadIdx.x];
    }
    __syncthreads();
    int d = d0 + threadIdx.x;
#pragma unroll
    for (int i = 0; i < 4; i++) {
        int n = n0 + threadIdx.y + i * 8;
        float v = tile[threadIdx.x][threadIdx.y + i * 8];
        size_t idx = bbase + (size_t)n * (Tn * Dn) + t * Dn + d;
        XR[idx] = v;
        __nv_bfloat16 h = __float2bfloat16(v);
        XRh[idx] = h;
        XRl[idx] = __float2bfloat16(v - __bfloat162float(h));
        float vp = v + pe[n * Dn + d];
        __nv_bfloat16 hp = __float2bfloat16(vp);
        XPEh[idx] = hp;
        XPEl[idx] = __float2bfloat16(vp - __bfloat162float(hp));
    }
}

__global__ void out_tr(const float* __restrict__ FF, float* __restrict__ out) {
    __shared__ float tile[32][33];
    int bt = blockIdx.z;
    int b = bt >> 5, t = bt & 31;
    int d0 = blockIdx.x * 32, n0 = blockIdx.y * 32;
    size_t bbase = (size_t)b * (Dn * Tn * Nn);
#pragma unroll
    for (int i = 0; i < 4; i++) {
        int n = n0 + threadIdx.y + i * 8;
        tile[threadIdx.y + i * 8][threadIdx.x] =
            FF[bbase + (size_t)n * (Tn * Dn) + t * Dn + d0 + threadIdx.x];
    }
    __syncthreads();
#pragma unroll
    for (int i = 0; i < 4; i++) {
        int d = d0 + threadIdx.y + i * 8;
        out[bbase + (size_t)d * (Tn * Nn) + t * Nn + n0 + threadIdx.x] =
            tile[threadIdx.x][threadIdx.y + i * 8];
    }
}

// weight fp32 -> hi/lo bf16
__global__ void conv_hl(const float* __restrict__ W, __nv_bfloat16* __restrict__ Wh,
                        __nv_bfloat16* __restrict__ Wl, int n) {
    int i = (blockIdx.x * blockDim.x + threadIdx.x) * 4;
    if (i >= n) return;
    float4 v = *(const float4*)&W[i];
    __nv_bfloat162 h0, l0, h1, l1;
    split2(v.x, v.y, h0, l0);
    split2(v.z, v.w, h1, l1);
    *(__nv_bfloat162*)&Wh[i] = h0; *(__nv_bfloat162*)&Wh[i + 2] = h1;
    *(__nv_bfloat162*)&Wl[i] = l0; *(__nv_bfloat162*)&Wl[i + 2] = l1;
}

// ------------------------------------------------------------------
// mma.sync split-bf16 GEMM: C[M x Ncols] = A * W^T  (3-term hi/lo)
// 128x128 tile, BK=32, 3-stage cp.async, 256 threads (8 warps, 2x4),
// warp tile 64x32. SMEM pitch 80B -> conflict-free ldmatrix.
// ------------------------------------------------------------------
#define PITCHB 80
#define TILEB (128 * PITCHB)       // 10240 B
#define OFF_AH 0
#define OFF_AL TILEB
#define OFF_BH (2 * TILEB)
#define OFF_BL (3 * TILEB)
#define STAGEB (4 * TILEB)         // 40960 B
#define GEMM_DSMEM (3 * STAGEB)    // 122880 B

__device__ __forceinline__ void load_tile128(uint32_t sdst, const __nv_bfloat16* __restrict__ g,
                                             size_t row0, int K, int k0, int tid) {
    int r = tid & 63;
    int c = tid >> 6;  // 0..3 (16B chunks)
    const char* gp = (const char*)(g + (row0 + r) * (size_t)K + k0) + c * 16;
    uint32_t dst = sdst + r * PITCHB + c * 16;
    size_t gstep = (size_t)64 * K * 2;
    cpasync16(dst, gp);
    cpasync16(dst + 64 * PITCHB, gp + gstep);
}

template <bool BIAS_, bool RELU_, bool RESID_, bool OUTF_, bool OUTHL_>
__global__ void __launch_bounds__(256, 1)
gemm_mma(const __nv_bfloat16* __restrict__ Ah, const __nv_bfloat16* __restrict__ Al,
         const __nv_bfloat16* __restrict__ Wh, const __nv_bfloat16* __restrict__ Wl,
         const float* __restrict__ bias, const float* __restrict__ Rsd,
         float* __restrict__ Cf, __nv_bfloat16* __restrict__ Ch, __nv_bfloat16* __restrict__ Cl,
         int Ncols, int K) {
    extern __shared__ char smraw[];
    const uint32_t sb = smem_u32(smraw);
    const int tid = threadIdx.x;
    const int wid = tid >> 5;
    const int lane = tid & 31;
    const size_t rowBase = (size_t)blockIdx.y * 128;
    const int colBase = blockIdx.x * 128;
    const int wm = (wid >> 2) * 64;  // warp m-offset (0 or 64)
    const int wn = (wid & 3) * 32;   // warp n-offset

    float acc[4][4][4];
#pragma unroll
    for (int mt = 0; mt < 4; mt++)
#pragma unroll
        for (int nt = 0; nt < 4; nt++)
#pragma unroll
            for (int q = 0; q < 4; q++) acc[mt][nt][q] = 0.f;

    const int KIT = K >> 5;

    // prologue: stages 0..2
#pragma unroll
    for (int s = 0; s < 3; s++) {
        if (s < KIT) {
            uint32_t st = sb + s * STAGEB;
            load_tile128(st + OFF_AH, Ah, rowBase, K, s * 32, tid);
            load_tile128(st + OFF_AL, Al, rowBase, K, s * 32, tid);
            load_tile128(st + OFF_BH, Wh, (size_t)colBase, K, s * 32, tid);
            load_tile128(st + OFF_BL, Wl, (size_t)colBase, K, s * 32, tid);
        }
        CP_COMMIT();
    }

    // fragment addresses (lane-dependent parts)
    const int arow = lane & 15;
    const int ainc = lane >> 4;                 // 0/1 -> +16B chunk
    const int brow = (lane & 7) + ((lane >> 4) << 3);
    const int binc = (lane >> 3) & 1;

    for (int it = 0; it < KIT; ++it) {
        const int buf = it % 3;
        CP_WAIT2();
        __syncthreads();
        const uint32_t stb = sb + buf * STAGEB;
#pragma unroll
        for (int kk = 0; kk < 2; kk++) {
            const int kc = kk * 2;
            uint32_t ah[4][4], alr[4][4], bh[4][2], bl[4][2];
#pragma unroll
            for (int mt = 0; mt < 4; mt++) {
                uint32_t ad = stb + OFF_AH + (wm + mt * 16 + arow) * PITCHB + (kc + ainc) * 16;
                LDSM4(ah[mt][0], ah[mt][1], ah[mt][2], ah[mt][3], ad);
                LDSM4(alr[mt][0], alr[mt][1], alr[mt][2], alr[mt][3], ad + (OFF_AL - OFF_AH));
            }
#pragma unroll
            for (int bt = 0; bt < 2; bt++) {
                uint32_t bd = stb + OFF_BH + (wn + bt * 16 + brow) * PITCHB + (kc + binc) * 16;
                uint32_t r0, r1, r2, r3;
                LDSM4(r0, r1, r2, r3, bd);
                bh[2 * bt][0] = r0; bh[2 * bt][1] = r1;
                bh[2 * bt + 1][0] = r2; bh[2 * bt + 1][1] = r3;
                LDSM4(r0, r1, r2, r3, bd + (OFF_BL - OFF_BH));
                bl[2 * bt][0] = r0; bl[2 * bt][1] = r1;
                bl[2 * bt + 1][0] = r2; bl[2 * bt + 1][1] = r3;
            }
#pragma unroll
            for (int mt = 0; mt < 4; mt++) {
#pragma unroll
                for (int nt = 0; nt < 4; nt++) {
                    MMA_BF16(acc[mt][nt], ah[mt], bh[nt]);
                    MMA_BF16(acc[mt][nt], ah[mt], bl[nt]);
                    MMA_BF16(acc[mt][nt], alr[mt], bh[nt]);
                }
            }
        }
        __syncthreads();
        if (it + 3 < KIT) {
            uint32_t st = sb + buf * STAGEB;
            int k0 = (it + 3) * 32;
            load_tile128(st + OFF_AH, Ah, rowBase, K, k0, tid);
            load_tile128(st + OFF_AL, Al, rowBase, K, k0, tid);
            load_tile128(st + OFF_BH, Wh, (size_t)colBase, K, k0, tid);
            load_tile128(st + OFF_BL, Wl, (size_t)colBase, K, k0, tid);
        }
        CP_COMMIT();
    }

    // epilogue
#pragma unroll
    for (int mt = 0; mt < 4; mt++) {
#pragma unroll
        for (int nt = 0; nt < 4; nt++) {
            const int col = colBase + wn + nt * 8 + (lane & 3) * 2;
#pragma unroll
            for (int half = 0; half < 2; half++) {
                const size_t row = rowBase + wm + mt * 16 + (lane >> 2) + half * 8;
                float vx = acc[mt][nt][half * 2 + 0];
                float vy = acc[mt][nt][half * 2 + 1];
                if (BIAS_) {
                    float2 bv = *(const float2*)&bias[col];
                    vx += bv.x; vy += bv.y;
                }
                if (RELU_) { vx = fmaxf(vx, 0.f); vy = fmaxf(vy, 0.f); }
                if (RESID_) {
                    float2 rv = *(const float2*)&Rsd[row * Ncols + col];
                    vx += rv.x; vy += rv.y;
                }
                if (OUTF_) {
                    *(float2*)&Cf[row * Ncols + col] = make_float2(vx, vy);
                }
                if (OUTHL_) {
                    __nv_bfloat162 Hv, Lv;
                    split2(vx, vy, Hv, Lv);
                    *(__nv_bfloat162*)&Ch[row * Ncols + col] = Hv;
                    *(__nv_bfloat162*)&Cl[row * Ncols + col] = Lv;
                }
            }
        }
    }
}

// ------------------------------------------------------------------
// Attention (fp32 FFMA), writes hi/lo bf16 output
// ------------------------------------------------------------------
__global__ void __launch_bounds__(256)
attn_kernel(const float* __restrict__ Qm, const float* __restrict__ Km,
            const float* __restrict__ Vm, const float* __restrict__ adj,
            const float* __restrict__ hw,
            __nv_bfloat16* __restrict__ ATTh, __nv_bfloat16* __restrict__ ATTl) {
    __shared__ float bufA[64][68];
    __shared__ float bufB[64][68];

    const int b = blockIdx.x >> 3;
    const int h = blockIdx.x & 7;
    const int tid = threadIdx.x;
    const int ty = tid >> 4;
    const int tx = tid & 15;
    const int dkl = tid & 63;
    const int nl0 = tid >> 6;

    const size_t base = ((size_t)b * 2048) * Dn + h * DKn;

    float acc[4][4];
#pragma unroll
    for (int i = 0; i < 4; i++)
#pragma unroll
        for (int j = 0; j < 4; j++) acc[i][j] = 0.f;

    for (int t0 = 0; t0 < 32; t0++) {
        __syncthreads();
        for (int nn = nl0; nn < 64; nn += 4) {
            size_t off = base + (size_t)(nn * 32 + t0) * Dn + dkl;
            bufA[dkl][nn] = Qm[off];
            bufB[dkl][nn] = Km[off];
        }
        __syncthreads();
#pragma unroll 8
        for (int dk = 0; dk < 64; dk++) {
            float4 q = *(const float4*)&bufA[dk][ty * 4];
            float4 k = *(const float4*)&bufB[dk][tx * 4];
            acc[0][0] = fmaf(q.x, k.x, acc[0][0]); acc[0][1] = fmaf(q.x, k.y, acc[0][1]);
            acc[0][2] = fmaf(q.x, k.z, acc[0][2]); acc[0][3] = fmaf(q.x, k.w, acc[0][3]);
            acc[1][0] = fmaf(q.y, k.x, acc[1][0]); acc[1][1] = fmaf(q.y, k.y, acc[1][1]);
            acc[1][2] = fmaf(q.y, k.z, acc[1][2]); acc[1][3] = fmaf(q.y, k.w, acc[1][3]);
            acc[2][0] = fmaf(q.z, k.x, acc[2][0]); acc[2][1] = fmaf(q.z, k.y, acc[2][1]);
            acc[2][2] = fmaf(q.z, k.z, acc[2][2]); acc[2][3] = fmaf(q.z, k.w, acc[2][3]);
            acc[3][0] = fmaf(q.w, k.x, acc[3][0]); acc[3][1] = fmaf(q.w, k.y, acc[3][1]);
            acc[3][2] = fmaf(q.w, k.z, acc[3][2]); acc[3][3] = fmaf(q.w, k.w, acc[3][3]);
        }
    }

    __syncthreads();
#pragma unroll
    for (int i = 0; i < 4; i++)
#pragma unroll
        for (int j = 0; j < 4; j++)
            bufB[ty * 4 + i][tx * 4 + j] = acc[i][j] * SCALE_F;
    __syncthreads();

    {
        const int w = tid >> 5, lane = tid & 31;
        const float hwv = hw[h];
        for (int rr = 0; rr < 8; rr++) {
            int row = w * 8 + rr;
            float v0 = bufB[row][lane];
            float v1 = bufB[row][lane + 32];
            float mx = fmaxf(v0, v1);
#pragma unroll
            for (int o = 16; o; o >>= 1) mx = fmaxf(mx, __shfl_xor_sync(0xffffffffu, mx, o));
            float e0 = __expf(v0 - mx), e1 = __expf(v1 - mx);
            float s = e0 + e1;
#pragma unroll
            for (int o = 16; o; o >>= 1) s += __shfl_xor_sync(0xffffffffu, s, o);
            float inv = 1.f / s;
            size_t ab = (size_t)h * 4096 + row * 64;
            bufB[row][lane]      = e0 * inv * hwv + adj[ab + lane];
            bufB[row][lane + 32] = e1 * inv * hwv + adj[ab + 32 + lane];
        }
    }

    for (int t0 = 0; t0 < 32; t0++) {
        __syncthreads();
        for (int mm = nl0; mm < 64; mm += 4) {
            bufA[mm][dkl] = Vm[base + (size_t)(mm * 32 + t0) * Dn + dkl];
        }
        __syncthreads();
        float o2[4][4];
#pragma unroll
        for (int i = 0; i < 4; i++)
#pragma unroll
            for (int j = 0; j < 4; j++) o2[i][j] = 0.f;
#pragma unroll 8
        for (int m = 0; m < 64; m++) {
            float4 v = *(const float4*)&bufA[m][tx * 4];
            float s0 = bufB[ty * 4 + 0][m];
            float s1 = bufB[ty * 4 + 1][m];
            float s2 = bufB[ty * 4 + 2][m];
            float s3 = bufB[ty * 4 + 3][m];
            o2[0][0] = fmaf(s0, v.x, o2[0][0]); o2[0][1] = fmaf(s0, v.y, o2[0][1]);
            o2[0][2] = fmaf(s0, v.z, o2[0][2]); o2[0][3] = fmaf(s0, v.w, o2[0][3]);
            o2[1][0] = fmaf(s1, v.x, o2[1][0]); o2[1][1] = fmaf(s1, v.y, o2[1][1]);
            o2[1][2] = fmaf(s1, v.z, o2[1][2]); o2[1][3] = fmaf(s1, v.w, o2[1][3]);
            o2[2][0] = fmaf(s2, v.x, o2[2][0]); o2[2][1] = fmaf(s2, v.y, o2[2][1]);
            o2[2][2] = fmaf(s2, v.z, o2[2][2]); o2[2][3] = fmaf(s2, v.w, o2[2][3]);
            o2[3][0] = fmaf(s3, v.x, o2[3][0]); o2[3][1] = fmaf(s3, v.y, o2[3][1]);
            o2[3][2] = fmaf(s3, v.z, o2[3][2]); o2[3][3] = fmaf(s3, v.w, o2[3][3]);
        }
#pragma unroll
        for (int i = 0; i < 4; i++) {
            int n = ty * 4 + i;
            size_t off = base + (size_t)(n * 32 + t0) * Dn + tx * 4;
            __nv_bfloat162 h0, l0, h1, l1;
            split2(o2[i][0], o2[i][1], h0, l0);
            split2(o2[i][2], o2[i][3], h1, l1);
            *(__nv_bfloat162*)&ATTh[off] = h0; *(__nv_bfloat162*)&ATTh[off + 2] = h1;
            *(__nv_bfloat162*)&ATTl[off] = l0; *(__nv_bfloat162*)&ATTl[off + 2] = l1;
        }
    }
}

// ------------------------------------------------------------------
// LayerNorm
// ------------------------------------------------------------------
__global__ void ln_partial(const float* __restrict__ Y1, float2* __restrict__ part) {
    const int c = blockIdx.x, b = blockIdx.y;
    const float* p = Y1 + (size_t)b * 1048576 + (size_t)c * 32768;
    float s = 0.f, s2 = 0.f;
    for (int i = threadIdx.x; i < 32768; i += 256) {
        float v = p[i];
        s += v; s2 += v * v;
    }
    __shared__ float rs[256], rs2[256];
    rs[threadIdx.x] = s; rs2[threadIdx.x] = s2;
    __syncthreads();
    for (int o = 128; o; o >>= 1) {
        if (threadIdx.x < o) {
            rs[threadIdx.x] += rs[threadIdx.x + o];
            rs2[threadIdx.x] += rs2[threadIdx.x + o];
        }
        __syncthreads();
    }
    if (threadIdx.x == 0) part[b * 32 + c] = make_float2(rs[0], rs2[0]);
}

__global__ void ln_final(const float2* __restrict__ part, float2* __restrict__ stats) {
    int b = threadIdx.x;
    if (b < Bn) {
        float s = 0.f, s2 = 0.f;
        for (int c = 0; c < 32; c++) {
            float2 p = part[b * 32 + c];
            s += p.x; s2 += p.y;
        }
        const float invN = 1.0f / 1048576.0f;
        float mean = s * invN;
        float var = s2 * invN - mean * mean;
        stats[b] = make_float2(mean, rsqrtf(var + LN_EPS));
    }
}

__global__ void ln_apply(const float* __restrict__ Y1, const float2* __restrict__ stats,
                         const float* __restrict__ g1, const float* __restrict__ be1,
                         float* __restrict__ X1,
                         __nv_bfloat16* __restrict__ X1h, __nv_bfloat16* __restrict__ X1l) {
    size_t e = ((size_t)blockIdx.x * blockDim.x + threadIdx.x) * 4;
    float2 st = stats[e >> 20];
    size_t gi = e & 1048575;
    float4 y = *(const float4*)&Y1[e];
    float4 g = *(const float4*)&g1[gi];
    float4 be = *(const float4*)&be1[gi];
    float4 o;
    o.x = (y.x - st.x) * st.y * g.x + be.x;
    o.y = (y.y - st.x) * st.y * g.y + be.y;
    o.z = (y.z - st.x) * st.y * g.z + be.z;
    o.w = (y.w - st.x) * st.y * g.w + be.w;
    *(float4*)&X1[e] = o;
    __nv_bfloat162 h0, l0, h1, l1;
    split2(o.x, o.y, h0, l0);
    split2(o.z, o.w, h1, l1);
    *(__nv_bfloat162*)&X1h[e] = h0; *(__nv_bfloat162*)&X1h[e + 2] = h1;
    *(__nv_bfloat162*)&X1l[e] = l0; *(__nv_bfloat162*)&X1l[e + 2] = l1;
}

// ------------------------------------------------------------------
// launch
// ------------------------------------------------------------------
extern "C" void kernel_launch(void* const* d_in, const int* in_sizes, int n_in,
                              void* d_out, int out_size) {
    const float* x   = (const float*)d_in[0];
    const float* Wq  = (const float*)d_in[1];
    const float* bq  = (const float*)d_in[2];
    const float* Wk  = (const float*)d_in[3];
    const float* bk  = (const float*)d_in[4];
    const float* Wv  = (const float*)d_in[5];
    const float* bv  = (const float*)d_in[6];
    const float* Wo  = (const float*)d_in[7];
    const float* bo  = (const float*)d_in[8];
    const float* W1  = (const float*)d_in[9];
    const float* b1  = (const float*)d_in[10];
    const float* W2  = (const float*)d_in[11];
    const float* b2  = (const float*)d_in[12];
    const float* g1  = (const float*)d_in[13];
    const float* be1 = (const float*)d_in[14];
    const float* adj = (const float*)d_in[15];
    const float* hw  = (const float*)d_in[16];
    const float* pe  = (const float*)d_in[17];
    float* out = (float*)d_out;

#define GETP(sym, ty, name) ty* name; { void* _p; cudaGetSymbolAddress(&_p, sym); name = (ty*)_p; }
    GETP(g_XR, float, XR) GETP(g_Qm, float, Qm) GETP(g_Km, float, Km) GETP(g_Vm, float, Vm)
    GETP(g_Y1, float, Y1) GETP(g_X1, float, X1) GETP(g_FF, float, FFo)
    GETP(g_XRh, __nv_bfloat16, XRh) GETP(g_XRl, __nv_bfloat16, XRl)
    GETP(g_XPEh, __nv_bfloat16, XPEh) GETP(g_XPEl, __nv_bfloat16, XPEl)
    GETP(g_ATTh, __nv_bfloat16, ATTh) GETP(g_ATTl, __nv_bfloat16, ATTl)
    GETP(g_X1h, __nv_bfloat16, X1h) GETP(g_X1l, __nv_bfloat16, X1l)
    GETP(g_Hh, __nv_bfloat16, Hh) GETP(g_Hl, __nv_bfloat16, Hl)
    GETP(g_Wqh, __nv_bfloat16, Wqh) GETP(g_Wql, __nv_bfloat16, Wql)
    GETP(g_Wkh, __nv_bfloat16, Wkh) GETP(g_Wkl, __nv_bfloat16, Wkl)
    GETP(g_Wvh, __nv_bfloat16, Wvh) GETP(g_Wvl, __nv_bfloat16, Wvl)
    GETP(g_Woh, __nv_bfloat16, Woh) GETP(g_Wol, __nv_bfloat16, Wol)
    GETP(g_W1h, __nv_bfloat16, W1h) GETP(g_W1l, __nv_bfloat16, W1l)
    GETP(g_W2h, __nv_bfloat16, W2h) GETP(g_W2l, __nv_bfloat16, W2l)
    GETP(g_part, float2, part) GETP(g_stats, float2, stats)
#undef GETP

    cudaFuncSetAttribute(gemm_mma<true, false, false, true, false>,
                         cudaFuncAttributeMaxDynamicSharedMemorySize, GEMM_DSMEM);
    cudaFuncSetAttribute(gemm_mma<true, false, true, true, false>,
                         cudaFuncAttributeMaxDynamicSharedMemorySize, GEMM_DSMEM);
    cudaFuncSetAttribute(gemm_mma<true, true, false, false, true>,
                         cudaFuncAttributeMaxDynamicSharedMemorySize, GEMM_DSMEM);

    // 0. weight conversion
    conv_hl<<<256, 256>>>(Wq, Wqh, Wql, Dn * Dn);
    conv_hl<<<256, 256>>>(Wk, Wkh, Wkl, Dn * Dn);
    conv_hl<<<256, 256>>>(Wv, Wvh, Wvl, Dn * Dn);
    conv_hl<<<256, 256>>>(Wo, Woh, Wol, Dn * Dn);
    conv_hl<<<1024, 256>>>(W1, W1h, W1l, FFn * Dn);
    conv_hl<<<1024, 256>>>(W2, W2h, W2l, Dn * FFn);

    // 1. transpose + split
    dim3 trGrid(16, 2, Bn * Tn);
    dim3 trBlk(32, 8);
    prep_xr<<<trGrid, trBlk>>>(x, pe, XR, XRh, XRl, XPEh, XPEl);

    // 2. QKV projections
    dim3 gD(Dn / 128, MTOT / 128);  // (4, 512)
    gemm_mma<true, false, false, true, false><<<gD, 256, GEMM_DSMEM>>>(
        XPEh, XPEl, Wqh, Wql, bq, nullptr, Qm, nullptr, nullptr, Dn, Dn);
    gemm_mma<true, false, false, true, false><<<gD, 256, GEMM_DSMEM>>>(
        XPEh, XPEl, Wkh, Wkl, bk, nullptr, Km, nullptr, nullptr, Dn, Dn);
    gemm_mma<true, false, false, true, false><<<gD, 256, GEMM_DSMEM>>>(
        XRh, XRl, Wvh, Wvl, bv, nullptr, Vm, nullptr, nullptr, Dn, Dn);

    // 3. attention
    attn_kernel<<<Bn * Hn, 256>>>(Qm, Km, Vm, adj, hw, ATTh, ATTl);

    // 4. output projection + residual
    gemm_mma<true, false, true, true, false><<<gD, 256, GEMM_DSMEM>>>(
        ATTh, ATTl, Woh, Wol, bo, XR, Y1, nullptr, nullptr, Dn, Dn);

    // 5. layernorm
    ln_partial<<<dim3(32, Bn), 256>>>(Y1, part);
    ln_final<<<1, 32>>>(part, stats);
    ln_apply<<<(MTOT * (size_t)Dn / 4) / 256, 256>>>(Y1, stats, g1, be1, X1, X1h, X1l);

    // 6. FFN
    dim3 gF1(FFn / 128, MTOT / 128);  // (16, 512)
    gemm_mma<true, true, false, false, true><<<gF1, 256, GEMM_DSMEM>>>(
        X1h, X1l, W1h, W1l, b1, nullptr, nullptr, Hh, Hl, FFn, Dn);
    gemm_mma<true, false, true, true, false><<<gD, 256, GEMM_DSMEM>>>(
        Hh, Hl, W2h, W2l, b2, X1, FFo, nullptr, nullptr, Dn, FFn);

    // 7. output transpose
    out_tr<<<trGrid, trBlk>>>(FFo, out);
}

// round 4
// speedup vs baseline: 2.4184x; 1.4297x over previous
#include <cuda_runtime.h>
#include <cuda_bf16.h>
#include <cstdint>
#include <math.h>

// Problem dims
#define Bn 32
#define Dn 512
#define Tn 32
#define Nn 64
#define Hn 8
#define DKn 64
#define FFn 2048
#define MTOT (Bn * Nn * Tn)
#define SCALE_F 0.022097086912079608f
#define LN_EPS 1e-5f

// ------------------------------------------------------------------
// Scratch
// ------------------------------------------------------------------
__device__ float g_XR[(size_t)MTOT * Dn];
__device__ float g_QK[(size_t)MTOT * 1024];
__device__ float g_Vm[(size_t)MTOT * Dn];
__device__ float g_Y1[(size_t)MTOT * Dn];
__device__ float g_X1[(size_t)MTOT * Dn];
__device__ float g_FF[(size_t)MTOT * Dn];
__device__ __nv_bfloat16 g_XRh[(size_t)MTOT * Dn], g_XRl[(size_t)MTOT * Dn];
__device__ __nv_bfloat16 g_XPEh[(size_t)MTOT * Dn], g_XPEl[(size_t)MTOT * Dn];
__device__ __nv_bfloat16 g_ATTh[(size_t)MTOT * Dn], g_ATTl[(size_t)MTOT * Dn];
__device__ __nv_bfloat16 g_X1h[(size_t)MTOT * Dn], g_X1l[(size_t)MTOT * Dn];
__device__ __nv_bfloat16 g_Hh[(size_t)MTOT * FFn], g_Hl[(size_t)MTOT * FFn];
__device__ __nv_bfloat16 g_Wqkh[1024 * Dn], g_Wqkl[1024 * Dn];
__device__ __nv_bfloat16 g_Wvh[Dn * Dn], g_Wvl[Dn * Dn];
__device__ __nv_bfloat16 g_Woh[Dn * Dn], g_Wol[Dn * Dn];
__device__ __nv_bfloat16 g_W1h[FFn * Dn], g_W1l[FFn * Dn];
__device__ __nv_bfloat16 g_W2h[Dn * FFn], g_W2l[Dn * FFn];
__device__ float g_bqk[1024];
__device__ float2 g_part[Bn * 32];
__device__ float2 g_stats[Bn];

// ------------------------------------------------------------------
// PTX helpers (compute_100-safe)
// ------------------------------------------------------------------
__device__ __forceinline__ uint32_t smem_u32(const void* p) {
    uint32_t a;
    asm("{ .reg .u64 t; cvta.to.shared.u64 t, %1; cvt.u32.u64 %0, t; }" : "=r"(a) : "l"(p));
    return a;
}
__device__ __forceinline__ void cpasync16(uint32_t dst, const void* src) {
    asm volatile("cp.async.cg.shared.global [%0], [%1], 16;" :: "r"(dst), "l"(src));
}
#define CP_COMMIT() asm volatile("cp.async.commit_group;" ::: "memory")
#define CP_WAIT2() asm volatile("cp.async.wait_group 2;" ::: "memory")

#define LDSM4(r0, r1, r2, r3, addr) \
    asm volatile("ldmatrix.sync.aligned.m8n8.x4.shared.b16 {%0,%1,%2,%3}, [%4];" \
                 : "=r"(r0), "=r"(r1), "=r"(r2), "=r"(r3) : "r"(addr))

#define MMA_BF16(d, a, b) \
    asm volatile("mma.sync.aligned.m16n8k16.row.col.f32.bf16.bf16.f32 " \
                 "{%0,%1,%2,%3}, {%4,%5,%6,%7}, {%8,%9}, {%0,%1,%2,%3};" \
                 : "+f"((d)[0]), "+f"((d)[1]), "+f"((d)[2]), "+f"((d)[3]) \
                 : "r"((a)[0]), "r"((a)[1]), "r"((a)[2]), "r"((a)[3]), \
                   "r"((b)[0]), "r"((b)[1]))

__device__ __forceinline__ void split2(float a, float b, __nv_bfloat162& h, __nv_bfloat162& l) {
    h = __floats2bfloat162_rn(a, b);
    l = __floats2bfloat162_rn(a - __low2float(h), b - __high2float(h));
}

// ------------------------------------------------------------------
// fused weight conversion (+ bias concat)
// ------------------------------------------------------------------
__global__ void conv_all(const float* __restrict__ Wq, const float* __restrict__ Wk,
                         const float* __restrict__ Wv, const float* __restrict__ Wo,
                         const float* __restrict__ W1, const float* __restrict__ W2,
                         const float* __restrict__ bq, const float* __restrict__ bk) {
    long i4 = (long)blockIdx.x * 256 + threadIdx.x;  // float4 index
    if (i4 >= 786432) {
        // bias concat block
        int t = threadIdx.x;
        if (blockIdx.x == 3072) {
            g_bqk[t] = bq[t];
            g_bqk[t + 256] = bq[t + 256];
            g_bqk[t + 512] = bk[t];
            g_bqk[t + 768] = bk[t + 256];
        }
        return;
    }
    const float* src;
    __nv_bfloat16 *dh, *dl;
    long o;
    if (i4 < 65536)       { src = Wq; dh = g_Wqkh;          dl = g_Wqkl;          o = i4; }
    else if (i4 < 131072) { src = Wk; dh = g_Wqkh + 262144; dl = g_Wqkl + 262144; o = i4 - 65536; }
    else if (i4 < 196608) { src = Wv; dh = g_Wvh;           dl = g_Wvl;           o = i4 - 131072; }
    else if (i4 < 262144) { src = Wo; dh = g_Woh;           dl = g_Wol;           o = i4 - 196608; }
    else if (i4 < 524288) { src = W1; dh = g_W1h;           dl = g_W1l;           o = i4 - 262144; }
    else                  { src = W2; dh = g_W2h;           dl = g_W2l;           o = i4 - 524288; }
    long e = o * 4;
    float4 v = *(const float4*)&src[e];
    __nv_bfloat162 h0, l0, h1, l1;
    split2(v.x, v.y, h0, l0);
    split2(v.z, v.w, h1, l1);
    *(__nv_bfloat162*)&dh[e] = h0; *(__nv_bfloat162*)&dh[e + 2] = h1;
    *(__nv_bfloat162*)&dl[e] = l0; *(__nv_bfloat162*)&dl[e + 2] = l1;
}

// ------------------------------------------------------------------
// prep / out transpose
// ------------------------------------------------------------------
__global__ void prep_xr(const float* __restrict__ x, const float* __restrict__ pe,
                        float* __restrict__ XR,
                        __nv_bfloat16* __restrict__ XRh, __nv_bfloat16* __restrict__ XRl,
                        __nv_bfloat16* __restrict__ XPEh, __nv_bfloat16* __restrict__ XPEl) {
    __shared__ float tile[32][33];
    int bt = blockIdx.z;
    int b = bt >> 5, t = bt & 31;
    int d0 = blockIdx.x * 32, n0 = blockIdx.y * 32;
    size_t bbase = (size_t)b * (Dn * Tn * Nn);
#pragma unroll
    for (int i = 0; i < 4; i++) {
        int d = d0 + threadIdx.y + i * 8;
        tile[threadIdx.y + i * 8][threadIdx.x] =
            x[bbase + (size_t)d * (Tn * Nn) + t * Nn + n0 + threadIdx.x];
    }
    __syncthreads();
    int d = d0 + threadIdx.x;
#pragma unroll
    for (int i = 0; i < 4; i++) {
        int n = n0 + threadIdx.y + i * 8;
        float v = tile[threadIdx.x][threadIdx.y + i * 8];
        size_t idx = bbase + (size_t)n * (Tn * Dn) + t * Dn + d;
        XR[idx] = v;
        __nv_bfloat16 h = __float2bfloat16(v);
        XRh[idx] = h;
        XRl[idx] = __float2bfloat16(v - __bfloat162float(h));
        float vp = v + pe[n * Dn + d];
        __nv_bfloat16 hp = __float2bfloat16(vp);
        XPEh[idx] = hp;
        XPEl[idx] = __float2bfloat16(vp - __bfloat162float(hp));
    }
}

__global__ void out_tr(const float* __restrict__ FF, float* __restrict__ out) {
    __shared__ float tile[32][33];
    int bt = blockIdx.z;
    int b = bt >> 5, t = bt & 31;
    int d0 = blockIdx.x * 32, n0 = blockIdx.y * 32;
    size_t bbase = (size_t)b * (Dn * Tn * Nn);
#pragma unroll
    for (int i = 0; i < 4; i++) {
        int n = n0 + threadIdx.y + i * 8;
        tile[threadIdx.y + i * 8][threadIdx.x] =
            FF[bbase + (size_t)n * (Tn * Dn) + t * Dn + d0 + threadIdx.x];
    }
    __syncthreads();
#pragma unroll
    for (int i = 0; i < 4; i++) {
        int d = d0 + threadIdx.y + i * 8;
        out[bbase + (size_t)d * (Tn * Nn) + t * Nn + n0 + threadIdx.x] =
            tile[threadIdx.x][threadIdx.y + i * 8];
    }
}

// ------------------------------------------------------------------
// mma.sync split-bf16 GEMM: 256x128 CTA tile, warp 64x64 (8 warps 4x2),
// BK=32, 3-stage cp.async, pitch-80 SMEM (conflict-free ldmatrix)
// ------------------------------------------------------------------
#define PITCHB 80
#define OFF_AH 0
#define OFF_AL (256 * PITCHB)               // 20480
#define OFF_BH (2 * 256 * PITCHB)           // 40960
#define OFF_BL (OFF_BH + 128 * PITCHB)      // 51200
#define STAGEB (OFF_BL + 128 * PITCHB)      // 61440
#define GEMM_DSMEM (3 * STAGEB)             // 184320

template <int ROWS>
__device__ __forceinline__ void load_tile(uint32_t sdst, const __nv_bfloat16* __restrict__ g,
                                          size_t row0, int K, int k0, int tid) {
    const char* gbase = (const char*)(g + row0 * (size_t)K + k0);
    size_t rs = (size_t)K * 2;
#pragma unroll
    for (int ch = tid; ch < ROWS * 4; ch += 256) {
        int r = ch >> 2, c = ch & 3;
        cpasync16(sdst + r * PITCHB + c * 16, gbase + (size_t)r * rs + c * 16);
    }
}

template <bool BIAS_, bool RELU_, bool RESID_, bool OUTF_, bool OUTHL_>
__global__ void __launch_bounds__(256, 1)
gemm_mma(const __nv_bfloat16* __restrict__ Ah, const __nv_bfloat16* __restrict__ Al,
         const __nv_bfloat16* __restrict__ Wh, const __nv_bfloat16* __restrict__ Wl,
         const float* __restrict__ bias, const float* __restrict__ Rsd,
         float* __restrict__ Cf, __nv_bfloat16* __restrict__ Ch, __nv_bfloat16* __restrict__ Cl,
         int Ncols, int K) {
    extern __shared__ char smraw[];
    const uint32_t sb = smem_u32(smraw);
    const int tid = threadIdx.x;
    const int wid = tid >> 5;
    const int lane = tid & 31;
    const size_t rowBase = (size_t)blockIdx.y * 256;
    const int colBase = blockIdx.x * 128;
    const int wm = (wid >> 1) * 64;  // 0,64,128,192
    const int wn = (wid & 1) * 64;   // 0,64

    float acc[4][8][4];
#pragma unroll
    for (int mt = 0; mt < 4; mt++)
#pragma unroll
        for (int nt = 0; nt < 8; nt++)
#pragma unroll
            for (int q = 0; q < 4; q++) acc[mt][nt][q] = 0.f;

    const int KIT = K >> 5;

#pragma unroll
    for (int s = 0; s < 3; s++) {
        uint32_t st = sb + s * STAGEB;
        load_tile<256>(st + OFF_AH, Ah, rowBase, K, s * 32, tid);
        load_tile<256>(st + OFF_AL, Al, rowBase, K, s * 32, tid);
        load_tile<128>(st + OFF_BH, Wh, (size_t)colBase, K, s * 32, tid);
        load_tile<128>(st + OFF_BL, Wl, (size_t)colBase, K, s * 32, tid);
        CP_COMMIT();
    }

    const int arow = lane & 15;
    const int ainc = lane >> 4;
    const int brow = (lane & 7) + ((lane >> 4) << 3);
    const int binc = (lane >> 3) & 1;

    for (int it = 0; it < KIT; ++it) {
        const int buf = it % 3;
        CP_WAIT2();
        __syncthreads();
        const uint32_t stb = sb + buf * STAGEB;
#pragma unroll
        for (int kc = 0; kc < 2; kc++) {
            uint32_t ah[4][4], alr[4][4], bh[8][2], bl[8][2];
#pragma unroll
            for (int mt = 0; mt < 4; mt++) {
                uint32_t ad = stb + OFF_AH + (wm + mt * 16 + arow) * PITCHB + kc * 32 + ainc * 16;
                LDSM4(ah[mt][0], ah[mt][1], ah[mt][2], ah[mt][3], ad);
                LDSM4(alr[mt][0], alr[mt][1], alr[mt][2], alr[mt][3], ad + (OFF_AL - OFF_AH));
            }
#pragma unroll
            for (int bt = 0; bt < 4; bt++) {
                uint32_t bd = stb + OFF_BH + (wn + bt * 16 + brow) * PITCHB + kc * 32 + binc * 16;
                uint32_t r0, r1, r2, r3;
                LDSM4(r0, r1, r2, r3, bd);
                bh[2 * bt][0] = r0; bh[2 * bt][1] = r1;
                bh[2 * bt + 1][0] = r2; bh[2 * bt + 1][1] = r3;
                LDSM4(r0, r1, r2, r3, bd + (OFF_BL - OFF_BH));
                bl[2 * bt][0] = r0; bl[2 * bt][1] = r1;
                bl[2 * bt + 1][0] = r2; bl[2 * bt + 1][1] = r3;
            }
#pragma unroll
            for (int mt = 0; mt < 4; mt++) {
#pragma unroll
                for (int nt = 0; nt < 8; nt++) {
                    MMA_BF16(acc[mt][nt], ah[mt], bh[nt]);
                    MMA_BF16(acc[mt][nt], ah[mt], bl[nt]);
                    MMA_BF16(acc[mt][nt], alr[mt], bh[nt]);
                }
            }
        }
        __syncthreads();
        if (it + 3 < KIT) {
            uint32_t st = sb + buf * STAGEB;
            int k0 = (it + 3) * 32;
            load_tile<256>(st + OFF_AH, Ah, rowBase, K, k0, tid);
            load_tile<256>(st + OFF_AL, Al, rowBase, K, k0, tid);
            load_tile<128>(st + OFF_BH, Wh, (size_t)colBase, K, k0, tid);
            load_tile<128>(st + OFF_BL, Wl, (size_t)colBase, K, k0, tid);
        }
        CP_COMMIT();
    }

    // epilogue
#pragma unroll
    for (int mt = 0; mt < 4; mt++) {
#pragma unroll
        for (int nt = 0; nt < 8; nt++) {
            const int col = colBase + wn + nt * 8 + (lane & 3) * 2;
#pragma unroll
            for (int half = 0; half < 2; half++) {
                const size_t row = rowBase + wm + mt * 16 + (lane >> 2) + half * 8;
                float vx = acc[mt][nt][half * 2 + 0];
                float vy = acc[mt][nt][half * 2 + 1];
                if (BIAS_) {
                    float2 bv = *(const float2*)&bias[col];
                    vx += bv.x; vy += bv.y;
                }
                if (RELU_) { vx = fmaxf(vx, 0.f); vy = fmaxf(vy, 0.f); }
                if (RESID_) {
                    float2 rv = *(const float2*)&Rsd[row * Ncols + col];
                    vx += rv.x; vy += rv.y;
                }
                if (OUTF_) {
                    *(float2*)&Cf[row * Ncols + col] = make_float2(vx, vy);
                }
                if (OUTHL_) {
                    __nv_bfloat162 Hv, Lv;
                    split2(vx, vy, Hv, Lv);
                    *(__nv_bfloat162*)&Ch[row * Ncols + col] = Hv;
                    *(__nv_bfloat162*)&Cl[row * Ncols + col] = Lv;
                }
            }
        }
    }
}

// ------------------------------------------------------------------
// Attention (fp32 FFMA); Q,K read from fused QK buffer (row stride 1024)
// ------------------------------------------------------------------
__global__ void __launch_bounds__(256)
attn_kernel(const float* __restrict__ QK, const float* __restrict__ Vm,
            const float* __restrict__ adj, const float* __restrict__ hw,
            __nv_bfloat16* __restrict__ ATTh, __nv_bfloat16* __restrict__ ATTl) {
    __shared__ float bufA[64][68];
    __shared__ float bufB[64][68];

    const int b = blockIdx.x >> 3;
    const int h = blockIdx.x & 7;
    const int tid = threadIdx.x;
    const int ty = tid >> 4;
    const int tx = tid & 15;
    const int dkl = tid & 63;
    const int nl0 = tid >> 6;

    const size_t base_q = ((size_t)b * 2048) * 1024 + h * DKn;
    const size_t base_k = base_q + 512;
    const size_t base_v = ((size_t)b * 2048) * Dn + h * DKn;

    float acc[4][4];
#pragma unroll
    for (int i = 0; i < 4; i++)
#pragma unroll
        for (int j = 0; j < 4; j++) acc[i][j] = 0.f;

    for (int t0 = 0; t0 < 32; t0++) {
        __syncthreads();
        for (int nn = nl0; nn < 64; nn += 4) {
            size_t off = (size_t)(nn * 32 + t0) * 1024 + dkl;
            bufA[dkl][nn] = QK[base_q + off];
            bufB[dkl][nn] = QK[base_k + off];
        }
        __syncthreads();
#pragma unroll 8
        for (int dk = 0; dk < 64; dk++) {
            float4 q = *(const float4*)&bufA[dk][ty * 4];
            float4 k = *(const float4*)&bufB[dk][tx * 4];
            acc[0][0] = fmaf(q.x, k.x, acc[0][0]); acc[0][1] = fmaf(q.x, k.y, acc[0][1]);
            acc[0][2] = fmaf(q.x, k.z, acc[0][2]); acc[0][3] = fmaf(q.x, k.w, acc[0][3]);
            acc[1][0] = fmaf(q.y, k.x, acc[1][0]); acc[1][1] = fmaf(q.y, k.y, acc[1][1]);
            acc[1][2] = fmaf(q.y, k.z, acc[1][2]); acc[1][3] = fmaf(q.y, k.w, acc[1][3]);
            acc[2][0] = fmaf(q.z, k.x, acc[2][0]); acc[2][1] = fmaf(q.z, k.y, acc[2][1]);
            acc[2][2] = fmaf(q.z, k.z, acc[2][2]); acc[2][3] = fmaf(q.z, k.w, acc[2][3]);
            acc[3][0] = fmaf(q.w, k.x, acc[3][0]); acc[3][1] = fmaf(q.w, k.y, acc[3][1]);
            acc[3][2] = fmaf(q.w, k.z, acc[3][2]); acc[3][3] = fmaf(q.w, k.w, acc[3][3]);
        }
    }

    __syncthreads();
#pragma unroll
    for (int i = 0; i < 4; i++)
#pragma unroll
        for (int j = 0; j < 4; j++)
            bufB[ty * 4 + i][tx * 4 + j] = acc[i][j] * SCALE_F;
    __syncthreads();

    {
        const int w = tid >> 5, lane = tid & 31;
        const float hwv = hw[h];
        for (int rr = 0; rr < 8; rr++) {
            int row = w * 8 + rr;
            float v0 = bufB[row][lane];
            float v1 = bufB[row][lane + 32];
            float mx = fmaxf(v0, v1);
#pragma unroll
            for (int o = 16; o; o >>= 1) mx = fmaxf(mx, __shfl_xor_sync(0xffffffffu, mx, o));
            float e0 = __expf(v0 - mx), e1 = __expf(v1 - mx);
            float s = e0 + e1;
#pragma unroll
            for (int o = 16; o; o >>= 1) s += __shfl_xor_sync(0xffffffffu, s, o);
            float inv = 1.f / s;
            size_t ab = (size_t)h * 4096 + row * 64;
            bufB[row][lane]      = e0 * inv * hwv + adj[ab + lane];
            bufB[row][lane + 32] = e1 * inv * hwv + adj[ab + 32 + lane];
        }
    }

    for (int t0 = 0; t0 < 32; t0++) {
        __syncthreads();
        for (int mm = nl0; mm < 64; mm += 4) {
            bufA[mm][dkl] = Vm[base_v + (size_t)(mm * 32 + t0) * Dn + dkl];
        }
        __syncthreads();
        float o2[4][4];
#pragma unroll
        for (int i = 0; i < 4; i++)
#pragma unroll
            for (int j = 0; j < 4; j++) o2[i][j] = 0.f;
#pragma unroll 8
        for (int m = 0; m < 64; m++) {
            float4 v = *(const float4*)&bufA[m][tx * 4];
            float s0 = bufB[ty * 4 + 0][m];
            float s1 = bufB[ty * 4 + 1][m];
            float s2 = bufB[ty * 4 + 2][m];
            float s3 = bufB[ty * 4 + 3][m];
            o2[0][0] = fmaf(s0, v.x, o2[0][0]); o2[0][1] = fmaf(s0, v.y, o2[0][1]);
            o2[0][2] = fmaf(s0, v.z, o2[0][2]); o2[0][3] = fmaf(s0, v.w, o2[0][3]);
            o2[1][0] = fmaf(s1, v.x, o2[1][0]); o2[1][1] = fmaf(s1, v.y, o2[1][1]);
            o2[1][2] = fmaf(s1, v.z, o2[1][2]); o2[1][3] = fmaf(s1, v.w, o2[1][3]);
            o2[2][0] = fmaf(s2, v.x, o2[2][0]); o2[2][1] = fmaf(s2, v.y, o2[2][1]);
            o2[2][2] = fmaf(s2, v.z, o2[2][2]); o2[2][3] = fmaf(s2, v.w, o2[2][3]);
            o2[3][0] = fmaf(s3, v.x, o2[3][0]); o2[3][1] = fmaf(s3, v.y, o2[3][1]);
            o2[3][2] = fmaf(s3, v.z, o2[3][2]); o2[3][3] = fmaf(s3, v.w, o2[3][3]);
        }
#pragma unroll
        for (int i = 0; i < 4; i++) {
            int n = ty * 4 + i;
            size_t off = base_v + (size_t)(n * 32 + t0) * Dn + tx * 4;
            __nv_bfloat162 h0, l0, h1, l1;
            split2(o2[i][0], o2[i][1], h0, l0);
            split2(o2[i][2], o2[i][3], h1, l1);
            *(__nv_bfloat162*)&ATTh[off] = h0; *(__nv_bfloat162*)&ATTh[off + 2] = h1;
            *(__nv_bfloat162*)&ATTl[off] = l0; *(__nv_bfloat162*)&ATTl[off + 2] = l1;
        }
    }
}

// ------------------------------------------------------------------
// LayerNorm
// ------------------------------------------------------------------
__global__ void ln_partial(const float* __restrict__ Y1, float2* __restrict__ part) {
    const int c = blockIdx.x, b = blockIdx.y;
    const float* p = Y1 + (size_t)b * 1048576 + (size_t)c * 32768;
    float s = 0.f, s2 = 0.f;
    for (int i = threadIdx.x; i < 32768; i += 256) {
        float v = p[i];
        s += v; s2 += v * v;
    }
    __shared__ float rs[256], rs2[256];
    rs[threadIdx.x] = s; rs2[threadIdx.x] = s2;
    __syncthreads();
    for (int o = 128; o; o >>= 1) {
        if (threadIdx.x < o) {
            rs[threadIdx.x] += rs[threadIdx.x + o];
            rs2[threadIdx.x] += rs2[threadIdx.x + o];
        }
        __syncthreads();
    }
    if (threadIdx.x == 0) part[b * 32 + c] = make_float2(rs[0], rs2[0]);
}

__global__ void ln_final(const float2* __restrict__ part, float2* __restrict__ stats) {
    int b = threadIdx.x;
    if (b < Bn) {
        float s = 0.f, s2 = 0.f;
        for (int c = 0; c < 32; c++) {
            float2 p = part[b * 32 + c];
            s += p.x; s2 += p.y;
        }
        const float invN = 1.0f / 1048576.0f;
        float mean = s * invN;
        float var = s2 * invN - mean * mean;
        stats[b] = make_float2(mean, rsqrtf(var + LN_EPS));
    }
}

__global__ void ln_apply(const float* __restrict__ Y1, const float2* __restrict__ stats,
                         const float* __restrict__ g1, const float* __restrict__ be1,
                         float* __restrict__ X1,
                         __nv_bfloat16* __restrict__ X1h, __nv_bfloat16* __restrict__ X1l) {
    size_t e = ((size_t)blockIdx.x * blockDim.x + threadIdx.x) * 4;
    float2 st = stats[e >> 20];
    size_t gi = e & 1048575;
    float4 y = *(const float4*)&Y1[e];
    float4 g = *(const float4*)&g1[gi];
    float4 be = *(const float4*)&be1[gi];
    float4 o;
    o.x = (y.x - st.x) * st.y * g.x + be.x;
    o.y = (y.y - st.x) * st.y * g.y + be.y;
    o.z = (y.z - st.x) * st.y * g.z + be.z;
    o.w = (y.w - st.x) * st.y * g.w + be.w;
    *(float4*)&X1[e] = o;
    __nv_bfloat162 h0, l0, h1, l1;
    split2(o.x, o.y, h0, l0);
    split2(o.z, o.w, h1, l1);
    *(__nv_bfloat162*)&X1h[e] = h0; *(__nv_bfloat162*)&X1h[e + 2] = h1;
    *(__nv_bfloat162*)&X1l[e] = l0; *(__nv_bfloat162*)&X1l[e + 2] = l1;
}

// ------------------------------------------------------------------
// launch
// ------------------------------------------------------------------
extern "C" void kernel_launch(void* const* d_in, const int* in_sizes, int n_in,
                              void* d_out, int out_size) {
    const float* x   = (const float*)d_in[0];
    const float* Wq  = (const float*)d_in[1];
    const float* bq  = (const float*)d_in[2];
    const float* Wk  = (const float*)d_in[3];
    const float* bk  = (const float*)d_in[4];
    const float* Wv  = (const float*)d_in[5];
    const float* bv  = (const float*)d_in[6];
    const float* Wo  = (const float*)d_in[7];
    const float* bo  = (const float*)d_in[8];
    const float* W1  = (const float*)d_in[9];
    const float* b1  = (const float*)d_in[10];
    const float* W2  = (const float*)d_in[11];
    const float* b2  = (const float*)d_in[12];
    const float* g1  = (const float*)d_in[13];
    const float* be1 = (const float*)d_in[14];
    const float* adj = (const float*)d_in[15];
    const float* hw  = (const float*)d_in[16];
    const float* pe  = (const float*)d_in[17];
    float* out = (float*)d_out;

#define GETP(sym, ty, name) ty* name; { void* _p; cudaGetSymbolAddress(&_p, sym); name = (ty*)_p; }
    GETP(g_XR, float, XR) GETP(g_QK, float, QK) GETP(g_Vm, float, Vm)
    GETP(g_Y1, float, Y1) GETP(g_X1, float, X1) GETP(g_FF, float, FFo)
    GETP(g_XRh, __nv_bfloat16, XRh) GETP(g_XRl, __nv_bfloat16, XRl)
    GETP(g_XPEh, __nv_bfloat16, XPEh) GETP(g_XPEl, __nv_bfloat16, XPEl)
    GETP(g_ATTh, __nv_bfloat16, ATTh) GETP(g_ATTl, __nv_bfloat16, ATTl)
    GETP(g_X1h, __nv_bfloat16, X1h) GETP(g_X1l, __nv_bfloat16, X1l)
    GETP(g_Hh, __nv_bfloat16, Hh) GETP(g_Hl, __nv_bfloat16, Hl)
    GETP(g_Wqkh, __nv_bfloat16, Wqkh) GETP(g_Wqkl, __nv_bfloat16, Wqkl)
    GETP(g_Wvh, __nv_bfloat16, Wvh) GETP(g_Wvl, __nv_bfloat16, Wvl)
    GETP(g_Woh, __nv_bfloat16, Woh) GETP(g_Wol, __nv_bfloat16, Wol)
    GETP(g_W1h, __nv_bfloat16, W1h) GETP(g_W1l, __nv_bfloat16, W1l)
    GETP(g_W2h, __nv_bfloat16, W2h) GETP(g_W2l, __nv_bfloat16, W2l)
    GETP(g_bqk, float, bqk)
    GETP(g_part, float2, part) GETP(g_stats, float2, stats)
#undef GETP

    cudaFuncSetAttribute(gemm_mma<true, false, false, true, false>,
                         cudaFuncAttributeMaxDynamicSharedMemorySize, GEMM_DSMEM);
    cudaFuncSetAttribute(gemm_mma<true, false, true, true, false>,
                         cudaFuncAttributeMaxDynamicSharedMemorySize, GEMM_DSMEM);
    cudaFuncSetAttribute(gemm_mma<true, true, false, false, true>,
                         cudaFuncAttributeMaxDynamicSharedMemorySize, GEMM_DSMEM);

    // 0. fused weight conversion + bias concat
    conv_all<<<3073, 256>>>(Wq, Wk, Wv, Wo, W1, W2, bq, bk);

    // 1. transpose + split
    dim3 trGrid(16, 2, Bn * Tn);
    dim3 trBlk(32, 8);
    prep_xr<<<trGrid, trBlk>>>(x, pe, XR, XRh, XRl, XPEh, XPEl);

    // 2. fused Q+K projection (N=1024), V projection
    dim3 gQK(1024 / 128, MTOT / 256);  // (8, 256)
    gemm_mma<true, false, false, true, false><<<gQK, 256, GEMM_DSMEM>>>(
        XPEh, XPEl, Wqkh, Wqkl, bqk, nullptr, QK, nullptr, nullptr, 1024, Dn);
    dim3 gD(Dn / 128, MTOT / 256);     // (4, 256)
    gemm_mma<true, false, false, true, false><<<gD, 256, GEMM_DSMEM>>>(
        XRh, XRl, Wvh, Wvl, bv, nullptr, Vm, nullptr, nullptr, Dn, Dn);

    // 3. attention
    attn_kernel<<<Bn * Hn, 256>>>(QK, Vm, adj, hw, ATTh, ATTl);

    // 4. output projection + residual (launch index 5 -> profiled)
    gemm_mma<true, false, true, true, false><<<gD, 256, GEMM_DSMEM>>>(
        ATTh, ATTl, Woh, Wol, bo, XR, Y1, nullptr, nullptr, Dn, Dn);

    // 5. layernorm
    ln_partial<<<dim3(32, Bn), 256>>>(Y1, part);
    ln_final<<<1, 32>>>(part, stats);
    ln_apply<<<(MTOT * (size_t)Dn / 4) / 256, 256>>>(Y1, stats, g1, be1, X1, X1h, X1l);

    // 6. FFN
    dim3 gF1(FFn / 128, MTOT / 256);   // (16, 256)
    gemm_mma<true, true, false, false, true><<<gF1, 256, GEMM_DSMEM>>>(
        X1h, X1l, W1h, W1l, b1, nullptr, nullptr, Hh, Hl, FFn, Dn);
    gemm_mma<true, false, true, true, false><<<gD, 256, GEMM_DSMEM>>>(
        Hh, Hl, W2h, W2l, b2, X1, FFo, nullptr, nullptr, Dn, FFn);

    // 7. output transpose
    out_tr<<<trGrid, trBlk>>>(FFo, out);
}

// round 7
// speedup vs baseline: 2.6664x; 1.1025x over previous
#include <cuda_runtime.h>
#include <cuda_bf16.h>
#include <cstdint>
#include <math.h>

// Problem dims
#define Bn 32
#define Dn 512
#define Tn 32
#define Nn 64
#define Hn 8
#define DKn 64
#define FFn 2048
#define MTOT (Bn * Nn * Tn)
#define SCALE_F 0.022097086912079608f
#define LN_EPS 1e-5f

// ------------------------------------------------------------------
// Scratch
// ------------------------------------------------------------------
__device__ float g_XR[(size_t)MTOT * Dn];
__device__ float g_QK[(size_t)MTOT * 1024];
__device__ float g_Vm[(size_t)MTOT * Dn];
__device__ float g_Y1[(size_t)MTOT * Dn];
__device__ float g_X1[(size_t)MTOT * Dn];
__device__ float g_FF[(size_t)MTOT * Dn];
__device__ __nv_bfloat16 g_XRh[(size_t)MTOT * Dn], g_XRl[(size_t)MTOT * Dn];
__device__ __nv_bfloat16 g_XPEh[(size_t)MTOT * Dn], g_XPEl[(size_t)MTOT * Dn];
__device__ __nv_bfloat16 g_ATTh[(size_t)MTOT * Dn], g_ATTl[(size_t)MTOT * Dn];
__device__ __nv_bfloat16 g_X1h[(size_t)MTOT * Dn], g_X1l[(size_t)MTOT * Dn];
__device__ __nv_bfloat16 g_Hh[(size_t)MTOT * FFn], g_Hl[(size_t)MTOT * FFn];
__device__ __nv_bfloat16 g_Wqkh[1024 * Dn], g_Wqkl[1024 * Dn];
__device__ __nv_bfloat16 g_Wvh[Dn * Dn], g_Wvl[Dn * Dn];
__device__ __nv_bfloat16 g_Woh[Dn * Dn], g_Wol[Dn * Dn];
__device__ __nv_bfloat16 g_W1h[FFn * Dn], g_W1l[FFn * Dn];
__device__ __nv_bfloat16 g_W2h[Dn * FFn], g_W2l[Dn * FFn];
__device__ float g_bqk[1024];
__device__ float2 g_part[Bn * 32];
__device__ float2 g_stats[Bn];

// ------------------------------------------------------------------
// PTX helpers (compute_100-safe)
// ------------------------------------------------------------------
__device__ __forceinline__ uint32_t smem_u32(const void* p) {
    uint32_t a;
    asm("{ .reg .u64 t; cvta.to.shared.u64 t, %1; cvt.u32.u64 %0, t; }" : "=r"(a) : "l"(p));
    return a;
}
__device__ __forceinline__ void cpasync16(uint32_t dst, const void* src) {
    asm volatile("cp.async.cg.shared.global [%0], [%1], 16;" :: "r"(dst), "l"(src));
}
#define CP_COMMIT() asm volatile("cp.async.commit_group;" ::: "memory")
#define CP_WAIT0() asm volatile("cp.async.wait_group 0;" ::: "memory")

#define LDSM4(r0, r1, r2, r3, addr) \
    asm volatile("ldmatrix.sync.aligned.m8n8.x4.shared.b16 {%0,%1,%2,%3}, [%4];" \
                 : "=r"(r0), "=r"(r1), "=r"(r2), "=r"(r3) : "r"(addr))

#define MMA_BF16(d, a, b) \
    asm volatile("mma.sync.aligned.m16n8k16.row.col.f32.bf16.bf16.f32 " \
                 "{%0,%1,%2,%3}, {%4,%5,%6,%7}, {%8,%9}, {%0,%1,%2,%3};" \
                 : "+f"((d)[0]), "+f"((d)[1]), "+f"((d)[2]), "+f"((d)[3]) \
                 : "r"((a)[0]), "r"((a)[1]), "r"((a)[2]), "r"((a)[3]), \
                   "r"((b)[0]), "r"((b)[1]))

__device__ __forceinline__ void split2(float a, float b, __nv_bfloat162& h, __nv_bfloat162& l) {
    h = __floats2bfloat162_rn(a, b);
    l = __floats2bfloat162_rn(a - __low2float(h), b - __high2float(h));
}

// ------------------------------------------------------------------
// fused weight conversion (+ bias concat)
// ------------------------------------------------------------------
__global__ void conv_all(const float* __restrict__ Wq, const float* __restrict__ Wk,
                         const float* __restrict__ Wv, const float* __restrict__ Wo,
                         const float* __restrict__ W1, const float* __restrict__ W2,
                         const float* __restrict__ bq, const float* __restrict__ bk) {
    long i4 = (long)blockIdx.x * 256 + threadIdx.x;
    if (i4 >= 786432) {
        int t = threadIdx.x;
        if (blockIdx.x == 3072) {
            g_bqk[t] = bq[t];
            g_bqk[t + 256] = bq[t + 256];
            g_bqk[t + 512] = bk[t];
            g_bqk[t + 768] = bk[t + 256];
        }
        return;
    }
    const float* src;
    __nv_bfloat16 *dh, *dl;
    long o;
    if (i4 < 65536)       { src = Wq; dh = g_Wqkh;          dl = g_Wqkl;          o = i4; }
    else if (i4 < 131072) { src = Wk; dh = g_Wqkh + 262144; dl = g_Wqkl + 262144; o = i4 - 65536; }
    else if (i4 < 196608) { src = Wv; dh = g_Wvh;           dl = g_Wvl;           o = i4 - 131072; }
    else if (i4 < 262144) { src = Wo; dh = g_Woh;           dl = g_Wol;           o = i4 - 196608; }
    else if (i4 < 524288) { src = W1; dh = g_W1h;           dl = g_W1l;           o = i4 - 262144; }
    else                  { src = W2; dh = g_W2h;           dl = g_W2l;           o = i4 - 524288; }
    long e = o * 4;
    float4 v = *(const float4*)&src[e];
    __nv_bfloat162 h0, l0, h1, l1;
    split2(v.x, v.y, h0, l0);
    split2(v.z, v.w, h1, l1);
    *(__nv_bfloat162*)&dh[e] = h0; *(__nv_bfloat162*)&dh[e + 2] = h1;
    *(__nv_bfloat162*)&dl[e] = l0; *(__nv_bfloat162*)&dl[e + 2] = l1;
}

// ------------------------------------------------------------------
// prep / out transpose
// ------------------------------------------------------------------
__global__ void prep_xr(const float* __restrict__ x, const float* __restrict__ pe,
                        float* __restrict__ XR,
                        __nv_bfloat16* __restrict__ XRh, __nv_bfloat16* __restrict__ XRl,
                        __nv_bfloat16* __restrict__ XPEh, __nv_bfloat16* __restrict__ XPEl) {
    __shared__ float tile[32][33];
    int bt = blockIdx.z;
    int b = bt >> 5, t = bt & 31;
    int d0 = blockIdx.x * 32, n0 = blockIdx.y * 32;
    size_t bbase = (size_t)b * (Dn * Tn * Nn);
#pragma unroll
    for (int i = 0; i < 4; i++) {
        int d = d0 + threadIdx.y + i * 8;
        tile[threadIdx.y + i * 8][threadIdx.x] =
            x[bbase + (size_t)d * (Tn * Nn) + t * Nn + n0 + threadIdx.x];
    }
    __syncthreads();
    int d = d0 + threadIdx.x;
#pragma unroll
    for (int i = 0; i < 4; i++) {
        int n = n0 + threadIdx.y + i * 8;
        float v = tile[threadIdx.x][threadIdx.y + i * 8];
        size_t idx = bbase + (size_t)n * (Tn * Dn) + t * Dn + d;
        XR[idx] = v;
        __nv_bfloat16 h = __float2bfloat16(v);
        XRh[idx] = h;
        XRl[idx] = __float2bfloat16(v - __bfloat162float(h));
        float vp = v + pe[n * Dn + d];
        __nv_bfloat16 hp = __float2bfloat16(vp);
        XPEh[idx] = hp;
        XPEl[idx] = __float2bfloat16(vp - __bfloat162float(hp));
    }
}

__global__ void out_tr(const float* __restrict__ FF, float* __restrict__ out) {
    __shared__ float tile[32][33];
    int bt = blockIdx.z;
    int b = bt >> 5, t = bt & 31;
    int d0 = blockIdx.x * 32, n0 = blockIdx.y * 32;
    size_t bbase = (size_t)b * (Dn * Tn * Nn);
#pragma unroll
    for (int i = 0; i < 4; i++) {
        int n = n0 + threadIdx.y + i * 8;
        tile[threadIdx.y + i * 8][threadIdx.x] =
            FF[bbase + (size_t)n * (Tn * Dn) + t * Dn + d0 + threadIdx.x];
    }
    __syncthreads();
#pragma unroll
    for (int i = 0; i < 4; i++) {
        int d = d0 + threadIdx.y + i * 8;
        out[bbase + (size_t)d * (Tn * Nn) + t * Nn + n0 + threadIdx.x] =
            tile[threadIdx.x][threadIdx.y + i * 8];
    }
}

// ------------------------------------------------------------------
// mma.sync split-bf16 GEMM: 256x128 CTA tile, warp 64x64 (8 warps 4x2),
// BK=64, 2-stage cp.async, ONE barrier per K-iter, pitch-144 SMEM
// ((r+c) mod 8 chunk permutation -> conflict-free ldmatrix).
// ------------------------------------------------------------------
#define PITCHB 144
#define OFF_AH 0
#define OFF_AL (256 * PITCHB)                 // 36864
#define OFF_BH (2 * 256 * PITCHB)             // 73728
#define OFF_BL (OFF_BH + 128 * PITCHB)        // 92160
#define STAGEB (OFF_BL + 128 * PITCHB)        // 110592
#define GEMM_DSMEM (2 * STAGEB)               // 221184

template <int ROWS>
__device__ __forceinline__ void load_tile(uint32_t sdst, const __nv_bfloat16* __restrict__ g,
                                          size_t row0, int K, int k0, int tid) {
    const char* gbase = (const char*)(g + row0 * (size_t)K + k0);
    size_t rs = (size_t)K * 2;
#pragma unroll
    for (int ch = tid; ch < ROWS * 8; ch += 256) {
        int r = ch >> 3, c = ch & 7;
        cpasync16(sdst + r * PITCHB + c * 16, gbase + (size_t)r * rs + c * 16);
    }
}

template <bool BIAS_, bool RELU_, bool RESID_, bool OUTF_, bool OUTHL_>
__global__ void __launch_bounds__(256, 1)
gemm_mma(const __nv_bfloat16* __restrict__ Ah, const __nv_bfloat16* __restrict__ Al,
         const __nv_bfloat16* __restrict__ Wh, const __nv_bfloat16* __restrict__ Wl,
         const float* __restrict__ bias, const float* __restrict__ Rsd,
         float* __restrict__ Cf, __nv_bfloat16* __restrict__ Ch, __nv_bfloat16* __restrict__ Cl,
         int Ncols, int K) {
    extern __shared__ char smraw[];
    const uint32_t sb = smem_u32(smraw);
    const int tid = threadIdx.x;
    const int wid = tid >> 5;
    const int lane = tid & 31;
    const size_t rowBase = (size_t)blockIdx.y * 256;
    const int colBase = blockIdx.x * 128;
    const int wm = (wid >> 1) * 64;
    const int wn = (wid & 1) * 64;

    float acc[4][8][4];
#pragma unroll
    for (int mt = 0; mt < 4; mt++)
#pragma unroll
        for (int nt = 0; nt < 8; nt++)
#pragma unroll
            for (int q = 0; q < 4; q++) acc[mt][nt][q] = 0.f;

    const int KIT = K >> 6;

    // prologue: stage 0
    load_tile<256>(sb + OFF_AH, Ah, rowBase, K, 0, tid);
    load_tile<256>(sb + OFF_AL, Al, rowBase, K, 0, tid);
    load_tile<128>(sb + OFF_BH, Wh, (size_t)colBase, K, 0, tid);
    load_tile<128>(sb + OFF_BL, Wl, (size_t)colBase, K, 0, tid);
    CP_COMMIT();

    const int arow = lane & 15;
    const int ainc = lane >> 4;
    const int brow = (lane & 7) + ((lane >> 4) << 3);
    const int binc = (lane >> 3) & 1;

    for (int it = 0; it < KIT; ++it) {
        CP_WAIT0();
        __syncthreads();
        // issue next-stage loads FIRST so they overlap the MMA block below
        if (it + 1 < KIT) {
            uint32_t st = sb + ((it + 1) & 1) * STAGEB;
            int k0 = (it + 1) * 64;
            load_tile<256>(st + OFF_AH, Ah, rowBase, K, k0, tid);
            load_tile<256>(st + OFF_AL, Al, rowBase, K, k0, tid);
            load_tile<128>(st + OFF_BH, Wh, (size_t)colBase, K, k0, tid);
            load_tile<128>(st + OFF_BL, Wl, (size_t)colBase, K, k0, tid);
        }
        CP_COMMIT();
        const uint32_t stb = sb + (it & 1) * STAGEB;
#pragma unroll
        for (int kc = 0; kc < 4; kc++) {
            uint32_t ah[4][4], alr[4][4], bh[8][2], bl[8][2];
#pragma unroll
            for (int mt = 0; mt < 4; mt++) {
                uint32_t ad = stb + OFF_AH + (wm + mt * 16 + arow) * PITCHB + kc * 32 + ainc * 16;
                LDSM4(ah[mt][0], ah[mt][1], ah[mt][2], ah[mt][3], ad);
                LDSM4(alr[mt][0], alr[mt][1], alr[mt][2], alr[mt][3], ad + (OFF_AL - OFF_AH));
            }
#pragma unroll
            for (int bt = 0; bt < 4; bt++) {
                uint32_t bd = stb + OFF_BH + (wn + bt * 16 + brow) * PITCHB + kc * 32 + binc * 16;
                uint32_t r0, r1, r2, r3;
                LDSM4(r0, r1, r2, r3, bd);
                bh[2 * bt][0] = r0; bh[2 * bt][1] = r1;
                bh[2 * bt + 1][0] = r2; bh[2 * bt + 1][1] = r3;
                LDSM4(r0, r1, r2, r3, bd + (OFF_BL - OFF_BH));
                bl[2 * bt][0] = r0; bl[2 * bt][1] = r1;
                bl[2 * bt + 1][0] = r2; bl[2 * bt + 1][1] = r3;
            }
#pragma unroll
            for (int mt = 0; mt < 4; mt++) {
#pragma unroll
                for (int nt = 0; nt < 8; nt++) {
                    MMA_BF16(acc[mt][nt], ah[mt], bh[nt]);
                    MMA_BF16(acc[mt][nt], ah[mt], bl[nt]);
                    MMA_BF16(acc[mt][nt], alr[mt], bh[nt]);
                }
            }
        }
    }

    // epilogue
#pragma unroll
    for (int mt = 0; mt < 4; mt++) {
#pragma unroll
        for (int nt = 0; nt < 8; nt++) {
            const int col = colBase + wn + nt * 8 + (lane & 3) * 2;
#pragma unroll
            for (int half = 0; half < 2; half++) {
                const size_t row = rowBase + wm + mt * 16 + (lane >> 2) + half * 8;
                float vx = acc[mt][nt][half * 2 + 0];
                float vy = acc[mt][nt][half * 2 + 1];
                if (BIAS_) {
                    float2 bv = *(const float2*)&bias[col];
                    vx += bv.x; vy += bv.y;
                }
                if (RELU_) { vx = fmaxf(vx, 0.f); vy = fmaxf(vy, 0.f); }
                if (RESID_) {
                    float2 rv = *(const float2*)&Rsd[row * Ncols + col];
                    vx += rv.x; vy += rv.y;
                }
                if (OUTF_) {
                    *(float2*)&Cf[row * Ncols + col] = make_float2(vx, vy);
                }
                if (OUTHL_) {
                    __nv_bfloat162 Hv, Lv;
                    split2(vx, vy, Hv, Lv);
                    *(__nv_bfloat162*)&Ch[row * Ncols + col] = Hv;
                    *(__nv_bfloat162*)&Cl[row * Ncols + col] = Lv;
                }
            }
        }
    }
}

// ------------------------------------------------------------------
// Attention (fp32 FFMA); Q,K from fused QK buffer (row stride 1024)
// ------------------------------------------------------------------
__global__ void __launch_bounds__(256)
attn_kernel(const float* __restrict__ QK, const float* __restrict__ Vm,
            const float* __restrict__ adj, const float* __restrict__ hw,
            __nv_bfloat16* __restrict__ ATTh, __nv_bfloat16* __restrict__ ATTl) {
    __shared__ float bufA[64][68];
    __shared__ float bufB[64][68];

    const int b = blockIdx.x >> 3;
    const int h = blockIdx.x & 7;
    const int tid = threadIdx.x;
    const int ty = tid >> 4;
    const int tx = tid & 15;
    const int dkl = tid & 63;
    const int nl0 = tid >> 6;

    const size_t base_q = ((size_t)b * 2048) * 1024 + h * DKn;
    const size_t base_k = base_q + 512;
    const size_t base_v = ((size_t)b * 2048) * Dn + h * DKn;

    float acc[4][4];
#pragma unroll
    for (int i = 0; i < 4; i++)
#pragma unroll
        for (int j = 0; j < 4; j++) acc[i][j] = 0.f;

    for (int t0 = 0; t0 < 32; t0++) {
        __syncthreads();
        for (int nn = nl0; nn < 64; nn += 4) {
            size_t off = (size_t)(nn * 32 + t0) * 1024 + dkl;
            bufA[dkl][nn] = QK[base_q + off];
            bufB[dkl][nn] = QK[base_k + off];
        }
        __syncthreads();
#pragma unroll 8
        for (int dk = 0; dk < 64; dk++) {
            float4 q = *(const float4*)&bufA[dk][ty * 4];
            float4 k = *(const float4*)&bufB[dk][tx * 4];
            acc[0][0] = fmaf(q.x, k.x, acc[0][0]); acc[0][1] = fmaf(q.x, k.y, acc[0][1]);
            acc[0][2] = fmaf(q.x, k.z, acc[0][2]); acc[0][3] = fmaf(q.x, k.w, acc[0][3]);
            acc[1][0] = fmaf(q.y, k.x, acc[1][0]); acc[1][1] = fmaf(q.y, k.y, acc[1][1]);
            acc[1][2] = fmaf(q.y, k.z, acc[1][2]); acc[1][3] = fmaf(q.y, k.w, acc[1][3]);
            acc[2][0] = fmaf(q.z, k.x, acc[2][0]); acc[2][1] = fmaf(q.z, k.y, acc[2][1]);
            acc[2][2] = fmaf(q.z, k.z, acc[2][2]); acc[2][3] = fmaf(q.z, k.w, acc[2][3]);
            acc[3][0] = fmaf(q.w, k.x, acc[3][0]); acc[3][1] = fmaf(q.w, k.y, acc[3][1]);
            acc[3][2] = fmaf(q.w, k.z, acc[3][2]); acc[3][3] = fmaf(q.w, k.w, acc[3][3]);
        }
    }

    __syncthreads();
#pragma unroll
    for (int i = 0; i < 4; i++)
#pragma unroll
        for (int j = 0; j < 4; j++)
            bufB[ty * 4 + i][tx * 4 + j] = acc[i][j] * SCALE_F;
    __syncthreads();

    {
        const int w = tid >> 5, lane = tid & 31;
        const float hwv = hw[h];
        for (int rr = 0; rr < 8; rr++) {
            int row = w * 8 + rr;
            float v0 = bufB[row][lane];
            float v1 = bufB[row][lane + 32];
            float mx = fmaxf(v0, v1);
#pragma unroll
            for (int o = 16; o; o >>= 1) mx = fmaxf(mx, __shfl_xor_sync(0xffffffffu, mx, o));
            float e0 = __expf(v0 - mx), e1 = __expf(v1 - mx);
            float s = e0 + e1;
#pragma unroll
            for (int o = 16; o; o >>= 1) s += __shfl_xor_sync(0xffffffffu, s, o);
            float inv = 1.f / s;
            size_t ab = (size_t)h * 4096 + row * 64;
            bufB[row][lane]      = e0 * inv * hwv + adj[ab + lane];
            bufB[row][lane + 32] = e1 * inv * hwv + adj[ab + 32 + lane];
        }
    }

    for (int t0 = 0; t0 < 32; t0++) {
        __syncthreads();
        for (int mm = nl0; mm < 64; mm += 4) {
            bufA[mm][dkl] = Vm[base_v + (size_t)(mm * 32 + t0) * Dn + dkl];
        }
        __syncthreads();
        float o2[4][4];
#pragma unroll
        for (int i = 0; i < 4; i++)
#pragma unroll
            for (int j = 0; j < 4; j++) o2[i][j] = 0.f;
#pragma unroll 8
        for (int m = 0; m < 64; m++) {
            float4 v = *(const float4*)&bufA[m][tx * 4];
            float s0 = bufB[ty * 4 + 0][m];
            float s1 = bufB[ty * 4 + 1][m];
            float s2 = bufB[ty * 4 + 2][m];
            float s3 = bufB[ty * 4 + 3][m];
            o2[0][0] = fmaf(s0, v.x, o2[0][0]); o2[0][1] = fmaf(s0, v.y, o2[0][1]);
            o2[0][2] = fmaf(s0, v.z, o2[0][2]); o2[0][3] = fmaf(s0, v.w, o2[0][3]);
            o2[1][0] = fmaf(s1, v.x, o2[1][0]); o2[1][1] = fmaf(s1, v.y, o2[1][1]);
            o2[1][2] = fmaf(s1, v.z, o2[1][2]); o2[1][3] = fmaf(s1, v.w, o2[1][3]);
            o2[2][0] = fmaf(s2, v.x, o2[2][0]); o2[2][1] = fmaf(s2, v.y, o2[2][1]);
            o2[2][2] = fmaf(s2, v.z, o2[2][2]); o2[2][3] = fmaf(s2, v.w, o2[2][3]);
            o2[3][0] = fmaf(s3, v.x, o2[3][0]); o2[3][1] = fmaf(s3, v.y, o2[3][1]);
            o2[3][2] = fmaf(s3, v.z, o2[3][2]); o2[3][3] = fmaf(s3, v.w, o2[3][3]);
        }
#pragma unroll
        for (int i = 0; i < 4; i++) {
            int n = ty * 4 + i;
            size_t off = base_v + (size_t)(n * 32 + t0) * Dn + tx * 4;
            __nv_bfloat162 h0, l0, h1, l1;
            split2(o2[i][0], o2[i][1], h0, l0);
            split2(o2[i][2], o2[i][3], h1, l1);
            *(__nv_bfloat162*)&ATTh[off] = h0; *(__nv_bfloat162*)&ATTh[off + 2] = h1;
            *(__nv_bfloat162*)&ATTl[off] = l0; *(__nv_bfloat162*)&ATTl[off + 2] = l1;
        }
    }
}

// ------------------------------------------------------------------
// LayerNorm
// ------------------------------------------------------------------
__global__ void ln_partial(const float* __restrict__ Y1, float2* __restrict__ part) {
    const int c = blockIdx.x, b = blockIdx.y;
    const float* p = Y1 + (size_t)b * 1048576 + (size_t)c * 32768;
    float s = 0.f, s2 = 0.f;
    for (int i = threadIdx.x; i < 32768; i += 256) {
        float v = p[i];
        s += v; s2 += v * v;
    }
    __shared__ float rs[256], rs2[256];
    rs[threadIdx.x] = s; rs2[threadIdx.x] = s2;
    __syncthreads();
    for (int o = 128; o; o >>= 1) {
        if (threadIdx.x < o) {
            rs[threadIdx.x] += rs[threadIdx.x + o];
            rs2[threadIdx.x] += rs2[threadIdx.x + o];
        }
        __syncthreads();
    }
    if (threadIdx.x == 0) part[b * 32 + c] = make_float2(rs[0], rs2[0]);
}

__global__ void ln_final(const float2* __restrict__ part, float2* __restrict__ stats) {
    int b = threadIdx.x;
    if (b < Bn) {
        float s = 0.f, s2 = 0.f;
        for (int c = 0; c < 32; c++) {
            float2 p = part[b * 32 + c];
            s += p.x; s2 += p.y;
        }
        const float invN = 1.0f / 1048576.0f;
        float mean = s * invN;
        float var = s2 * invN - mean * mean;
        stats[b] = make_float2(mean, rsqrtf(var + LN_EPS));
    }
}

__global__ void ln_apply(const float* __restrict__ Y1, const float2* __restrict__ stats,
                         const float* __restrict__ g1, const float* __restrict__ be1,
                         float* __restrict__ X1,
                         __nv_bfloat16* __restrict__ X1h, __nv_bfloat16* __restrict__ X1l) {
    size_t e = ((size_t)blockIdx.x * blockDim.x + threadIdx.x) * 4;
    float2 st = stats[e >> 20];
    size_t gi = e & 1048575;
    float4 y = *(const float4*)&Y1[e];
    float4 g = *(const float4*)&g1[gi];
    float4 be = *(const float4*)&be1[gi];
    float4 o;
    o.x = (y.x - st.x) * st.y * g.x + be.x;
    o.y = (y.y - st.x) * st.y * g.y + be.y;
    o.z = (y.z - st.x) * st.y * g.z + be.z;
    o.w = (y.w - st.x) * st.y * g.w + be.w;
    *(float4*)&X1[e] = o;
    __nv_bfloat162 h0, l0, h1, l1;
    split2(o.x, o.y, h0, l0);
    split2(o.z, o.w, h1, l1);
    *(__nv_bfloat162*)&X1h[e] = h0; *(__nv_bfloat162*)&X1h[e + 2] = h1;
    *(__nv_bfloat162*)&X1l[e] = l0; *(__nv_bfloat162*)&X1l[e + 2] = l1;
}

// ------------------------------------------------------------------
// launch
// ------------------------------------------------------------------
extern "C" void kernel_launch(void* const* d_in, const int* in_sizes, int n_in,
                              void* d_out, int out_size) {
    const float* x   = (const float*)d_in[0];
    const float* Wq  = (const float*)d_in[1];
    const float* bq  = (const float*)d_in[2];
    const float* Wk  = (const float*)d_in[3];
    const float* bk  = (const float*)d_in[4];
    const float* Wv  = (const float*)d_in[5];
    const float* bv  = (const float*)d_in[6];
    const float* Wo  = (const float*)d_in[7];
    const float* bo  = (const float*)d_in[8];
    const float* W1  = (const float*)d_in[9];
    const float* b1  = (const float*)d_in[10];
    const float* W2  = (const float*)d_in[11];
    const float* b2  = (const float*)d_in[12];
    const float* g1  = (const float*)d_in[13];
    const float* be1 = (const float*)d_in[14];
    const float* adj = (const float*)d_in[15];
    const float* hw  = (const float*)d_in[16];
    const float* pe  = (const float*)d_in[17];
    float* out = (float*)d_out;

#define GETP(sym, ty, name) ty* name; { void* _p; cudaGetSymbolAddress(&_p, sym); name = (ty*)_p; }
    GETP(g_XR, float, XR) GETP(g_QK, float, QK) GETP(g_Vm, float, Vm)
    GETP(g_Y1, float, Y1) GETP(g_X1, float, X1) GETP(g_FF, float, FFo)
    GETP(g_XRh, __nv_bfloat16, XRh) GETP(g_XRl, __nv_bfloat16, XRl)
    GETP(g_XPEh, __nv_bfloat16, XPEh) GETP(g_XPEl, __nv_bfloat16, XPEl)
    GETP(g_ATTh, __nv_bfloat16, ATTh) GETP(g_ATTl, __nv_bfloat16, ATTl)
    GETP(g_X1h, __nv_bfloat16, X1h) GETP(g_X1l, __nv_bfloat16, X1l)
    GETP(g_Hh, __nv_bfloat16, Hh) GETP(g_Hl, __nv_bfloat16, Hl)
    GETP(g_Wqkh, __nv_bfloat16, Wqkh) GETP(g_Wqkl, __nv_bfloat16, Wqkl)
    GETP(g_Wvh, __nv_bfloat16, Wvh) GETP(g_Wvl, __nv_bfloat16, Wvl)
    GETP(g_Woh, __nv_bfloat16, Woh) GETP(g_Wol, __nv_bfloat16, Wol)
    GETP(g_W1h, __nv_bfloat16, W1h) GETP(g_W1l, __nv_bfloat16, W1l)
    GETP(g_W2h, __nv_bfloat16, W2h) GETP(g_W2l, __nv_bfloat16, W2l)
    GETP(g_bqk, float, bqk)
    GETP(g_part, float2, part) GETP(g_stats, float2, stats)
#undef GETP

    cudaFuncSetAttribute(gemm_mma<true, false, false, true, false>,
                         cudaFuncAttributeMaxDynamicSharedMemorySize, GEMM_DSMEM);
    cudaFuncSetAttribute(gemm_mma<true, false, true, true, false>,
                         cudaFuncAttributeMaxDynamicSharedMemorySize, GEMM_DSMEM);
    cudaFuncSetAttribute(gemm_mma<true, true, false, false, true>,
                         cudaFuncAttributeMaxDynamicSharedMemorySize, GEMM_DSMEM);

    // 0. fused weight conversion + bias concat
    conv_all<<<3073, 256>>>(Wq, Wk, Wv, Wo, W1, W2, bq, bk);

    // 1. transpose + split
    dim3 trGrid(16, 2, Bn * Tn);
    dim3 trBlk(32, 8);
    prep_xr<<<trGrid, trBlk>>>(x, pe, XR, XRh, XRl, XPEh, XPEl);

    // 2. fused Q+K projection (N=1024), V projection
    dim3 gQK(1024 / 128, MTOT / 256);  // (8, 256)
    gemm_mma<true, false, false, true, false><<<gQK, 256, GEMM_DSMEM>>>(
        XPEh, XPEl, Wqkh, Wqkl, bqk, nullptr, QK, nullptr, nullptr, 1024, Dn);
    dim3 gD(Dn / 128, MTOT / 256);     // (4, 256)
    gemm_mma<true, false, false, true, false><<<gD, 256, GEMM_DSMEM>>>(
        XRh, XRl, Wvh, Wvl, bv, nullptr, Vm, nullptr, nullptr, Dn, Dn);

    // 3. attention
    attn_kernel<<<Bn * Hn, 256>>>(QK, Vm, adj, hw, ATTh, ATTl);

    // 4. output projection + residual (launch index 5 -> profiled)
    gemm_mma<true, false, true, true, false><<<gD, 256, GEMM_DSMEM>>>(
        ATTh, ATTl, Woh, Wol, bo, XR, Y1, nullptr, nullptr, Dn, Dn);

    // 5. layernorm
    ln_partial<<<dim3(32, Bn), 256>>>(Y1, part);
    ln_final<<<1, 32>>>(part, stats);
    ln_apply<<<(MTOT * (size_t)Dn / 4) / 256, 256>>>(Y1, stats, g1, be1, X1, X1h, X1l);

    // 6. FFN
    dim3 gF1(FFn / 128, MTOT / 256);   // (16, 256)
    gemm_mma<true, true, false, false, true><<<gF1, 256, GEMM_DSMEM>>>(
        X1h, X1l, W1h, W1l, b1, nullptr, nullptr, Hh, Hl, FFn, Dn);
    gemm_mma<true, false, true, true, false><<<gD, 256, GEMM_DSMEM>>>(
        Hh, Hl, W2h, W2l, b2, X1, FFo, nullptr, nullptr, Dn, FFn);

    // 7. output transpose
    out_tr<<<trGrid, trBlk>>>(FFo, out);
}

// round 9
// speedup vs baseline: 2.8430x; 1.0662x over previous
#include <cuda_runtime.h>
#include <cuda_bf16.h>
#include <cstdint>
#include <math.h>

// Problem dims
#define Bn 32
#define Dn 512
#define Tn 32
#define Nn 64
#define Hn 8
#define DKn 64
#define FFn 2048
#define MTOT (Bn * Nn * Tn)
#define SCALE_F 0.022097086912079608f
#define LN_EPS 1e-5f

// ------------------------------------------------------------------
// Scratch
// ------------------------------------------------------------------
__device__ float g_XR[(size_t)MTOT * Dn];
__device__ float g_QK[(size_t)MTOT * 1024];
__device__ float g_Vm[(size_t)MTOT * Dn];
__device__ float g_Y1[(size_t)MTOT * Dn];
__device__ float g_X1[(size_t)MTOT * Dn];
__device__ float g_FF[(size_t)MTOT * Dn];
__device__ __nv_bfloat16 g_XRh[(size_t)MTOT * Dn], g_XRl[(size_t)MTOT * Dn];
__device__ __nv_bfloat16 g_XPEh[(size_t)MTOT * Dn], g_XPEl[(size_t)MTOT * Dn];
__device__ __nv_bfloat16 g_ATTh[(size_t)MTOT * Dn], g_ATTl[(size_t)MTOT * Dn];
__device__ __nv_bfloat16 g_X1h[(size_t)MTOT * Dn], g_X1l[(size_t)MTOT * Dn];
__device__ __nv_bfloat16 g_Hh[(size_t)MTOT * FFn], g_Hl[(size_t)MTOT * FFn];
__device__ __nv_bfloat16 g_Wqkh[1024 * Dn], g_Wqkl[1024 * Dn];
__device__ __nv_bfloat16 g_Wvh[Dn * Dn], g_Wvl[Dn * Dn];
__device__ __nv_bfloat16 g_Woh[Dn * Dn], g_Wol[Dn * Dn];
__device__ __nv_bfloat16 g_W1h[FFn * Dn], g_W1l[FFn * Dn];
__device__ __nv_bfloat16 g_W2h[Dn * FFn], g_W2l[Dn * FFn];
__device__ float g_bqk[1024];
__device__ float2 g_part[Bn * 32];
__device__ float2 g_stats[Bn];

// ------------------------------------------------------------------
// PTX helpers (compute_100-safe)
// ------------------------------------------------------------------
__device__ __forceinline__ uint32_t smem_u32(const void* p) {
    uint32_t a;
    asm("{ .reg .u64 t; cvta.to.shared.u64 t, %1; cvt.u32.u64 %0, t; }" : "=r"(a) : "l"(p));
    return a;
}
__device__ __forceinline__ void cpasync16(uint32_t dst, const void* src) {
    asm volatile("cp.async.cg.shared.global [%0], [%1], 16;" :: "r"(dst), "l"(src));
}
#define CP_COMMIT() asm volatile("cp.async.commit_group;" ::: "memory")
#define CP_WAIT0() asm volatile("cp.async.wait_group 0;" ::: "memory")

#define LDSM4(r0, r1, r2, r3, addr) \
    asm volatile("ldmatrix.sync.aligned.m8n8.x4.shared.b16 {%0,%1,%2,%3}, [%4];" \
                 : "=r"(r0), "=r"(r1), "=r"(r2), "=r"(r3) : "r"(addr))

#define MMA_BF16(d, a, b) \
    asm volatile("mma.sync.aligned.m16n8k16.row.col.f32.bf16.bf16.f32 " \
                 "{%0,%1,%2,%3}, {%4,%5,%6,%7}, {%8,%9}, {%0,%1,%2,%3};" \
                 : "+f"((d)[0]), "+f"((d)[1]), "+f"((d)[2]), "+f"((d)[3]) \
                 : "r"((a)[0]), "r"((a)[1]), "r"((a)[2]), "r"((a)[3]), \
                   "r"((b)[0]), "r"((b)[1]))

__device__ __forceinline__ void split2(float a, float b, __nv_bfloat162& h, __nv_bfloat162& l) {
    h = __floats2bfloat162_rn(a, b);
    l = __floats2bfloat162_rn(a - __low2float(h), b - __high2float(h));
}

// ------------------------------------------------------------------
// fused weight conversion (+ bias concat)
// ------------------------------------------------------------------
__global__ void conv_all(const float* __restrict__ Wq, const float* __restrict__ Wk,
                         const float* __restrict__ Wv, const float* __restrict__ Wo,
                         const float* __restrict__ W1, const float* __restrict__ W2,
                         const float* __restrict__ bq, const float* __restrict__ bk) {
    long i4 = (long)blockIdx.x * 256 + threadIdx.x;
    if (i4 >= 786432) {
        int t = threadIdx.x;
        if (blockIdx.x == 3072) {
            g_bqk[t] = bq[t];
            g_bqk[t + 256] = bq[t + 256];
            g_bqk[t + 512] = bk[t];
            g_bqk[t + 768] = bk[t + 256];
        }
        return;
    }
    const float* src;
    __nv_bfloat16 *dh, *dl;
    long o;
    if (i4 < 65536)       { src = Wq; dh = g_Wqkh;          dl = g_Wqkl;          o = i4; }
    else if (i4 < 131072) { src = Wk; dh = g_Wqkh + 262144; dl = g_Wqkl + 262144; o = i4 - 65536; }
    else if (i4 < 196608) { src = Wv; dh = g_Wvh;           dl = g_Wvl;           o = i4 - 131072; }
    else if (i4 < 262144) { src = Wo; dh = g_Woh;           dl = g_Wol;           o = i4 - 196608; }
    else if (i4 < 524288) { src = W1; dh = g_W1h;           dl = g_W1l;           o = i4 - 262144; }
    else                  { src = W2; dh = g_W2h;           dl = g_W2l;           o = i4 - 524288; }
    long e = o * 4;
    float4 v = *(const float4*)&src[e];
    __nv_bfloat162 h0, l0, h1, l1;
    split2(v.x, v.y, h0, l0);
    split2(v.z, v.w, h1, l1);
    *(__nv_bfloat162*)&dh[e] = h0; *(__nv_bfloat162*)&dh[e + 2] = h1;
    *(__nv_bfloat162*)&dl[e] = l0; *(__nv_bfloat162*)&dl[e + 2] = l1;
}

// ------------------------------------------------------------------
// prep / out transpose
// ------------------------------------------------------------------
__global__ void prep_xr(const float* __restrict__ x, const float* __restrict__ pe,
                        float* __restrict__ XR,
                        __nv_bfloat16* __restrict__ XRh, __nv_bfloat16* __restrict__ XRl,
                        __nv_bfloat16* __restrict__ XPEh, __nv_bfloat16* __restrict__ XPEl) {
    __shared__ float tile[32][33];
    int bt = blockIdx.z;
    int b = bt >> 5, t = bt & 31;
    int d0 = blockIdx.x * 32, n0 = blockIdx.y * 32;
    size_t bbase = (size_t)b * (Dn * Tn * Nn);
#pragma unroll
    for (int i = 0; i < 4; i++) {
        int d = d0 + threadIdx.y + i * 8;
        tile[threadIdx.y + i * 8][threadIdx.x] =
            x[bbase + (size_t)d * (Tn * Nn) + t * Nn + n0 + threadIdx.x];
    }
    __syncthreads();
    int d = d0 + threadIdx.x;
#pragma unroll
    for (int i = 0; i < 4; i++) {
        int n = n0 + threadIdx.y + i * 8;
        float v = tile[threadIdx.x][threadIdx.y + i * 8];
        size_t idx = bbase + (size_t)n * (Tn * Dn) + t * Dn + d;
        XR[idx] = v;
        __nv_bfloat16 h = __float2bfloat16(v);
        XRh[idx] = h;
        XRl[idx] = __float2bfloat16(v - __bfloat162float(h));
        float vp = v + pe[n * Dn + d];
        __nv_bfloat16 hp = __float2bfloat16(vp);
        XPEh[idx] = hp;
        XPEl[idx] = __float2bfloat16(vp - __bfloat162float(hp));
    }
}

__global__ void out_tr(const float* __restrict__ FF, float* __restrict__ out) {
    __shared__ float tile[32][33];
    int bt = blockIdx.z;
    int b = bt >> 5, t = bt & 31;
    int d0 = blockIdx.x * 32, n0 = blockIdx.y * 32;
    size_t bbase = (size_t)b * (Dn * Tn * Nn);
#pragma unroll
    for (int i = 0; i < 4; i++) {
        int n = n0 + threadIdx.y + i * 8;
        tile[threadIdx.y + i * 8][threadIdx.x] =
            FF[bbase + (size_t)n * (Tn * Dn) + t * Dn + d0 + threadIdx.x];
    }
    __syncthreads();
#pragma unroll
    for (int i = 0; i < 4; i++) {
        int d = d0 + threadIdx.y + i * 8;
        out[bbase + (size_t)d * (Tn * Nn) + t * Nn + n0 + threadIdx.x] =
            tile[threadIdx.x][threadIdx.y + i * 8];
    }
}

// ------------------------------------------------------------------
// mma.sync split-bf16 GEMM: 256x128 CTA tile, warp 64x64 (8 warps 4x2),
// BK=64, 2-stage cp.async, ONE barrier per K-iter, pitch-144 SMEM.
// Next-stage cp.async issue is SPREAD across the 4 kc sub-blocks,
// placed in the ldmatrix->mma latency window.
// ------------------------------------------------------------------
#define PITCHB 144
#define OFF_AH 0
#define OFF_AL (256 * PITCHB)                 // 36864
#define OFF_BH (2 * 256 * PITCHB)             // 73728
#define OFF_BL (OFF_BH + 128 * PITCHB)        // 92160
#define STAGEB (OFF_BL + 128 * PITCHB)        // 110592
#define GEMM_DSMEM (2 * STAGEB)               // 221184

template <int ROWS>
__device__ __forceinline__ void load_tile(uint32_t sdst, const __nv_bfloat16* __restrict__ g,
                                          size_t row0, int K, int k0, int tid) {
    const char* gbase = (const char*)(g + row0 * (size_t)K + k0);
    size_t rs = (size_t)K * 2;
#pragma unroll
    for (int ch = tid; ch < ROWS * 8; ch += 256) {
        int r = ch >> 3, c = ch & 7;
        cpasync16(sdst + r * PITCHB + c * 16, gbase + (size_t)r * rs + c * 16);
    }
}

template <bool BIAS_, bool RELU_, bool RESID_, bool OUTF_, bool OUTHL_>
__global__ void __launch_bounds__(256, 1)
gemm_mma(const __nv_bfloat16* __restrict__ Ah, const __nv_bfloat16* __restrict__ Al,
         const __nv_bfloat16* __restrict__ Wh, const __nv_bfloat16* __restrict__ Wl,
         const float* __restrict__ bias, const float* __restrict__ Rsd,
         float* __restrict__ Cf, __nv_bfloat16* __restrict__ Ch, __nv_bfloat16* __restrict__ Cl,
         int Ncols, int K) {
    extern __shared__ char smraw[];
    const uint32_t sb = smem_u32(smraw);
    const int tid = threadIdx.x;
    const int wid = tid >> 5;
    const int lane = tid & 31;
    const size_t rowBase = (size_t)blockIdx.y * 256;
    const int colBase = blockIdx.x * 128;
    const int wm = (wid >> 1) * 64;
    const int wn = (wid & 1) * 64;

    float acc[4][8][4];
#pragma unroll
    for (int mt = 0; mt < 4; mt++)
#pragma unroll
        for (int nt = 0; nt < 8; nt++)
#pragma unroll
            for (int q = 0; q < 4; q++) acc[mt][nt][q] = 0.f;

    const int KIT = K >> 6;

    // prologue: stage 0
    load_tile<256>(sb + OFF_AH, Ah, rowBase, K, 0, tid);
    load_tile<256>(sb + OFF_AL, Al, rowBase, K, 0, tid);
    load_tile<128>(sb + OFF_BH, Wh, (size_t)colBase, K, 0, tid);
    load_tile<128>(sb + OFF_BL, Wl, (size_t)colBase, K, 0, tid);
    CP_COMMIT();

    const int arow = lane & 15;
    const int ainc = lane >> 4;
    const int brow = (lane & 7) + ((lane >> 4) << 3);
    const int binc = (lane >> 3) & 1;

    for (int it = 0; it < KIT; ++it) {
        CP_WAIT0();
        __syncthreads();
        const bool pf = (it + 1 < KIT);
        const uint32_t stn = sb + ((it + 1) & 1) * STAGEB;
        const int k0n = (it + 1) * 64;
        const uint32_t stb = sb + (it & 1) * STAGEB;
#pragma unroll
        for (int kc = 0; kc < 4; kc++) {
            uint32_t ah[4][4], alr[4][4], bh[8][2], bl[8][2];
#pragma unroll
            for (int mt = 0; mt < 4; mt++) {
                uint32_t ad = stb + OFF_AH + (wm + mt * 16 + arow) * PITCHB + kc * 32 + ainc * 16;
                LDSM4(ah[mt][0], ah[mt][1], ah[mt][2], ah[mt][3], ad);
                LDSM4(alr[mt][0], alr[mt][1], alr[mt][2], alr[mt][3], ad + (OFF_AL - OFF_AH));
            }
#pragma unroll
            for (int bt = 0; bt < 4; bt++) {
                uint32_t bd = stb + OFF_BH + (wn + bt * 16 + brow) * PITCHB + kc * 32 + binc * 16;
                uint32_t r0, r1, r2, r3;
                LDSM4(r0, r1, r2, r3, bd);
                bh[2 * bt][0] = r0; bh[2 * bt][1] = r1;
                bh[2 * bt + 1][0] = r2; bh[2 * bt + 1][1] = r3;
                LDSM4(r0, r1, r2, r3, bd + (OFF_BL - OFF_BH));
                bl[2 * bt][0] = r0; bl[2 * bt][1] = r1;
                bl[2 * bt + 1][0] = r2; bl[2 * bt + 1][1] = r3;
            }
            // prefetch quarter: issued in the ldmatrix->mma latency window
            if (pf) {
                if (kc == 0)      load_tile<256>(stn + OFF_AH, Ah, rowBase, K, k0n, tid);
                else if (kc == 1) load_tile<256>(stn + OFF_AL, Al, rowBase, K, k0n, tid);
                else if (kc == 2) load_tile<128>(stn + OFF_BH, Wh, (size_t)colBase, K, k0n, tid);
                else              load_tile<128>(stn + OFF_BL, Wl, (size_t)colBase, K, k0n, tid);
            }
#pragma unroll
            for (int mt = 0; mt < 4; mt++) {
#pragma unroll
                for (int nt = 0; nt < 8; nt++) {
                    MMA_BF16(acc[mt][nt], ah[mt], bh[nt]);
                    MMA_BF16(acc[mt][nt], ah[mt], bl[nt]);
                    MMA_BF16(acc[mt][nt], alr[mt], bh[nt]);
                }
            }
        }
        CP_COMMIT();
    }

    // epilogue
#pragma unroll
    for (int mt = 0; mt < 4; mt++) {
#pragma unroll
        for (int nt = 0; nt < 8; nt++) {
            const int col = colBase + wn + nt * 8 + (lane & 3) * 2;
#pragma unroll
            for (int half = 0; half < 2; half++) {
                const size_t row = rowBase + wm + mt * 16 + (lane >> 2) + half * 8;
                float vx = acc[mt][nt][half * 2 + 0];
                float vy = acc[mt][nt][half * 2 + 1];
                if (BIAS_) {
                    float2 bv = *(const float2*)&bias[col];
                    vx += bv.x; vy += bv.y;
                }
                if (RELU_) { vx = fmaxf(vx, 0.f); vy = fmaxf(vy, 0.f); }
                if (RESID_) {
                    float2 rv = *(const float2*)&Rsd[row * Ncols + col];
                    vx += rv.x; vy += rv.y;
                }
                if (OUTF_) {
                    *(float2*)&Cf[row * Ncols + col] = make_float2(vx, vy);
                }
                if (OUTHL_) {
                    __nv_bfloat162 Hv, Lv;
                    split2(vx, vy, Hv, Lv);
                    *(__nv_bfloat162*)&Ch[row * Ncols + col] = Hv;
                    *(__nv_bfloat162*)&Cl[row * Ncols + col] = Lv;
                }
            }
        }
    }
}

// ------------------------------------------------------------------
// Attention (fp32 FFMA); Q,K from fused QK buffer (row stride 1024)
// ------------------------------------------------------------------
__global__ void __launch_bounds__(256)
attn_kernel(const float* __restrict__ QK, const float* __restrict__ Vm,
            const float* __restrict__ adj, const float* __restrict__ hw,
            __nv_bfloat16* __restrict__ ATTh, __nv_bfloat16* __restrict__ ATTl) {
    __shared__ float bufA[64][68];
    __shared__ float bufB[64][68];

    const int b = blockIdx.x >> 3;
    const int h = blockIdx.x & 7;
    const int tid = threadIdx.x;
    const int ty = tid >> 4;
    const int tx = tid & 15;
    const int dkl = tid & 63;
    const int nl0 = tid >> 6;

    const size_t base_q = ((size_t)b * 2048) * 1024 + h * DKn;
    const size_t base_k = base_q + 512;
    const size_t base_v = ((size_t)b * 2048) * Dn + h * DKn;

    float acc[4][4];
#pragma unroll
    for (int i = 0; i < 4; i++)
#pragma unroll
        for (int j = 0; j < 4; j++) acc[i][j] = 0.f;

    for (int t0 = 0; t0 < 32; t0++) {
        __syncthreads();
        for (int nn = nl0; nn < 64; nn += 4) {
            size_t off = (size_t)(nn * 32 + t0) * 1024 + dkl;
            bufA[dkl][nn] = QK[base_q + off];
            bufB[dkl][nn] = QK[base_k + off];
        }
        __syncthreads();
#pragma unroll 8
        for (int dk = 0; dk < 64; dk++) {
            float4 q = *(const float4*)&bufA[dk][ty * 4];
            float4 k = *(const float4*)&bufB[dk][tx * 4];
            acc[0][0] = fmaf(q.x, k.x, acc[0][0]); acc[0][1] = fmaf(q.x, k.y, acc[0][1]);
            acc[0][2] = fmaf(q.x, k.z, acc[0][2]); acc[0][3] = fmaf(q.x, k.w, acc[0][3]);
            acc[1][0] = fmaf(q.y, k.x, acc[1][0]); acc[1][1] = fmaf(q.y, k.y, acc[1][1]);
            acc[1][2] = fmaf(q.y, k.z, acc[1][2]); acc[1][3] = fmaf(q.y, k.w, acc[1][3]);
            acc[2][0] = fmaf(q.z, k.x, acc[2][0]); acc[2][1] = fmaf(q.z, k.y, acc[2][1]);
            acc[2][2] = fmaf(q.z, k.z, acc[2][2]); acc[2][3] = fmaf(q.z, k.w, acc[2][3]);
            acc[3][0] = fmaf(q.w, k.x, acc[3][0]); acc[3][1] = fmaf(q.w, k.y, acc[3][1]);
            acc[3][2] = fmaf(q.w, k.z, acc[3][2]); acc[3][3] = fmaf(q.w, k.w, acc[3][3]);
        }
    }

    __syncthreads();
#pragma unroll
    for (int i = 0; i < 4; i++)
#pragma unroll
        for (int j = 0; j < 4; j++)
            bufB[ty * 4 + i][tx * 4 + j] = acc[i][j] * SCALE_F;
    __syncthreads();

    {
        const int w = tid >> 5, lane = tid & 31;
        const float hwv = hw[h];
        for (int rr = 0; rr < 8; rr++) {
            int row = w * 8 + rr;
            float v0 = bufB[row][lane];
            float v1 = bufB[row][lane + 32];
            float mx = fmaxf(v0, v1);
#pragma unroll
            for (int o = 16; o; o >>= 1) mx = fmaxf(mx, __shfl_xor_sync(0xffffffffu, mx, o));
            float e0 = __expf(v0 - mx), e1 = __expf(v1 - mx);
            float s = e0 + e1;
#pragma unroll
            for (int o = 16; o; o >>= 1) s += __shfl_xor_sync(0xffffffffu, s, o);
            float inv = 1.f / s;
            size_t ab = (size_t)h * 4096 + row * 64;
            bufB[row][lane]      = e0 * inv * hwv + adj[ab + lane];
            bufB[row][lane + 32] = e1 * inv * hwv + adj[ab + 32 + lane];
        }
    }

    for (int t0 = 0; t0 < 32; t0++) {
        __syncthreads();
        for (int mm = nl0; mm < 64; mm += 4) {
            bufA[mm][dkl] = Vm[base_v + (size_t)(mm * 32 + t0) * Dn + dkl];
        }
        __syncthreads();
        float o2[4][4];
#pragma unroll
        for (int i = 0; i < 4; i++)
#pragma unroll
            for (int j = 0; j < 4; j++) o2[i][j] = 0.f;
#pragma unroll 8
        for (int m = 0; m < 64; m++) {
            float4 v = *(const float4*)&bufA[m][tx * 4];
            float s0 = bufB[ty * 4 + 0][m];
            float s1 = bufB[ty * 4 + 1][m];
            float s2 = bufB[ty * 4 + 2][m];
            float s3 = bufB[ty * 4 + 3][m];
            o2[0][0] = fmaf(s0, v.x, o2[0][0]); o2[0][1] = fmaf(s0, v.y, o2[0][1]);
            o2[0][2] = fmaf(s0, v.z, o2[0][2]); o2[0][3] = fmaf(s0, v.w, o2[0][3]);
            o2[1][0] = fmaf(s1, v.x, o2[1][0]); o2[1][1] = fmaf(s1, v.y, o2[1][1]);
            o2[1][2] = fmaf(s1, v.z, o2[1][2]); o2[1][3] = fmaf(s1, v.w, o2[1][3]);
            o2[2][0] = fmaf(s2, v.x, o2[2][0]); o2[2][1] = fmaf(s2, v.y, o2[2][1]);
            o2[2][2] = fmaf(s2, v.z, o2[2][2]); o2[2][3] = fmaf(s2, v.w, o2[2][3]);
            o2[3][0] = fmaf(s3, v.x, o2[3][0]); o2[3][1] = fmaf(s3, v.y, o2[3][1]);
            o2[3][2] = fmaf(s3, v.z, o2[3][2]); o2[3][3] = fmaf(s3, v.w, o2[3][3]);
        }
#pragma unroll
        for (int i = 0; i < 4; i++) {
            int n = ty * 4 + i;
            size_t off = base_v + (size_t)(n * 32 + t0) * Dn + tx * 4;
            __nv_bfloat162 h0, l0, h1, l1;
            split2(o2[i][0], o2[i][1], h0, l0);
            split2(o2[i][2], o2[i][3], h1, l1);
            *(__nv_bfloat162*)&ATTh[off] = h0; *(__nv_bfloat162*)&ATTh[off + 2] = h1;
            *(__nv_bfloat162*)&ATTl[off] = l0; *(__nv_bfloat162*)&ATTl[off + 2] = l1;
        }
    }
}

// ------------------------------------------------------------------
// LayerNorm
// ------------------------------------------------------------------
__global__ void ln_partial(const float* __restrict__ Y1, float2* __restrict__ part) {
    const int c = blockIdx.x, b = blockIdx.y;
    const float* p = Y1 + (size_t)b * 1048576 + (size_t)c * 32768;
    float s = 0.f, s2 = 0.f;
    for (int i = threadIdx.x; i < 32768; i += 256) {
        float v = p[i];
        s += v; s2 += v * v;
    }
    __shared__ float rs[256], rs2[256];
    rs[threadIdx.x] = s; rs2[threadIdx.x] = s2;
    __syncthreads();
    for (int o = 128; o; o >>= 1) {
        if (threadIdx.x < o) {
            rs[threadIdx.x] += rs[threadIdx.x + o];
            rs2[threadIdx.x] += rs2[threadIdx.x + o];
        }
        __syncthreads();
    }
    if (threadIdx.x == 0) part[b * 32 + c] = make_float2(rs[0], rs2[0]);
}

__global__ void ln_final(const float2* __restrict__ part, float2* __restrict__ stats) {
    int b = threadIdx.x;
    if (b < Bn) {
        float s = 0.f, s2 = 0.f;
        for (int c = 0; c < 32; c++) {
            float2 p = part[b * 32 + c];
            s += p.x; s2 += p.y;
        }
        const float invN = 1.0f / 1048576.0f;
        float mean = s * invN;
        float var = s2 * invN - mean * mean;
        stats[b] = make_float2(mean, rsqrtf(var + LN_EPS));
    }
}

__global__ void ln_apply(const float* __restrict__ Y1, const float2* __restrict__ stats,
                         const float* __restrict__ g1, const float* __restrict__ be1,
                         float* __restrict__ X1,
                         __nv_bfloat16* __restrict__ X1h, __nv_bfloat16* __restrict__ X1l) {
    size_t e = ((size_t)blockIdx.x * blockDim.x + threadIdx.x) * 4;
    float2 st = stats[e >> 20];
    size_t gi = e & 1048575;
    float4 y = *(const float4*)&Y1[e];
    float4 g = *(const float4*)&g1[gi];
    float4 be = *(const float4*)&be1[gi];
    float4 o;
    o.x = (y.x - st.x) * st.y * g.x + be.x;
    o.y = (y.y - st.x) * st.y * g.y + be.y;
    o.z = (y.z - st.x) * st.y * g.z + be.z;
    o.w = (y.w - st.x) * st.y * g.w + be.w;
    *(float4*)&X1[e] = o;
    __nv_bfloat162 h0, l0, h1, l1;
    split2(o.x, o.y, h0, l0);
    split2(o.z, o.w, h1, l1);
    *(__nv_bfloat162*)&X1h[e] = h0; *(__nv_bfloat162*)&X1h[e + 2] = h1;
    *(__nv_bfloat162*)&X1l[e] = l0; *(__nv_bfloat162*)&X1l[e + 2] = l1;
}

// ------------------------------------------------------------------
// launch
// ------------------------------------------------------------------
extern "C" void kernel_launch(void* const* d_in, const int* in_sizes, int n_in,
                              void* d_out, int out_size) {
    const float* x   = (const float*)d_in[0];
    const float* Wq  = (const float*)d_in[1];
    const float* bq  = (const float*)d_in[2];
    const float* Wk  = (const float*)d_in[3];
    const float* bk  = (const float*)d_in[4];
    const float* Wv  = (const float*)d_in[5];
    const float* bv  = (const float*)d_in[6];
    const float* Wo  = (const float*)d_in[7];
    const float* bo  = (const float*)d_in[8];
    const float* W1  = (const float*)d_in[9];
    const float* b1  = (const float*)d_in[10];
    const float* W2  = (const float*)d_in[11];
    const float* b2  = (const float*)d_in[12];
    const float* g1  = (const float*)d_in[13];
    const float* be1 = (const float*)d_in[14];
    const float* adj = (const float*)d_in[15];
    const float* hw  = (const float*)d_in[16];
    const float* pe  = (const float*)d_in[17];
    float* out = (float*)d_out;

#define GETP(sym, ty, name) ty* name; { void* _p; cudaGetSymbolAddress(&_p, sym); name = (ty*)_p; }
    GETP(g_XR, float, XR) GETP(g_QK, float, QK) GETP(g_Vm, float, Vm)
    GETP(g_Y1, float, Y1) GETP(g_X1, float, X1) GETP(g_FF, float, FFo)
    GETP(g_XRh, __nv_bfloat16, XRh) GETP(g_XRl, __nv_bfloat16, XRl)
    GETP(g_XPEh, __nv_bfloat16, XPEh) GETP(g_XPEl, __nv_bfloat16, XPEl)
    GETP(g_ATTh, __nv_bfloat16, ATTh) GETP(g_ATTl, __nv_bfloat16, ATTl)
    GETP(g_X1h, __nv_bfloat16, X1h) GETP(g_X1l, __nv_bfloat16, X1l)
    GETP(g_Hh, __nv_bfloat16, Hh) GETP(g_Hl, __nv_bfloat16, Hl)
    GETP(g_Wqkh, __nv_bfloat16, Wqkh) GETP(g_Wqkl, __nv_bfloat16, Wqkl)
    GETP(g_Wvh, __nv_bfloat16, Wvh) GETP(g_Wvl, __nv_bfloat16, Wvl)
    GETP(g_Woh, __nv_bfloat16, Woh) GETP(g_Wol, __nv_bfloat16, Wol)
    GETP(g_W1h, __nv_bfloat16, W1h) GETP(g_W1l, __nv_bfloat16, W1l)
    GETP(g_W2h, __nv_bfloat16, W2h) GETP(g_W2l, __nv_bfloat16, W2l)
    GETP(g_bqk, float, bqk)
    GETP(g_part, float2, part) GETP(g_stats, float2, stats)
#undef GETP

    cudaFuncSetAttribute(gemm_mma<true, false, false, true, false>,
                         cudaFuncAttributeMaxDynamicSharedMemorySize, GEMM_DSMEM);
    cudaFuncSetAttribute(gemm_mma<true, false, true, true, false>,
                         cudaFuncAttributeMaxDynamicSharedMemorySize, GEMM_DSMEM);
    cudaFuncSetAttribute(gemm_mma<true, true, false, false, true>,
                         cudaFuncAttributeMaxDynamicSharedMemorySize, GEMM_DSMEM);

    // 0. fused weight conversion + bias concat
    conv_all<<<3073, 256>>>(Wq, Wk, Wv, Wo, W1, W2, bq, bk);

    // 1. transpose + split
    dim3 trGrid(16, 2, Bn * Tn);
    dim3 trBlk(32, 8);
    prep_xr<<<trGrid, trBlk>>>(x, pe, XR, XRh, XRl, XPEh, XPEl);

    // 2. fused Q+K projection (N=1024), V projection
    dim3 gQK(1024 / 128, MTOT / 256);  // (8, 256)
    gemm_mma<true, false, false, true, false><<<gQK, 256, GEMM_DSMEM>>>(
        XPEh, XPEl, Wqkh, Wqkl, bqk, nullptr, QK, nullptr, nullptr, 1024, Dn);
    dim3 gD(Dn / 128, MTOT / 256);     // (4, 256)
    gemm_mma<true, false, false, true, false><<<gD, 256, GEMM_DSMEM>>>(
        XRh, XRl, Wvh, Wvl, bv, nullptr, Vm, nullptr, nullptr, Dn, Dn);

    // 3. attention
    attn_kernel<<<Bn * Hn, 256>>>(QK, Vm, adj, hw, ATTh, ATTl);

    // 4. output projection + residual (launch index 5 -> profiled)
    gemm_mma<true, false, true, true, false><<<gD, 256, GEMM_DSMEM>>>(
        ATTh, ATTl, Woh, Wol, bo, XR, Y1, nullptr, nullptr, Dn, Dn);

    // 5. layernorm
    ln_partial<<<dim3(32, Bn), 256>>>(Y1, part);
    ln_final<<<1, 32>>>(part, stats);
    ln_apply<<<(MTOT * (size_t)Dn / 4) / 256, 256>>>(Y1, stats, g1, be1, X1, X1h, X1l);

    // 6. FFN
    dim3 gF1(FFn / 128, MTOT / 256);   // (16, 256)
    gemm_mma<true, true, false, false, true><<<gF1, 256, GEMM_DSMEM>>>(
        X1h, X1l, W1h, W1l, b1, nullptr, nullptr, Hh, Hl, FFn, Dn);
    gemm_mma<true, false, true, true, false><<<gD, 256, GEMM_DSMEM>>>(
        Hh, Hl, W2h, W2l, b2, X1, FFo, nullptr, nullptr, Dn, FFn);

    // 7. output transpose
    out_tr<<<trGrid, trBlk>>>(FFo, out);
}

// round 10
// speedup vs baseline: 4.1291x; 1.4524x over previous
#include <cuda_runtime.h>
#include <cuda_bf16.h>
#include <cuda_fp16.h>
#include <cstdint>
#include <math.h>

#define Bn 32
#define Dn 512
#define Tn 32
#define Nn 64
#define Hn 8
#define DKn 64
#define FFn 2048
#define MTOT (Bn * Nn * Tn)
#define SCALE_F 0.022097086912079608f
#define LN_EPS 1e-5f

// ------------------------------------------------------------------
// Scratch. NOTE: g_W1h/g_W2h/g_X1h/g_Hh hold FP16 bits (bf16-typed).
// ------------------------------------------------------------------
__device__ float g_XR[(size_t)MTOT * Dn];
__device__ float g_QK[(size_t)MTOT * 1024];
__device__ float g_Vm[(size_t)MTOT * Dn];
__device__ float g_Y1[(size_t)MTOT * Dn];
__device__ float g_X1[(size_t)MTOT * Dn];
__device__ float g_FF[(size_t)MTOT * Dn];
__device__ __nv_bfloat16 g_XRh[(size_t)MTOT * Dn], g_XRl[(size_t)MTOT * Dn];
__device__ __nv_bfloat16 g_XPEh[(size_t)MTOT * Dn], g_XPEl[(size_t)MTOT * Dn];
__device__ __nv_bfloat16 g_ATTh[(size_t)MTOT * Dn], g_ATTl[(size_t)MTOT * Dn];
__device__ __nv_bfloat16 g_X1h[(size_t)MTOT * Dn];      // fp16 bits
__device__ __nv_bfloat16 g_Hh[(size_t)MTOT * FFn];      // fp16 bits
__device__ __nv_bfloat16 g_Wqkh[1024 * Dn], g_Wqkl[1024 * Dn];
__device__ __nv_bfloat16 g_Wvh[Dn * Dn], g_Wvl[Dn * Dn];
__device__ __nv_bfloat16 g_Woh[Dn * Dn], g_Wol[Dn * Dn];
__device__ __nv_bfloat16 g_W1h[FFn * Dn];               // fp16 bits
__device__ __nv_bfloat16 g_W2h[Dn * FFn];               // fp16 bits
__device__ float g_bqk[1024];
__device__ float2 g_part[Bn * 32];
__device__ float2 g_stats[Bn];

// ------------------------------------------------------------------
__device__ __forceinline__ uint32_t smem_u32(const void* p) {
    uint32_t a;
    asm("{ .reg .u64 t; cvta.to.shared.u64 t, %1; cvt.u32.u64 %0, t; }" : "=r"(a) : "l"(p));
    return a;
}
__device__ __forceinline__ void cpasync16(uint32_t dst, const void* src) {
    asm volatile("cp.async.cg.shared.global [%0], [%1], 16;" :: "r"(dst), "l"(src));
}
#define CP_COMMIT() asm volatile("cp.async.commit_group;" ::: "memory")
#define CP_WAIT0() asm volatile("cp.async.wait_group 0;" ::: "memory")

#define LDSM4(r0, r1, r2, r3, addr) \
    asm volatile("ldmatrix.sync.aligned.m8n8.x4.shared.b16 {%0,%1,%2,%3}, [%4];" \
                 : "=r"(r0), "=r"(r1), "=r"(r2), "=r"(r3) : "r"(addr))

#define MMA_BF16(d, a, b) \
    asm volatile("mma.sync.aligned.m16n8k16.row.col.f32.bf16.bf16.f32 " \
                 "{%0,%1,%2,%3}, {%4,%5,%6,%7}, {%8,%9}, {%0,%1,%2,%3};" \
                 : "+f"((d)[0]), "+f"((d)[1]), "+f"((d)[2]), "+f"((d)[3]) \
                 : "r"((a)[0]), "r"((a)[1]), "r"((a)[2]), "r"((a)[3]), \
                   "r"((b)[0]), "r"((b)[1]))

#define MMA_F16(d, a, b) \
    asm volatile("mma.sync.aligned.m16n8k16.row.col.f32.f16.f16.f32 " \
                 "{%0,%1,%2,%3}, {%4,%5,%6,%7}, {%8,%9}, {%0,%1,%2,%3};" \
                 : "+f"((d)[0]), "+f"((d)[1]), "+f"((d)[2]), "+f"((d)[3]) \
                 : "r"((a)[0]), "r"((a)[1]), "r"((a)[2]), "r"((a)[3]), \
                   "r"((b)[0]), "r"((b)[1]))

__device__ __forceinline__ void split2(float a, float b, __nv_bfloat162& h, __nv_bfloat162& l) {
    h = __floats2bfloat162_rn(a, b);
    l = __floats2bfloat162_rn(a - __low2float(h), b - __high2float(h));
}
__device__ __forceinline__ uint32_t h2bits(float a, float b) {
    __half2 h = __floats2half2_rn(a, b);
    return *(uint32_t*)&h;
}

// ------------------------------------------------------------------
// weight conversion: Wq/Wk/Wv/Wo -> bf16 hi/lo; W1/W2 -> fp16 single
// ------------------------------------------------------------------
__global__ void conv_all(const float* __restrict__ Wq, const float* __restrict__ Wk,
                         const float* __restrict__ Wv, const float* __restrict__ Wo,
                         const float* __restrict__ W1, const float* __restrict__ W2,
                         const float* __restrict__ bq, const float* __restrict__ bk) {
    long i4 = (long)blockIdx.x * 256 + threadIdx.x;
    if (i4 >= 786432) {
        int t = threadIdx.x;
        if (blockIdx.x == 3072) {
            g_bqk[t] = bq[t];
            g_bqk[t + 256] = bq[t + 256];
            g_bqk[t + 512] = bk[t];
            g_bqk[t + 768] = bk[t + 256];
        }
        return;
    }
    if (i4 < 262144) {  // attention weights: bf16 hi/lo
        const float* src;
        __nv_bfloat16 *dh, *dl;
        long o;
        if (i4 < 65536)       { src = Wq; dh = g_Wqkh;          dl = g_Wqkl;          o = i4; }
        else if (i4 < 131072) { src = Wk; dh = g_Wqkh + 262144; dl = g_Wqkl + 262144; o = i4 - 65536; }
        else if (i4 < 196608) { src = Wv; dh = g_Wvh;           dl = g_Wvl;           o = i4 - 131072; }
        else                  { src = Wo; dh = g_Woh;           dl = g_Wol;           o = i4 - 196608; }
        long e = o * 4;
        float4 v = *(const float4*)&src[e];
        __nv_bfloat162 h0, l0, h1, l1;
        split2(v.x, v.y, h0, l0);
        split2(v.z, v.w, h1, l1);
        *(__nv_bfloat162*)&dh[e] = h0; *(__nv_bfloat162*)&dh[e + 2] = h1;
        *(__nv_bfloat162*)&dl[e] = l0; *(__nv_bfloat162*)&dl[e + 2] = l1;
    } else {            // FFN weights: fp16 single
        const float* src;
        __nv_bfloat16* dh;
        long o;
        if (i4 < 524288) { src = W1; dh = g_W1h; o = i4 - 262144; }
        else             { src = W2; dh = g_W2h; o = i4 - 524288; }
        long e = o * 4;
        float4 v = *(const float4*)&src[e];
        *(uint2*)&dh[e] = make_uint2(h2bits(v.x, v.y), h2bits(v.z, v.w));
    }
}

// ------------------------------------------------------------------
__global__ void prep_xr(const float* __restrict__ x, const float* __restrict__ pe,
                        float* __restrict__ XR,
                        __nv_bfloat16* __restrict__ XRh, __nv_bfloat16* __restrict__ XRl,
                        __nv_bfloat16* __restrict__ XPEh, __nv_bfloat16* __restrict__ XPEl) {
    __shared__ float tile[32][33];
    int bt = blockIdx.z;
    int b = bt >> 5, t = bt & 31;
    int d0 = blockIdx.x * 32, n0 = blockIdx.y * 32;
    size_t bbase = (size_t)b * (Dn * Tn * Nn);
#pragma unroll
    for (int i = 0; i < 4; i++) {
        int d = d0 + threadIdx.y + i * 8;
        tile[threadIdx.y + i * 8][threadIdx.x] =
            x[bbase + (size_t)d * (Tn * Nn) + t * Nn + n0 + threadIdx.x];
    }
    __syncthreads();
    int d = d0 + threadIdx.x;
#pragma unroll
    for (int i = 0; i < 4; i++) {
        int n = n0 + threadIdx.y + i * 8;
        float v = tile[threadIdx.x][threadIdx.y + i * 8];
        size_t idx = bbase + (size_t)n * (Tn * Dn) + t * Dn + d;
        XR[idx] = v;
        __nv_bfloat16 h = __float2bfloat16(v);
        XRh[idx] = h;
        XRl[idx] = __float2bfloat16(v - __bfloat162float(h));
        float vp = v + pe[n * Dn + d];
        __nv_bfloat16 hp = __float2bfloat16(vp);
        XPEh[idx] = hp;
        XPEl[idx] = __float2bfloat16(vp - __bfloat162float(hp));
    }
}

__global__ void out_tr(const float* __restrict__ FF, float* __restrict__ out) {
    __shared__ float tile[32][33];
    int bt = blockIdx.z;
    int b = bt >> 5, t = bt & 31;
    int d0 = blockIdx.x * 32, n0 = blockIdx.y * 32;
    size_t bbase = (size_t)b * (Dn * Tn * Nn);
#pragma unroll
    for (int i = 0; i < 4; i++) {
        int n = n0 + threadIdx.y + i * 8;
        tile[threadIdx.y + i * 8][threadIdx.x] =
            FF[bbase + (size_t)n * (Tn * Dn) + t * Dn + d0 + threadIdx.x];
    }
    __syncthreads();
#pragma unroll
    for (int i = 0; i < 4; i++) {
        int d = d0 + threadIdx.y + i * 8;
        out[bbase + (size_t)d * (Tn * Nn) + t * Nn + n0 + threadIdx.x] =
            tile[threadIdx.x][threadIdx.y + i * 8];
    }
}

// ------------------------------------------------------------------
// GEMM: 256x128 tile, warp 64x64, BK=64, 2-stage, 1 barrier/iter,
// pitch-144 smem, spread prefetch.
// ONE_=false: 3-term split-bf16.  ONE_=true: 1-term fp16.
// OUTM_: 0=float, 1=bf16 hi/lo, 2=fp16 bits
// ------------------------------------------------------------------
#define PITCHB 144
template <bool BIAS_, bool RELU_, bool RESID_, int OUTM_, bool ONE_>
__global__ void __launch_bounds__(256, 1)
gemm_mma(const __nv_bfloat16* __restrict__ Ah, const __nv_bfloat16* __restrict__ Al,
         const __nv_bfloat16* __restrict__ Wh, const __nv_bfloat16* __restrict__ Wl,
         const float* __restrict__ bias, const float* __restrict__ Rsd,
         float* __restrict__ Cf, __nv_bfloat16* __restrict__ Ch, __nv_bfloat16* __restrict__ Cl,
         int Ncols, int K) {
    constexpr uint32_t oAH = 0;
    constexpr uint32_t oAL = 256 * PITCHB;
    constexpr uint32_t oBH = ONE_ ? (256 * PITCHB) : (2 * 256 * PITCHB);
    constexpr uint32_t oBL = (2 * 256 + 128) * PITCHB;
    constexpr uint32_t STG = ONE_ ? (384 * PITCHB) : (768 * PITCHB);

    extern __shared__ char smraw[];
    const uint32_t sb = smem_u32(smraw);
    const int tid = threadIdx.x;
    const int wid = tid >> 5;
    const int lane = tid & 31;
    const size_t rowBase = (size_t)blockIdx.y * 256;
    const int colBase = blockIdx.x * 128;
    const int wm = (wid >> 1) * 64;
    const int wn = (wid & 1) * 64;

    float acc[4][8][4];
#pragma unroll
    for (int mt = 0; mt < 4; mt++)
#pragma unroll
        for (int nt = 0; nt < 8; nt++)
#pragma unroll
            for (int q = 0; q < 4; q++) acc[mt][nt][q] = 0.f;

    const int KIT = K >> 6;

    auto load_tile = [&](uint32_t sdst, const __nv_bfloat16* g, size_t row0, int k0, int rows) {
        const char* gbase = (const char*)(g + row0 * (size_t)K + k0);
        size_t rs = (size_t)K * 2;
        for (int ch = tid; ch < rows * 8; ch += 256) {
            int r = ch >> 3, c = ch & 7;
            cpasync16(sdst + r * PITCHB + c * 16, gbase + (size_t)r * rs + c * 16);
        }
    };

    // prologue
    load_tile(sb + oAH, Ah, rowBase, 0, 256);
    if (!ONE_) load_tile(sb + oAL, Al, rowBase, 0, 256);
    load_tile(sb + oBH, Wh, (size_t)colBase, 0, 128);
    if (!ONE_) load_tile(sb + oBL, Wl, (size_t)colBase, 0, 128);
    CP_COMMIT();

    const int arow = lane & 15;
    const int ainc = lane >> 4;
    const int brow = (lane & 7) + ((lane >> 4) << 3);
    const int binc = (lane >> 3) & 1;

    for (int it = 0; it < KIT; ++it) {
        CP_WAIT0();
        __syncthreads();
        const bool pf = (it + 1 < KIT);
        const uint32_t stn = sb + ((it + 1) & 1) * STG;
        const int k0n = (it + 1) * 64;
        const uint32_t stb = sb + (it & 1) * STG;
#pragma unroll
        for (int kc = 0; kc < 4; kc++) {
            uint32_t ah[4][4], alr[4][4], bh[8][2], bl[8][2];
#pragma unroll
            for (int mt = 0; mt < 4; mt++) {
                uint32_t ad = stb + oAH + (wm + mt * 16 + arow) * PITCHB + kc * 32 + ainc * 16;
                LDSM4(ah[mt][0], ah[mt][1], ah[mt][2], ah[mt][3], ad);
                if (!ONE_) LDSM4(alr[mt][0], alr[mt][1], alr[mt][2], alr[mt][3], ad + (oAL - oAH));
            }
#pragma unroll
            for (int bt = 0; bt < 4; bt++) {
                uint32_t bd = stb + oBH + (wn + bt * 16 + brow) * PITCHB + kc * 32 + binc * 16;
                uint32_t r0, r1, r2, r3;
                LDSM4(r0, r1, r2, r3, bd);
                bh[2 * bt][0] = r0; bh[2 * bt][1] = r1;
                bh[2 * bt + 1][0] = r2; bh[2 * bt + 1][1] = r3;
                if (!ONE_) {
                    LDSM4(r0, r1, r2, r3, bd + (oBL - oBH));
                    bl[2 * bt][0] = r0; bl[2 * bt][1] = r1;
                    bl[2 * bt + 1][0] = r2; bl[2 * bt + 1][1] = r3;
                }
            }
            if (pf) {
                if (!ONE_) {
                    if (kc == 0)      load_tile(stn + oAH, Ah, rowBase, k0n, 256);
                    else if (kc == 1) load_tile(stn + oAL, Al, rowBase, k0n, 256);
                    else if (kc == 2) load_tile(stn + oBH, Wh, (size_t)colBase, k0n, 128);
                    else              load_tile(stn + oBL, Wl, (size_t)colBase, k0n, 128);
                } else {
                    if (kc == 0)      load_tile(stn + oAH, Ah, rowBase, k0n, 256);
                    else if (kc == 2) load_tile(stn + oBH, Wh, (size_t)colBase, k0n, 128);
                }
            }
#pragma unroll
            for (int mt = 0; mt < 4; mt++) {
#pragma unroll
                for (int nt = 0; nt < 8; nt++) {
                    if (ONE_) {
                        MMA_F16(acc[mt][nt], ah[mt], bh[nt]);
                    } else {
                        MMA_BF16(acc[mt][nt], ah[mt], bh[nt]);
                        MMA_BF16(acc[mt][nt], ah[mt], bl[nt]);
                        MMA_BF16(acc[mt][nt], alr[mt], bh[nt]);
                    }
                }
            }
        }
        CP_COMMIT();
    }

    // epilogue
#pragma unroll
    for (int mt = 0; mt < 4; mt++) {
#pragma unroll
        for (int nt = 0; nt < 8; nt++) {
            const int col = colBase + wn + nt * 8 + (lane & 3) * 2;
#pragma unroll
            for (int half = 0; half < 2; half++) {
                const size_t row = rowBase + wm + mt * 16 + (lane >> 2) + half * 8;
                float vx = acc[mt][nt][half * 2 + 0];
                float vy = acc[mt][nt][half * 2 + 1];
                if (BIAS_) {
                    float2 bv = *(const float2*)&bias[col];
                    vx += bv.x; vy += bv.y;
                }
                if (RELU_) { vx = fmaxf(vx, 0.f); vy = fmaxf(vy, 0.f); }
                if (RESID_) {
                    float2 rv = *(const float2*)&Rsd[row * Ncols + col];
                    vx += rv.x; vy += rv.y;
                }
                if (OUTM_ == 0) {
                    *(float2*)&Cf[row * Ncols + col] = make_float2(vx, vy);
                } else if (OUTM_ == 1) {
                    __nv_bfloat162 Hv, Lv;
                    split2(vx, vy, Hv, Lv);
                    *(__nv_bfloat162*)&Ch[row * Ncols + col] = Hv;
                    *(__nv_bfloat162*)&Cl[row * Ncols + col] = Lv;
                } else {
                    *(uint32_t*)&Ch[row * Ncols + col] = h2bits(vx, vy);
                }
            }
        }
    }
}
#define GEMM_DSMEM3 (768 * PITCHB * 2)   // 221184
#define GEMM_DSMEM1 (384 * PITCHB * 2)   // 110592

// ------------------------------------------------------------------
// Attention (fp32 FFMA)
// ------------------------------------------------------------------
__global__ void __launch_bounds__(256)
attn_kernel(const float* __restrict__ QK, const float* __restrict__ Vm,
            const float* __restrict__ adj, const float* __restrict__ hw,
            __nv_bfloat16* __restrict__ ATTh, __nv_bfloat16* __restrict__ ATTl) {
    __shared__ float bufA[64][68];
    __shared__ float bufB[64][68];

    const int b = blockIdx.x >> 3;
    const int h = blockIdx.x & 7;
    const int tid = threadIdx.x;
    const int ty = tid >> 4;
    const int tx = tid & 15;
    const int dkl = tid & 63;
    const int nl0 = tid >> 6;

    const size_t base_q = ((size_t)b * 2048) * 1024 + h * DKn;
    const size_t base_k = base_q + 512;
    const size_t base_v = ((size_t)b * 2048) * Dn + h * DKn;

    float acc[4][4];
#pragma unroll
    for (int i = 0; i < 4; i++)
#pragma unroll
        for (int j = 0; j < 4; j++) acc[i][j] = 0.f;

    for (int t0 = 0; t0 < 32; t0++) {
        __syncthreads();
        for (int nn = nl0; nn < 64; nn += 4) {
            size_t off = (size_t)(nn * 32 + t0) * 1024 + dkl;
            bufA[dkl][nn] = QK[base_q + off];
            bufB[dkl][nn] = QK[base_k + off];
        }
        __syncthreads();
#pragma unroll 8
        for (int dk = 0; dk < 64; dk++) {
            float4 q = *(const float4*)&bufA[dk][ty * 4];
            float4 k = *(const float4*)&bufB[dk][tx * 4];
            acc[0][0] = fmaf(q.x, k.x, acc[0][0]); acc[0][1] = fmaf(q.x, k.y, acc[0][1]);
            acc[0][2] = fmaf(q.x, k.z, acc[0][2]); acc[0][3] = fmaf(q.x, k.w, acc[0][3]);
            acc[1][0] = fmaf(q.y, k.x, acc[1][0]); acc[1][1] = fmaf(q.y, k.y, acc[1][1]);
            acc[1][2] = fmaf(q.y, k.z, acc[1][2]); acc[1][3] = fmaf(q.y, k.w, acc[1][3]);
            acc[2][0] = fmaf(q.z, k.x, acc[2][0]); acc[2][1] = fmaf(q.z, k.y, acc[2][1]);
            acc[2][2] = fmaf(q.z, k.z, acc[2][2]); acc[2][3] = fmaf(q.z, k.w, acc[2][3]);
            acc[3][0] = fmaf(q.w, k.x, acc[3][0]); acc[3][1] = fmaf(q.w, k.y, acc[3][1]);
            acc[3][2] = fmaf(q.w, k.z, acc[3][2]); acc[3][3] = fmaf(q.w, k.w, acc[3][3]);
        }
    }

    __syncthreads();
#pragma unroll
    for (int i = 0; i < 4; i++)
#pragma unroll
        for (int j = 0; j < 4; j++)
            bufB[ty * 4 + i][tx * 4 + j] = acc[i][j] * SCALE_F;
    __syncthreads();

    {
        const int w = tid >> 5, lane = tid & 31;
        const float hwv = hw[h];
        for (int rr = 0; rr < 8; rr++) {
            int row = w * 8 + rr;
            float v0 = bufB[row][lane];
            float v1 = bufB[row][lane + 32];
            float mx = fmaxf(v0, v1);
#pragma unroll
            for (int o = 16; o; o >>= 1) mx = fmaxf(mx, __shfl_xor_sync(0xffffffffu, mx, o));
            float e0 = __expf(v0 - mx), e1 = __expf(v1 - mx);
            float s = e0 + e1;
#pragma unroll
            for (int o = 16; o; o >>= 1) s += __shfl_xor_sync(0xffffffffu, s, o);
            float inv = 1.f / s;
            size_t ab = (size_t)h * 4096 + row * 64;
            bufB[row][lane]      = e0 * inv * hwv + adj[ab + lane];
            bufB[row][lane + 32] = e1 * inv * hwv + adj[ab + 32 + lane];
        }
    }

    for (int t0 = 0; t0 < 32; t0++) {
        __syncthreads();
        for (int mm = nl0; mm < 64; mm += 4) {
            bufA[mm][dkl] = Vm[base_v + (size_t)(mm * 32 + t0) * Dn + dkl];
        }
        __syncthreads();
        float o2[4][4];
#pragma unroll
        for (int i = 0; i < 4; i++)
#pragma unroll
            for (int j = 0; j < 4; j++) o2[i][j] = 0.f;
#pragma unroll 8
        for (int m = 0; m < 64; m++) {
            float4 v = *(const float4*)&bufA[m][tx * 4];
            float s0 = bufB[ty * 4 + 0][m];
            float s1 = bufB[ty * 4 + 1][m];
            float s2 = bufB[ty * 4 + 2][m];
            float s3 = bufB[ty * 4 + 3][m];
            o2[0][0] = fmaf(s0, v.x, o2[0][0]); o2[0][1] = fmaf(s0, v.y, o2[0][1]);
            o2[0][2] = fmaf(s0, v.z, o2[0][2]); o2[0][3] = fmaf(s0, v.w, o2[0][3]);
            o2[1][0] = fmaf(s1, v.x, o2[1][0]); o2[1][1] = fmaf(s1, v.y, o2[1][1]);
            o2[1][2] = fmaf(s1, v.z, o2[1][2]); o2[1][3] = fmaf(s1, v.w, o2[1][3]);
            o2[2][0] = fmaf(s2, v.x, o2[2][0]); o2[2][1] = fmaf(s2, v.y, o2[2][1]);
            o2[2][2] = fmaf(s2, v.z, o2[2][2]); o2[2][3] = fmaf(s2, v.w, o2[2][3]);
            o2[3][0] = fmaf(s3, v.x, o2[3][0]); o2[3][1] = fmaf(s3, v.y, o2[3][1]);
            o2[3][2] = fmaf(s3, v.z, o2[3][2]); o2[3][3] = fmaf(s3, v.w, o2[3][3]);
        }
#pragma unroll
        for (int i = 0; i < 4; i++) {
            int n = ty * 4 + i;
            size_t off = base_v + (size_t)(n * 32 + t0) * Dn + tx * 4;
            __nv_bfloat162 h0, l0, h1, l1;
            split2(o2[i][0], o2[i][1], h0, l0);
            split2(o2[i][2], o2[i][3], h1, l1);
            *(__nv_bfloat162*)&ATTh[off] = h0; *(__nv_bfloat162*)&ATTh[off + 2] = h1;
            *(__nv_bfloat162*)&ATTl[off] = l0; *(__nv_bfloat162*)&ATTl[off + 2] = l1;
        }
    }
}

// ------------------------------------------------------------------
// LayerNorm
// ------------------------------------------------------------------
__global__ void ln_partial(const float* __restrict__ Y1, float2* __restrict__ part) {
    const int c = blockIdx.x, b = blockIdx.y;
    const float* p = Y1 + (size_t)b * 1048576 + (size_t)c * 32768;
    float s = 0.f, s2 = 0.f;
    for (int i = threadIdx.x; i < 32768; i += 256) {
        float v = p[i];
        s += v; s2 += v * v;
    }
    __shared__ float rs[256], rs2[256];
    rs[threadIdx.x] = s; rs2[threadIdx.x] = s2;
    __syncthreads();
    for (int o = 128; o; o >>= 1) {
        if (threadIdx.x < o) {
            rs[threadIdx.x] += rs[threadIdx.x + o];
            rs2[threadIdx.x] += rs2[threadIdx.x + o];
        }
        __syncthreads();
    }
    if (threadIdx.x == 0) part[b * 32 + c] = make_float2(rs[0], rs2[0]);
}

__global__ void ln_final(const float2* __restrict__ part, float2* __restrict__ stats) {
    int b = threadIdx.x;
    if (b < Bn) {
        float s = 0.f, s2 = 0.f;
        for (int c = 0; c < 32; c++) {
            float2 p = part[b * 32 + c];
            s += p.x; s2 += p.y;
        }
        const float invN = 1.0f / 1048576.0f;
        float mean = s * invN;
        float var = s2 * invN - mean * mean;
        stats[b] = make_float2(mean, rsqrtf(var + LN_EPS));
    }
}

__global__ void ln_apply(const float* __restrict__ Y1, const float2* __restrict__ stats,
                         const float* __restrict__ g1, const float* __restrict__ be1,
                         float* __restrict__ X1, __nv_bfloat16* __restrict__ X1h) {
    size_t e = ((size_t)blockIdx.x * blockDim.x + threadIdx.x) * 4;
    float2 st = stats[e >> 20];
    size_t gi = e & 1048575;
    float4 y = *(const float4*)&Y1[e];
    float4 g = *(const float4*)&g1[gi];
    float4 be = *(const float4*)&be1[gi];
    float4 o;
    o.x = (y.x - st.x) * st.y * g.x + be.x;
    o.y = (y.y - st.x) * st.y * g.y + be.y;
    o.z = (y.z - st.x) * st.y * g.z + be.z;
    o.w = (y.w - st.x) * st.y * g.w + be.w;
    *(float4*)&X1[e] = o;
    *(uint2*)&X1h[e] = make_uint2(h2bits(o.x, o.y), h2bits(o.z, o.w));  // fp16 bits
}

// ------------------------------------------------------------------
extern "C" void kernel_launch(void* const* d_in, const int* in_sizes, int n_in,
                              void* d_out, int out_size) {
    const float* x   = (const float*)d_in[0];
    const float* Wq  = (const float*)d_in[1];
    const float* bq  = (const float*)d_in[2];
    const float* Wk  = (const float*)d_in[3];
    const float* bk  = (const float*)d_in[4];
    const float* Wv  = (const float*)d_in[5];
    const float* bv  = (const float*)d_in[6];
    const float* Wo  = (const float*)d_in[7];
    const float* bo  = (const float*)d_in[8];
    const float* W1  = (const float*)d_in[9];
    const float* b1  = (const float*)d_in[10];
    const float* W2  = (const float*)d_in[11];
    const float* b2  = (const float*)d_in[12];
    const float* g1  = (const float*)d_in[13];
    const float* be1 = (const float*)d_in[14];
    const float* adj = (const float*)d_in[15];
    const float* hw  = (const float*)d_in[16];
    const float* pe  = (const float*)d_in[17];
    float* out = (float*)d_out;

#define GETP(sym, ty, name) ty* name; { void* _p; cudaGetSymbolAddress(&_p, sym); name = (ty*)_p; }
    GETP(g_XR, float, XR) GETP(g_QK, float, QK) GETP(g_Vm, float, Vm)
    GETP(g_Y1, float, Y1) GETP(g_X1, float, X1) GETP(g_FF, float, FFo)
    GETP(g_XRh, __nv_bfloat16, XRh) GETP(g_XRl, __nv_bfloat16, XRl)
    GETP(g_XPEh, __nv_bfloat16, XPEh) GETP(g_XPEl, __nv_bfloat16, XPEl)
    GETP(g_ATTh, __nv_bfloat16, ATTh) GETP(g_ATTl, __nv_bfloat16, ATTl)
    GETP(g_X1h, __nv_bfloat16, X1h)
    GETP(g_Hh, __nv_bfloat16, Hh)
    GETP(g_Wqkh, __nv_bfloat16, Wqkh) GETP(g_Wqkl, __nv_bfloat16, Wqkl)
    GETP(g_Wvh, __nv_bfloat16, Wvh) GETP(g_Wvl, __nv_bfloat16, Wvl)
    GETP(g_Woh, __nv_bfloat16, Woh) GETP(g_Wol, __nv_bfloat16, Wol)
    GETP(g_W1h, __nv_bfloat16, W1h)
    GETP(g_W2h, __nv_bfloat16, W2h)
    GETP(g_bqk, float, bqk)
    GETP(g_part, float2, part) GETP(g_stats, float2, stats)
#undef GETP

    cudaFuncSetAttribute(gemm_mma<true, false, false, 0, false>,
                         cudaFuncAttributeMaxDynamicSharedMemorySize, GEMM_DSMEM3);
    cudaFuncSetAttribute(gemm_mma<true, false, true, 0, false>,
                         cudaFuncAttributeMaxDynamicSharedMemorySize, GEMM_DSMEM3);
    cudaFuncSetAttribute(gemm_mma<true, true, false, 2, true>,
                         cudaFuncAttributeMaxDynamicSharedMemorySize, GEMM_DSMEM1);
    cudaFuncSetAttribute(gemm_mma<true, false, true, 0, true>,
                         cudaFuncAttributeMaxDynamicSharedMemorySize, GEMM_DSMEM1);

    // 0. weight conversion
    conv_all<<<3073, 256>>>(Wq, Wk, Wv, Wo, W1, W2, bq, bk);

    // 1. transpose + split
    dim3 trGrid(16, 2, Bn * Tn);
    dim3 trBlk(32, 8);
    prep_xr<<<trGrid, trBlk>>>(x, pe, XR, XRh, XRl, XPEh, XPEl);

    // 2. fused Q+K projection, V projection (3-term bf16)
    dim3 gQK(1024 / 128, MTOT / 256);
    gemm_mma<true, false, false, 0, false><<<gQK, 256, GEMM_DSMEM3>>>(
        XPEh, XPEl, Wqkh, Wqkl, bqk, nullptr, QK, nullptr, nullptr, 1024, Dn);
    dim3 gD(Dn / 128, MTOT / 256);
    gemm_mma<true, false, false, 0, false><<<gD, 256, GEMM_DSMEM3>>>(
        XRh, XRl, Wvh, Wvl, bv, nullptr, Vm, nullptr, nullptr, Dn, Dn);

    // 3. attention
    attn_kernel<<<Bn * Hn, 256>>>(QK, Vm, adj, hw, ATTh, ATTl);

    // 4. output projection + residual (3-term bf16)
    gemm_mma<true, false, true, 0, false><<<gD, 256, GEMM_DSMEM3>>>(
        ATTh, ATTl, Woh, Wol, bo, XR, Y1, nullptr, nullptr, Dn, Dn);

    // 5. layernorm
    ln_partial<<<dim3(32, Bn), 256>>>(Y1, part);
    ln_final<<<1, 32>>>(part, stats);
    ln_apply<<<(MTOT * (size_t)Dn / 4) / 256, 256>>>(Y1, stats, g1, be1, X1, X1h);

    // 6. FFN (1-term fp16)
    dim3 gF1(FFn / 128, MTOT / 256);
    gemm_mma<true, true, false, 2, true><<<gF1, 256, GEMM_DSMEM1>>>(
        X1h, nullptr, W1h, nullptr, b1, nullptr, nullptr, Hh, nullptr, FFn, Dn);
    gemm_mma<true, false, true, 0, true><<<gD, 256, GEMM_DSMEM1>>>(
        Hh, nullptr, W2h, nullptr, b2, X1, FFo, nullptr, nullptr, Dn, FFn);

    // 7. output transpose
    out_tr<<<trGrid, trBlk>>>(FFo, out);
}

// round 11
// speedup vs baseline: 5.3657x; 1.2995x over previous
#include <cuda_runtime.h>
#include <cuda_bf16.h>
#include <cuda_fp16.h>
#include <cstdint>
#include <math.h>

#define Bn 32
#define Dn 512
#define Tn 32
#define Nn 64
#define Hn 8
#define DKn 64
#define FFn 2048
#define MTOT (Bn * Nn * Tn)
#define SCALE_F 0.022097086912079608f
#define LN_EPS 1e-5f

// ------------------------------------------------------------------
// Scratch. All bf16-typed half buffers hold FP16 bits.
// ------------------------------------------------------------------
__device__ float g_XR[(size_t)MTOT * Dn];
__device__ float g_QK[(size_t)MTOT * 1024];
__device__ float g_Vm[(size_t)MTOT * Dn];
__device__ float g_Y1[(size_t)MTOT * Dn];
__device__ float g_X1[(size_t)MTOT * Dn];
__device__ float g_FF[(size_t)MTOT * Dn];
__device__ __nv_bfloat16 g_XRh[(size_t)MTOT * Dn];      // fp16
__device__ __nv_bfloat16 g_XPEh[(size_t)MTOT * Dn];     // fp16
__device__ __nv_bfloat16 g_ATTh[(size_t)MTOT * Dn];     // fp16
__device__ __nv_bfloat16 g_X1h[(size_t)MTOT * Dn];      // fp16
__device__ __nv_bfloat16 g_Hh[(size_t)MTOT * FFn];      // fp16
__device__ __nv_bfloat16 g_Wqkh[1024 * Dn];             // fp16
__device__ __nv_bfloat16 g_Wvh[Dn * Dn];                // fp16
__device__ __nv_bfloat16 g_Woh[Dn * Dn];                // fp16
__device__ __nv_bfloat16 g_W1h[FFn * Dn];               // fp16
__device__ __nv_bfloat16 g_W2h[Dn * FFn];               // fp16
__device__ float g_bqk[1024];
__device__ float2 g_part[Bn * 32];
__device__ float2 g_stats[Bn];

// ------------------------------------------------------------------
__device__ __forceinline__ uint32_t smem_u32(const void* p) {
    uint32_t a;
    asm("{ .reg .u64 t; cvta.to.shared.u64 t, %1; cvt.u32.u64 %0, t; }" : "=r"(a) : "l"(p));
    return a;
}
__device__ __forceinline__ void cpasync16(uint32_t dst, const void* src) {
    asm volatile("cp.async.cg.shared.global [%0], [%1], 16;" :: "r"(dst), "l"(src));
}
#define CP_COMMIT() asm volatile("cp.async.commit_group;" ::: "memory")
#define CP_WAIT0() asm volatile("cp.async.wait_group 0;" ::: "memory")

#define LDSM4(r0, r1, r2, r3, addr) \
    asm volatile("ldmatrix.sync.aligned.m8n8.x4.shared.b16 {%0,%1,%2,%3}, [%4];" \
                 : "=r"(r0), "=r"(r1), "=r"(r2), "=r"(r3) : "r"(addr))

#define MMA_F16(d, a, b) \
    asm volatile("mma.sync.aligned.m16n8k16.row.col.f32.f16.f16.f32 " \
                 "{%0,%1,%2,%3}, {%4,%5,%6,%7}, {%8,%9}, {%0,%1,%2,%3};" \
                 : "+f"((d)[0]), "+f"((d)[1]), "+f"((d)[2]), "+f"((d)[3]) \
                 : "r"((a)[0]), "r"((a)[1]), "r"((a)[2]), "r"((a)[3]), \
                   "r"((b)[0]), "r"((b)[1]))

__device__ __forceinline__ uint32_t h2bits(float a, float b) {
    __half2 h = __floats2half2_rn(a, b);
    return *(uint32_t*)&h;
}

// ------------------------------------------------------------------
// weight conversion: ALL weights -> fp16 single; bias concat for QK
// ------------------------------------------------------------------
__global__ void conv_all(const float* __restrict__ Wq, const float* __restrict__ Wk,
                         const float* __restrict__ Wv, const float* __restrict__ Wo,
                         const float* __restrict__ W1, const float* __restrict__ W2,
                         const float* __restrict__ bq, const float* __restrict__ bk) {
    long i4 = (long)blockIdx.x * 256 + threadIdx.x;
    if (i4 >= 786432) {
        int t = threadIdx.x;
        if (blockIdx.x == 3072) {
            g_bqk[t] = bq[t];
            g_bqk[t + 256] = bq[t + 256];
            g_bqk[t + 512] = bk[t];
            g_bqk[t + 768] = bk[t + 256];
        }
        return;
    }
    const float* src;
    __nv_bfloat16* dh;
    long o;
    if (i4 < 65536)       { src = Wq; dh = g_Wqkh;          o = i4; }
    else if (i4 < 131072) { src = Wk; dh = g_Wqkh + 262144; o = i4 - 65536; }
    else if (i4 < 196608) { src = Wv; dh = g_Wvh;           o = i4 - 131072; }
    else if (i4 < 262144) { src = Wo; dh = g_Woh;           o = i4 - 196608; }
    else if (i4 < 524288) { src = W1; dh = g_W1h;           o = i4 - 262144; }
    else                  { src = W2; dh = g_W2h;           o = i4 - 524288; }
    long e = o * 4;
    float4 v = *(const float4*)&src[e];
    *(uint2*)&dh[e] = make_uint2(h2bits(v.x, v.y), h2bits(v.z, v.w));
}

// ------------------------------------------------------------------
__global__ void prep_xr(const float* __restrict__ x, const float* __restrict__ pe,
                        float* __restrict__ XR,
                        __nv_bfloat16* __restrict__ XRh, __nv_bfloat16* __restrict__ XPEh) {
    __shared__ float tile[32][33];
    int bt = blockIdx.z;
    int b = bt >> 5, t = bt & 31;
    int d0 = blockIdx.x * 32, n0 = blockIdx.y * 32;
    size_t bbase = (size_t)b * (Dn * Tn * Nn);
#pragma unroll
    for (int i = 0; i < 4; i++) {
        int d = d0 + threadIdx.y + i * 8;
        tile[threadIdx.y + i * 8][threadIdx.x] =
            x[bbase + (size_t)d * (Tn * Nn) + t * Nn + n0 + threadIdx.x];
    }
    __syncthreads();
    int d = d0 + threadIdx.x;
#pragma unroll
    for (int i = 0; i < 4; i++) {
        int n = n0 + threadIdx.y + i * 8;
        float v = tile[threadIdx.x][threadIdx.y + i * 8];
        size_t idx = bbase + (size_t)n * (Tn * Dn) + t * Dn + d;
        XR[idx] = v;
        __half hv = __float2half_rn(v);
        *(uint16_t*)&XRh[idx] = *(uint16_t*)&hv;
        __half hp = __float2half_rn(v + pe[n * Dn + d]);
        *(uint16_t*)&XPEh[idx] = *(uint16_t*)&hp;
    }
}

__global__ void out_tr(const float* __restrict__ FF, float* __restrict__ out) {
    __shared__ float tile[32][33];
    int bt = blockIdx.z;
    int b = bt >> 5, t = bt & 31;
    int d0 = blockIdx.x * 32, n0 = blockIdx.y * 32;
    size_t bbase = (size_t)b * (Dn * Tn * Nn);
#pragma unroll
    for (int i = 0; i < 4; i++) {
        int n = n0 + threadIdx.y + i * 8;
        tile[threadIdx.y + i * 8][threadIdx.x] =
            FF[bbase + (size_t)n * (Tn * Dn) + t * Dn + d0 + threadIdx.x];
    }
    __syncthreads();
#pragma unroll
    for (int i = 0; i < 4; i++) {
        int d = d0 + threadIdx.y + i * 8;
        out[bbase + (size_t)d * (Tn * Nn) + t * Nn + n0 + threadIdx.x] =
            tile[threadIdx.x][threadIdx.y + i * 8];
    }
}

// ------------------------------------------------------------------
// fp16 1-term GEMM: 256x128 tile, warp 64x64, BK=64, 2-stage,
// 1 barrier/iter, pitch-144 smem, spread prefetch.
// OUTM_: 0=float, 2=fp16 bits
// ------------------------------------------------------------------
#define PITCHB 144
#define STG_B (384 * PITCHB)            // 55296
#define GEMM_DSMEM (2 * STG_B)          // 110592

template <bool BIAS_, bool RELU_, bool RESID_, int OUTM_>
__global__ void __launch_bounds__(256, 1)
gemm_mma(const __nv_bfloat16* __restrict__ Ah, const __nv_bfloat16* __restrict__ Wh,
         const float* __restrict__ bias, const float* __restrict__ Rsd,
         float* __restrict__ Cf, __nv_bfloat16* __restrict__ Ch,
         int Ncols, int K) {
    constexpr uint32_t oAH = 0;
    constexpr uint32_t oBH = 256 * PITCHB;

    extern __shared__ char smraw[];
    const uint32_t sb = smem_u32(smraw);
    const int tid = threadIdx.x;
    const int wid = tid >> 5;
    const int lane = tid & 31;
    const size_t rowBase = (size_t)blockIdx.y * 256;
    const int colBase = blockIdx.x * 128;
    const int wm = (wid >> 1) * 64;
    const int wn = (wid & 1) * 64;

    float acc[4][8][4];
#pragma unroll
    for (int mt = 0; mt < 4; mt++)
#pragma unroll
        for (int nt = 0; nt < 8; nt++)
#pragma unroll
            for (int q = 0; q < 4; q++) acc[mt][nt][q] = 0.f;

    const int KIT = K >> 6;

    auto load_tile = [&](uint32_t sdst, const __nv_bfloat16* g, size_t row0, int k0, int rows) {
        const char* gbase = (const char*)(g + row0 * (size_t)K + k0);
        size_t rs = (size_t)K * 2;
        for (int ch = tid; ch < rows * 8; ch += 256) {
            int r = ch >> 3, c = ch & 7;
            cpasync16(sdst + r * PITCHB + c * 16, gbase + (size_t)r * rs + c * 16);
        }
    };

    load_tile(sb + oAH, Ah, rowBase, 0, 256);
    load_tile(sb + oBH, Wh, (size_t)colBase, 0, 128);
    CP_COMMIT();

    const int arow = lane & 15;
    const int ainc = lane >> 4;
    const int brow = (lane & 7) + ((lane >> 4) << 3);
    const int binc = (lane >> 3) & 1;

    for (int it = 0; it < KIT; ++it) {
        CP_WAIT0();
        __syncthreads();
        const bool pf = (it + 1 < KIT);
        const uint32_t stn = sb + ((it + 1) & 1) * STG_B;
        const int k0n = (it + 1) * 64;
        const uint32_t stb = sb + (it & 1) * STG_B;
#pragma unroll
        for (int kc = 0; kc < 4; kc++) {
            uint32_t ah[4][4], bh[8][2];
#pragma unroll
            for (int mt = 0; mt < 4; mt++) {
                uint32_t ad = stb + oAH + (wm + mt * 16 + arow) * PITCHB + kc * 32 + ainc * 16;
                LDSM4(ah[mt][0], ah[mt][1], ah[mt][2], ah[mt][3], ad);
            }
#pragma unroll
            for (int bt = 0; bt < 4; bt++) {
                uint32_t bd = stb + oBH + (wn + bt * 16 + brow) * PITCHB + kc * 32 + binc * 16;
                uint32_t r0, r1, r2, r3;
                LDSM4(r0, r1, r2, r3, bd);
                bh[2 * bt][0] = r0; bh[2 * bt][1] = r1;
                bh[2 * bt + 1][0] = r2; bh[2 * bt + 1][1] = r3;
            }
            if (pf) {
                if (kc == 0)      load_tile(stn + oAH, Ah, rowBase, k0n, 256);
                else if (kc == 2) load_tile(stn + oBH, Wh, (size_t)colBase, k0n, 128);
            }
#pragma unroll
            for (int mt = 0; mt < 4; mt++) {
#pragma unroll
                for (int nt = 0; nt < 8; nt++) {
                    MMA_F16(acc[mt][nt], ah[mt], bh[nt]);
                }
            }
        }
        CP_COMMIT();
    }

    // epilogue
#pragma unroll
    for (int mt = 0; mt < 4; mt++) {
#pragma unroll
        for (int nt = 0; nt < 8; nt++) {
            const int col = colBase + wn + nt * 8 + (lane & 3) * 2;
#pragma unroll
            for (int half = 0; half < 2; half++) {
                const size_t row = rowBase + wm + mt * 16 + (lane >> 2) + half * 8;
                float vx = acc[mt][nt][half * 2 + 0];
                float vy = acc[mt][nt][half * 2 + 1];
                if (BIAS_) {
                    float2 bv = *(const float2*)&bias[col];
                    vx += bv.x; vy += bv.y;
                }
                if (RELU_) { vx = fmaxf(vx, 0.f); vy = fmaxf(vy, 0.f); }
                if (RESID_) {
                    float2 rv = *(const float2*)&Rsd[row * Ncols + col];
                    vx += rv.x; vy += rv.y;
                }
                if (OUTM_ == 0) {
                    *(float2*)&Cf[row * Ncols + col] = make_float2(vx, vy);
                } else {
                    *(uint32_t*)&Ch[row * Ncols + col] = h2bits(vx, vy);
                }
            }
        }
    }
}

// ------------------------------------------------------------------
// Attention (fp32 FFMA); outputs fp16 single
// ------------------------------------------------------------------
__global__ void __launch_bounds__(256)
attn_kernel(const float* __restrict__ QK, const float* __restrict__ Vm,
            const float* __restrict__ adj, const float* __restrict__ hw,
            __nv_bfloat16* __restrict__ ATTh) {
    __shared__ float bufA[64][68];
    __shared__ float bufB[64][68];

    const int b = blockIdx.x >> 3;
    const int h = blockIdx.x & 7;
    const int tid = threadIdx.x;
    const int ty = tid >> 4;
    const int tx = tid & 15;
    const int dkl = tid & 63;
    const int nl0 = tid >> 6;

    const size_t base_q = ((size_t)b * 2048) * 1024 + h * DKn;
    const size_t base_k = base_q + 512;
    const size_t base_v = ((size_t)b * 2048) * Dn + h * DKn;

    float acc[4][4];
#pragma unroll
    for (int i = 0; i < 4; i++)
#pragma unroll
        for (int j = 0; j < 4; j++) acc[i][j] = 0.f;

    for (int t0 = 0; t0 < 32; t0++) {
        __syncthreads();
        for (int nn = nl0; nn < 64; nn += 4) {
            size_t off = (size_t)(nn * 32 + t0) * 1024 + dkl;
            bufA[dkl][nn] = QK[base_q + off];
            bufB[dkl][nn] = QK[base_k + off];
        }
        __syncthreads();
#pragma unroll 8
        for (int dk = 0; dk < 64; dk++) {
            float4 q = *(const float4*)&bufA[dk][ty * 4];
            float4 k = *(const float4*)&bufB[dk][tx * 4];
            acc[0][0] = fmaf(q.x, k.x, acc[0][0]); acc[0][1] = fmaf(q.x, k.y, acc[0][1]);
            acc[0][2] = fmaf(q.x, k.z, acc[0][2]); acc[0][3] = fmaf(q.x, k.w, acc[0][3]);
            acc[1][0] = fmaf(q.y, k.x, acc[1][0]); acc[1][1] = fmaf(q.y, k.y, acc[1][1]);
            acc[1][2] = fmaf(q.y, k.z, acc[1][2]); acc[1][3] = fmaf(q.y, k.w, acc[1][3]);
            acc[2][0] = fmaf(q.z, k.x, acc[2][0]); acc[2][1] = fmaf(q.z, k.y, acc[2][1]);
            acc[2][2] = fmaf(q.z, k.z, acc[2][2]); acc[2][3] = fmaf(q.z, k.w, acc[2][3]);
            acc[3][0] = fmaf(q.w, k.x, acc[3][0]); acc[3][1] = fmaf(q.w, k.y, acc[3][1]);
            acc[3][2] = fmaf(q.w, k.z, acc[3][2]); acc[3][3] = fmaf(q.w, k.w, acc[3][3]);
        }
    }

    __syncthreads();
#pragma unroll
    for (int i = 0; i < 4; i++)
#pragma unroll
        for (int j = 0; j < 4; j++)
            bufB[ty * 4 + i][tx * 4 + j] = acc[i][j] * SCALE_F;
    __syncthreads();

    {
        const int w = tid >> 5, lane = tid & 31;
        const float hwv = hw[h];
        for (int rr = 0; rr < 8; rr++) {
            int row = w * 8 + rr;
            float v0 = bufB[row][lane];
            float v1 = bufB[row][lane + 32];
            float mx = fmaxf(v0, v1);
#pragma unroll
            for (int o = 16; o; o >>= 1) mx = fmaxf(mx, __shfl_xor_sync(0xffffffffu, mx, o));
            float e0 = __expf(v0 - mx), e1 = __expf(v1 - mx);
            float s = e0 + e1;
#pragma unroll
            for (int o = 16; o; o >>= 1) s += __shfl_xor_sync(0xffffffffu, s, o);
            float inv = 1.f / s;
            size_t ab = (size_t)h * 4096 + row * 64;
            bufB[row][lane]      = e0 * inv * hwv + adj[ab + lane];
            bufB[row][lane + 32] = e1 * inv * hwv + adj[ab + 32 + lane];
        }
    }

    for (int t0 = 0; t0 < 32; t0++) {
        __syncthreads();
        for (int mm = nl0; mm < 64; mm += 4) {
            bufA[mm][dkl] = Vm[base_v + (size_t)(mm * 32 + t0) * Dn + dkl];
        }
        __syncthreads();
        float o2[4][4];
#pragma unroll
        for (int i = 0; i < 4; i++)
#pragma unroll
            for (int j = 0; j < 4; j++) o2[i][j] = 0.f;
#pragma unroll 8
        for (int m = 0; m < 64; m++) {
            float4 v = *(const float4*)&bufA[m][tx * 4];
            float s0 = bufB[ty * 4 + 0][m];
            float s1 = bufB[ty * 4 + 1][m];
            float s2 = bufB[ty * 4 + 2][m];
            float s3 = bufB[ty * 4 + 3][m];
            o2[0][0] = fmaf(s0, v.x, o2[0][0]); o2[0][1] = fmaf(s0, v.y, o2[0][1]);
            o2[0][2] = fmaf(s0, v.z, o2[0][2]); o2[0][3] = fmaf(s0, v.w, o2[0][3]);
            o2[1][0] = fmaf(s1, v.x, o2[1][0]); o2[1][1] = fmaf(s1, v.y, o2[1][1]);
            o2[1][2] = fmaf(s1, v.z, o2[1][2]); o2[1][3] = fmaf(s1, v.w, o2[1][3]);
            o2[2][0] = fmaf(s2, v.x, o2[2][0]); o2[2][1] = fmaf(s2, v.y, o2[2][1]);
            o2[2][2] = fmaf(s2, v.z, o2[2][2]); o2[2][3] = fmaf(s2, v.w, o2[2][3]);
            o2[3][0] = fmaf(s3, v.x, o2[3][0]); o2[3][1] = fmaf(s3, v.y, o2[3][1]);
            o2[3][2] = fmaf(s3, v.z, o2[3][2]); o2[3][3] = fmaf(s3, v.w, o2[3][3]);
        }
#pragma unroll
        for (int i = 0; i < 4; i++) {
            int n = ty * 4 + i;
            size_t off = base_v + (size_t)(n * 32 + t0) * Dn + tx * 4;
            *(uint2*)&ATTh[off] = make_uint2(h2bits(o2[i][0], o2[i][1]),
                                             h2bits(o2[i][2], o2[i][3]));
        }
    }
}

// ------------------------------------------------------------------
// LayerNorm
// ------------------------------------------------------------------
__global__ void ln_partial(const float* __restrict__ Y1, float2* __restrict__ part) {
    const int c = blockIdx.x, b = blockIdx.y;
    const float* p = Y1 + (size_t)b * 1048576 + (size_t)c * 32768;
    float s = 0.f, s2 = 0.f;
    for (int i = threadIdx.x; i < 32768; i += 256) {
        float v = p[i];
        s += v; s2 += v * v;
    }
    __shared__ float rs[256], rs2[256];
    rs[threadIdx.x] = s; rs2[threadIdx.x] = s2;
    __syncthreads();
    for (int o = 128; o; o >>= 1) {
        if (threadIdx.x < o) {
            rs[threadIdx.x] += rs[threadIdx.x + o];
            rs2[threadIdx.x] += rs2[threadIdx.x + o];
        }
        __syncthreads();
    }
    if (threadIdx.x == 0) part[b * 32 + c] = make_float2(rs[0], rs2[0]);
}

__global__ void ln_final(const float2* __restrict__ part, float2* __restrict__ stats) {
    int b = threadIdx.x;
    if (b < Bn) {
        float s = 0.f, s2 = 0.f;
        for (int c = 0; c < 32; c++) {
            float2 p = part[b * 32 + c];
            s += p.x; s2 += p.y;
        }
        const float invN = 1.0f / 1048576.0f;
        float mean = s * invN;
        float var = s2 * invN - mean * mean;
        stats[b] = make_float2(mean, rsqrtf(var + LN_EPS));
    }
}

__global__ void ln_apply(const float* __restrict__ Y1, const float2* __restrict__ stats,
                         const float* __restrict__ g1, const float* __restrict__ be1,
                         float* __restrict__ X1, __nv_bfloat16* __restrict__ X1h) {
    size_t e = ((size_t)blockIdx.x * blockDim.x + threadIdx.x) * 4;
    float2 st = stats[e >> 20];
    size_t gi = e & 1048575;
    float4 y = *(const float4*)&Y1[e];
    float4 g = *(const float4*)&g1[gi];
    float4 be = *(const float4*)&be1[gi];
    float4 o;
    o.x = (y.x - st.x) * st.y * g.x + be.x;
    o.y = (y.y - st.x) * st.y * g.y + be.y;
    o.z = (y.z - st.x) * st.y * g.z + be.z;
    o.w = (y.w - st.x) * st.y * g.w + be.w;
    *(float4*)&X1[e] = o;
    *(uint2*)&X1h[e] = make_uint2(h2bits(o.x, o.y), h2bits(o.z, o.w));
}

// ------------------------------------------------------------------
extern "C" void kernel_launch(void* const* d_in, const int* in_sizes, int n_in,
                              void* d_out, int out_size) {
    const float* x   = (const float*)d_in[0];
    const float* Wq  = (const float*)d_in[1];
    const float* bq  = (const float*)d_in[2];
    const float* Wk  = (const float*)d_in[3];
    const float* bk  = (const float*)d_in[4];
    const float* Wv  = (const float*)d_in[5];
    const float* bv  = (const float*)d_in[6];
    const float* Wo  = (const float*)d_in[7];
    const float* bo  = (const float*)d_in[8];
    const float* W1  = (const float*)d_in[9];
    const float* b1  = (const float*)d_in[10];
    const float* W2  = (const float*)d_in[11];
    const float* b2  = (const float*)d_in[12];
    const float* g1  = (const float*)d_in[13];
    const float* be1 = (const float*)d_in[14];
    const float* adj = (const float*)d_in[15];
    const float* hw  = (const float*)d_in[16];
    const float* pe  = (const float*)d_in[17];
    float* out = (float*)d_out;

#define GETP(sym, ty, name) ty* name; { void* _p; cudaGetSymbolAddress(&_p, sym); name = (ty*)_p; }
    GETP(g_XR, float, XR) GETP(g_QK, float, QK) GETP(g_Vm, float, Vm)
    GETP(g_Y1, float, Y1) GETP(g_X1, float, X1) GETP(g_FF, float, FFo)
    GETP(g_XRh, __nv_bfloat16, XRh)
    GETP(g_XPEh, __nv_bfloat16, XPEh)
    GETP(g_ATTh, __nv_bfloat16, ATTh)
    GETP(g_X1h, __nv_bfloat16, X1h)
    GETP(g_Hh, __nv_bfloat16, Hh)
    GETP(g_Wqkh, __nv_bfloat16, Wqkh)
    GETP(g_Wvh, __nv_bfloat16, Wvh)
    GETP(g_Woh, __nv_bfloat16, Woh)
    GETP(g_W1h, __nv_bfloat16, W1h)
    GETP(g_W2h, __nv_bfloat16, W2h)
    GETP(g_bqk, float, bqk)
    GETP(g_part, float2, part) GETP(g_stats, float2, stats)
#undef GETP

    cudaFuncSetAttribute(gemm_mma<true, false, false, 0>,
                         cudaFuncAttributeMaxDynamicSharedMemorySize, GEMM_DSMEM);
    cudaFuncSetAttribute(gemm_mma<true, false, true, 0>,
                         cudaFuncAttributeMaxDynamicSharedMemorySize, GEMM_DSMEM);
    cudaFuncSetAttribute(gemm_mma<true, true, false, 2>,
                         cudaFuncAttributeMaxDynamicSharedMemorySize, GEMM_DSMEM);

    // 0. weight conversion
    conv_all<<<3073, 256>>>(Wq, Wk, Wv, Wo, W1, W2, bq, bk);

    // 1. transpose + fp16 conversion
    dim3 trGrid(16, 2, Bn * Tn);
    dim3 trBlk(32, 8);
    prep_xr<<<trGrid, trBlk>>>(x, pe, XR, XRh, XPEh);

    // 2. fused Q+K projection, V projection (fp16 1-term)
    dim3 gQK(1024 / 128, MTOT / 256);
    gemm_mma<true, false, false, 0><<<gQK, 256, GEMM_DSMEM>>>(
        XPEh, Wqkh, bqk, nullptr, QK, nullptr, 1024, Dn);
    dim3 gD(Dn / 128, MTOT / 256);
    gemm_mma<true, false, false, 0><<<gD, 256, GEMM_DSMEM>>>(
        XRh, Wvh, bv, nullptr, Vm, nullptr, Dn, Dn);

    // 3. attention
    attn_kernel<<<Bn * Hn, 256>>>(QK, Vm, adj, hw, ATTh);

    // 4. output projection + residual
    gemm_mma<true, false, true, 0><<<gD, 256, GEMM_DSMEM>>>(
        ATTh, Woh, bo, XR, Y1, nullptr, Dn, Dn);

    // 5. layernorm
    ln_partial<<<dim3(32, Bn), 256>>>(Y1, part);
    ln_final<<<1, 32>>>(part, stats);
    ln_apply<<<(MTOT * (size_t)Dn / 4) / 256, 256>>>(Y1, stats, g1, be1, X1, X1h);

    // 6. FFN
    dim3 gF1(FFn / 128, MTOT / 256);
    gemm_mma<true, true, false, 2><<<gF1, 256, GEMM_DSMEM>>>(
        X1h, W1h, b1, nullptr, nullptr, Hh, FFn, Dn);
    gemm_mma<true, false, true, 0><<<gD, 256, GEMM_DSMEM>>>(
        Hh, W2h, b2, X1, FFo, nullptr, Dn, FFn);

    // 7. output transpose
    out_tr<<<trGrid, trBlk>>>(FFo, out);
}

// round 12
// speedup vs baseline: 5.8341x; 1.0873x over previous
#include <cuda_runtime.h>
#include <cuda_bf16.h>
#include <cuda_fp16.h>
#include <cstdint>
#include <math.h>

#define Bn 32
#define Dn 512
#define Tn 32
#define Nn 64
#define Hn 8
#define DKn 64
#define FFn 2048
#define MTOT (Bn * Nn * Tn)
#define SCALE_F 0.022097086912079608f
#define LN_EPS 1e-5f

// ------------------------------------------------------------------
// Scratch. bf16-typed half buffers hold FP16 bits.
// ------------------------------------------------------------------
__device__ float g_XR[(size_t)MTOT * Dn];
__device__ float g_Y1[(size_t)MTOT * Dn];
__device__ float g_X1[(size_t)MTOT * Dn];
__device__ float g_FF[(size_t)MTOT * Dn];
__device__ __nv_bfloat16 g_QKh[(size_t)MTOT * 1024];    // fp16
__device__ __nv_bfloat16 g_Vmh[(size_t)MTOT * Dn];      // fp16
__device__ __nv_bfloat16 g_XRh[(size_t)MTOT * Dn];      // fp16
__device__ __nv_bfloat16 g_XPEh[(size_t)MTOT * Dn];     // fp16
__device__ __nv_bfloat16 g_ATTh[(size_t)MTOT * Dn];     // fp16
__device__ __nv_bfloat16 g_X1h[(size_t)MTOT * Dn];      // fp16
__device__ __nv_bfloat16 g_Hh[(size_t)MTOT * FFn];      // fp16
__device__ __nv_bfloat16 g_Wqkh[1024 * Dn];             // fp16
__device__ __nv_bfloat16 g_Wvh[Dn * Dn];                // fp16
__device__ __nv_bfloat16 g_Woh[Dn * Dn];                // fp16
__device__ __nv_bfloat16 g_W1h[FFn * Dn];               // fp16
__device__ __nv_bfloat16 g_W2h[Dn * FFn];               // fp16
__device__ float g_bqk[1024];
__device__ float2 g_part[Bn * 32];
__device__ float2 g_stats[Bn];

// ------------------------------------------------------------------
__device__ __forceinline__ uint32_t smem_u32(const void* p) {
    uint32_t a;
    asm("{ .reg .u64 t; cvta.to.shared.u64 t, %1; cvt.u32.u64 %0, t; }" : "=r"(a) : "l"(p));
    return a;
}
__device__ __forceinline__ void cpasync16(uint32_t dst, const void* src) {
    asm volatile("cp.async.cg.shared.global [%0], [%1], 16;" :: "r"(dst), "l"(src));
}
#define CP_COMMIT() asm volatile("cp.async.commit_group;" ::: "memory")
#define CP_WAIT0() asm volatile("cp.async.wait_group 0;" ::: "memory")

#define LDSM4(r0, r1, r2, r3, addr) \
    asm volatile("ldmatrix.sync.aligned.m8n8.x4.shared.b16 {%0,%1,%2,%3}, [%4];" \
                 : "=r"(r0), "=r"(r1), "=r"(r2), "=r"(r3) : "r"(addr))

#define MMA_F16(d, a, b) \
    asm volatile("mma.sync.aligned.m16n8k16.row.col.f32.f16.f16.f32 " \
                 "{%0,%1,%2,%3}, {%4,%5,%6,%7}, {%8,%9}, {%0,%1,%2,%3};" \
                 : "+f"((d)[0]), "+f"((d)[1]), "+f"((d)[2]), "+f"((d)[3]) \
                 : "r"((a)[0]), "r"((a)[1]), "r"((a)[2]), "r"((a)[3]), \
                   "r"((b)[0]), "r"((b)[1]))

__device__ __forceinline__ uint32_t h2bits(float a, float b) {
    __half2 h = __floats2half2_rn(a, b);
    return *(uint32_t*)&h;
}
__device__ __forceinline__ float h2f(const __nv_bfloat16* p) {
    return __half2float(*(const __half*)p);
}

// ------------------------------------------------------------------
// weight conversion -> fp16; bias concat
// ------------------------------------------------------------------
__global__ void conv_all(const float* __restrict__ Wq, const float* __restrict__ Wk,
                         const float* __restrict__ Wv, const float* __restrict__ Wo,
                         const float* __restrict__ W1, const float* __restrict__ W2,
                         const float* __restrict__ bq, const float* __restrict__ bk) {
    long i4 = (long)blockIdx.x * 256 + threadIdx.x;
    if (i4 >= 786432) {
        int t = threadIdx.x;
        if (blockIdx.x == 3072) {
            g_bqk[t] = bq[t];
            g_bqk[t + 256] = bq[t + 256];
            g_bqk[t + 512] = bk[t];
            g_bqk[t + 768] = bk[t + 256];
        }
        return;
    }
    const float* src;
    __nv_bfloat16* dh;
    long o;
    if (i4 < 65536)       { src = Wq; dh = g_Wqkh;          o = i4; }
    else if (i4 < 131072) { src = Wk; dh = g_Wqkh + 262144; o = i4 - 65536; }
    else if (i4 < 196608) { src = Wv; dh = g_Wvh;           o = i4 - 131072; }
    else if (i4 < 262144) { src = Wo; dh = g_Woh;           o = i4 - 196608; }
    else if (i4 < 524288) { src = W1; dh = g_W1h;           o = i4 - 262144; }
    else                  { src = W2; dh = g_W2h;           o = i4 - 524288; }
    long e = o * 4;
    float4 v = *(const float4*)&src[e];
    *(uint2*)&dh[e] = make_uint2(h2bits(v.x, v.y), h2bits(v.z, v.w));
}

// ------------------------------------------------------------------
__global__ void prep_xr(const float* __restrict__ x, const float* __restrict__ pe,
                        float* __restrict__ XR,
                        __nv_bfloat16* __restrict__ XRh, __nv_bfloat16* __restrict__ XPEh) {
    __shared__ float tile[32][33];
    int bt = blockIdx.z;
    int b = bt >> 5, t = bt & 31;
    int d0 = blockIdx.x * 32, n0 = blockIdx.y * 32;
    size_t bbase = (size_t)b * (Dn * Tn * Nn);
#pragma unroll
    for (int i = 0; i < 4; i++) {
        int d = d0 + threadIdx.y + i * 8;
        tile[threadIdx.y + i * 8][threadIdx.x] =
            x[bbase + (size_t)d * (Tn * Nn) + t * Nn + n0 + threadIdx.x];
    }
    __syncthreads();
    int d = d0 + threadIdx.x;
#pragma unroll
    for (int i = 0; i < 4; i++) {
        int n = n0 + threadIdx.y + i * 8;
        float v = tile[threadIdx.x][threadIdx.y + i * 8];
        size_t idx = bbase + (size_t)n * (Tn * Dn) + t * Dn + d;
        XR[idx] = v;
        __half hv = __float2half_rn(v);
        *(uint16_t*)&XRh[idx] = *(uint16_t*)&hv;
        __half hp = __float2half_rn(v + pe[n * Dn + d]);
        *(uint16_t*)&XPEh[idx] = *(uint16_t*)&hp;
    }
}

__global__ void out_tr(const float* __restrict__ FF, float* __restrict__ out) {
    __shared__ float tile[32][33];
    int bt = blockIdx.z;
    int b = bt >> 5, t = bt & 31;
    int d0 = blockIdx.x * 32, n0 = blockIdx.y * 32;
    size_t bbase = (size_t)b * (Dn * Tn * Nn);
#pragma unroll
    for (int i = 0; i < 4; i++) {
        int n = n0 + threadIdx.y + i * 8;
        tile[threadIdx.y + i * 8][threadIdx.x] =
            FF[bbase + (size_t)n * (Tn * Dn) + t * Dn + d0 + threadIdx.x];
    }
    __syncthreads();
#pragma unroll
    for (int i = 0; i < 4; i++) {
        int d = d0 + threadIdx.y + i * 8;
        out[bbase + (size_t)d * (Tn * Nn) + t * Nn + n0 + threadIdx.x] =
            tile[threadIdx.x][threadIdx.y + i * 8];
    }
}

// ------------------------------------------------------------------
// fp16 GEMM: 256x128 tile, warp 64x64, BK=128, 2-stage, 1 barrier/iter,
// pitch-272 smem ((r+c) mod 8 permutation), prefetch spread over 6 kc.
// OUTM_: 0=float, 2=fp16 bits
// ------------------------------------------------------------------
#define PITCHB 272
#define STG_B (384 * PITCHB)            // 104448
#define GEMM_DSMEM (2 * STG_B)          // 208896

template <bool BIAS_, bool RELU_, bool RESID_, int OUTM_>
__global__ void __launch_bounds__(256, 1)
gemm_mma(const __nv_bfloat16* __restrict__ Ah, const __nv_bfloat16* __restrict__ Wh,
         const float* __restrict__ bias, const float* __restrict__ Rsd,
         float* __restrict__ Cf, __nv_bfloat16* __restrict__ Ch,
         int Ncols, int K) {
    constexpr uint32_t oAH = 0;
    constexpr uint32_t oBH = 256 * PITCHB;

    extern __shared__ char smraw[];
    const uint32_t sb = smem_u32(smraw);
    const int tid = threadIdx.x;
    const int wid = tid >> 5;
    const int lane = tid & 31;
    const size_t rowBase = (size_t)blockIdx.y * 256;
    const int colBase = blockIdx.x * 128;
    const int wm = (wid >> 1) * 64;
    const int wn = (wid & 1) * 64;

    float acc[4][8][4];
#pragma unroll
    for (int mt = 0; mt < 4; mt++)
#pragma unroll
        for (int nt = 0; nt < 8; nt++)
#pragma unroll
            for (int q = 0; q < 4; q++) acc[mt][nt][q] = 0.f;

    const int KIT = K >> 7;

    // load 64 rows of a tile (16 chunks of 16B per row)
    auto load64 = [&](uint32_t sdst, const __nv_bfloat16* g, size_t row0, int k0, int r0) {
        const char* gbase = (const char*)(g + (row0 + r0) * (size_t)K + k0);
        size_t rs = (size_t)K * 2;
#pragma unroll
        for (int q = 0; q < 4; q++) {
            int ch = tid + q * 256;
            int r = ch >> 4, c = ch & 15;
            cpasync16(sdst + (r0 + r) * PITCHB + c * 16, gbase + (size_t)r * rs + c * 16);
        }
    };

    // prologue: stage 0 full
#pragma unroll
    for (int r0 = 0; r0 < 256; r0 += 64) load64(sb + oAH, Ah, rowBase, 0, r0);
    load64(sb + oBH, Wh, (size_t)colBase, 0, 0);
    load64(sb + oBH, Wh, (size_t)colBase, 0, 64);
    CP_COMMIT();

    const int arow = lane & 15;
    const int ainc = lane >> 4;
    const int brow = (lane & 7) + ((lane >> 4) << 3);
    const int binc = (lane >> 3) & 1;

    for (int it = 0; it < KIT; ++it) {
        CP_WAIT0();
        __syncthreads();
        const bool pf = (it + 1 < KIT);
        const uint32_t stn = sb + ((it + 1) & 1) * STG_B;
        const int k0n = (it + 1) * 128;
        const uint32_t stb = sb + (it & 1) * STG_B;
#pragma unroll
        for (int kc = 0; kc < 8; kc++) {
            uint32_t ah[4][4], bh[8][2];
#pragma unroll
            for (int mt = 0; mt < 4; mt++) {
                uint32_t ad = stb + oAH + (wm + mt * 16 + arow) * PITCHB + kc * 32 + ainc * 16;
                LDSM4(ah[mt][0], ah[mt][1], ah[mt][2], ah[mt][3], ad);
            }
#pragma unroll
            for (int bt = 0; bt < 4; bt++) {
                uint32_t bd = stb + oBH + (wn + bt * 16 + brow) * PITCHB + kc * 32 + binc * 16;
                uint32_t r0, r1, r2, r3;
                LDSM4(r0, r1, r2, r3, bd);
                bh[2 * bt][0] = r0; bh[2 * bt][1] = r1;
                bh[2 * bt + 1][0] = r2; bh[2 * bt + 1][1] = r3;
            }
            // prefetch slice in the ldmatrix->mma latency window
            if (pf) {
                if (kc < 4)       load64(stn + oAH, Ah, rowBase, k0n, kc * 64);
                else if (kc == 4) load64(stn + oBH, Wh, (size_t)colBase, k0n, 0);
                else if (kc == 5) load64(stn + oBH, Wh, (size_t)colBase, k0n, 64);
            }
#pragma unroll
            for (int mt = 0; mt < 4; mt++) {
#pragma unroll
                for (int nt = 0; nt < 8; nt++) {
                    MMA_F16(acc[mt][nt], ah[mt], bh[nt]);
                }
            }
        }
        CP_COMMIT();
    }

    // epilogue
#pragma unroll
    for (int mt = 0; mt < 4; mt++) {
#pragma unroll
        for (int nt = 0; nt < 8; nt++) {
            const int col = colBase + wn + nt * 8 + (lane & 3) * 2;
#pragma unroll
            for (int half = 0; half < 2; half++) {
                const size_t row = rowBase + wm + mt * 16 + (lane >> 2) + half * 8;
                float vx = acc[mt][nt][half * 2 + 0];
                float vy = acc[mt][nt][half * 2 + 1];
                if (BIAS_) {
                    float2 bv = *(const float2*)&bias[col];
                    vx += bv.x; vy += bv.y;
                }
                if (RELU_) { vx = fmaxf(vx, 0.f); vy = fmaxf(vy, 0.f); }
                if (RESID_) {
                    float2 rv = *(const float2*)&Rsd[row * Ncols + col];
                    vx += rv.x; vy += rv.y;
                }
                if (OUTM_ == 0) {
                    *(float2*)&Cf[row * Ncols + col] = make_float2(vx, vy);
                } else {
                    *(uint32_t*)&Ch[row * Ncols + col] = h2bits(vx, vy);
                }
            }
        }
    }
}

// ------------------------------------------------------------------
// Attention (fp32 FFMA); reads fp16 QK/V, writes fp16
// ------------------------------------------------------------------
__global__ void __launch_bounds__(256)
attn_kernel(const __nv_bfloat16* __restrict__ QKh, const __nv_bfloat16* __restrict__ Vmh,
            const float* __restrict__ adj, const float* __restrict__ hw,
            __nv_bfloat16* __restrict__ ATTh) {
    __shared__ float bufA[64][68];
    __shared__ float bufB[64][68];

    const int b = blockIdx.x >> 3;
    const int h = blockIdx.x & 7;
    const int tid = threadIdx.x;
    const int ty = tid >> 4;
    const int tx = tid & 15;
    const int dkl = tid & 63;
    const int nl0 = tid >> 6;

    const size_t base_q = ((size_t)b * 2048) * 1024 + h * DKn;
    const size_t base_k = base_q + 512;
    const size_t base_v = ((size_t)b * 2048) * Dn + h * DKn;

    float acc[4][4];
#pragma unroll
    for (int i = 0; i < 4; i++)
#pragma unroll
        for (int j = 0; j < 4; j++) acc[i][j] = 0.f;

    for (int t0 = 0; t0 < 32; t0++) {
        __syncthreads();
        for (int nn = nl0; nn < 64; nn += 4) {
            size_t off = (size_t)(nn * 32 + t0) * 1024 + dkl;
            bufA[dkl][nn] = h2f(&QKh[base_q + off]);
            bufB[dkl][nn] = h2f(&QKh[base_k + off]);
        }
        __syncthreads();
#pragma unroll 8
        for (int dk = 0; dk < 64; dk++) {
            float4 q = *(const float4*)&bufA[dk][ty * 4];
            float4 k = *(const float4*)&bufB[dk][tx * 4];
            acc[0][0] = fmaf(q.x, k.x, acc[0][0]); acc[0][1] = fmaf(q.x, k.y, acc[0][1]);
            acc[0][2] = fmaf(q.x, k.z, acc[0][2]); acc[0][3] = fmaf(q.x, k.w, acc[0][3]);
            acc[1][0] = fmaf(q.y, k.x, acc[1][0]); acc[1][1] = fmaf(q.y, k.y, acc[1][1]);
            acc[1][2] = fmaf(q.y, k.z, acc[1][2]); acc[1][3] = fmaf(q.y, k.w, acc[1][3]);
            acc[2][0] = fmaf(q.z, k.x, acc[2][0]); acc[2][1] = fmaf(q.z, k.y, acc[2][1]);
            acc[2][2] = fmaf(q.z, k.z, acc[2][2]); acc[2][3] = fmaf(q.z, k.w, acc[2][3]);
            acc[3][0] = fmaf(q.w, k.x, acc[3][0]); acc[3][1] = fmaf(q.w, k.y, acc[3][1]);
            acc[3][2] = fmaf(q.w, k.z, acc[3][2]); acc[3][3] = fmaf(q.w, k.w, acc[3][3]);
        }
    }

    __syncthreads();
#pragma unroll
    for (int i = 0; i < 4; i++)
#pragma unroll
        for (int j = 0; j < 4; j++)
            bufB[ty * 4 + i][tx * 4 + j] = acc[i][j] * SCALE_F;
    __syncthreads();

    {
        const int w = tid >> 5, lane = tid & 31;
        const float hwv = hw[h];
        for (int rr = 0; rr < 8; rr++) {
            int row = w * 8 + rr;
            float v0 = bufB[row][lane];
            float v1 = bufB[row][lane + 32];
            float mx = fmaxf(v0, v1);
#pragma unroll
            for (int o = 16; o; o >>= 1) mx = fmaxf(mx, __shfl_xor_sync(0xffffffffu, mx, o));
            float e0 = __expf(v0 - mx), e1 = __expf(v1 - mx);
            float s = e0 + e1;
#pragma unroll
            for (int o = 16; o; o >>= 1) s += __shfl_xor_sync(0xffffffffu, s, o);
            float inv = 1.f / s;
            size_t ab = (size_t)h * 4096 + row * 64;
            bufB[row][lane]      = e0 * inv * hwv + adj[ab + lane];
            bufB[row][lane + 32] = e1 * inv * hwv + adj[ab + 32 + lane];
        }
    }

    for (int t0 = 0; t0 < 32; t0++) {
        __syncthreads();
        for (int mm = nl0; mm < 64; mm += 4) {
            bufA[mm][dkl] = h2f(&Vmh[base_v + (size_t)(mm * 32 + t0) * Dn + dkl]);
        }
        __syncthreads();
        float o2[4][4];
#pragma unroll
        for (int i = 0; i < 4; i++)
#pragma unroll
            for (int j = 0; j < 4; j++) o2[i][j] = 0.f;
#pragma unroll 8
        for (int m = 0; m < 64; m++) {
            float4 v = *(const float4*)&bufA[m][tx * 4];
            float s0 = bufB[ty * 4 + 0][m];
            float s1 = bufB[ty * 4 + 1][m];
            float s2 = bufB[ty * 4 + 2][m];
            float s3 = bufB[ty * 4 + 3][m];
            o2[0][0] = fmaf(s0, v.x, o2[0][0]); o2[0][1] = fmaf(s0, v.y, o2[0][1]);
            o2[0][2] = fmaf(s0, v.z, o2[0][2]); o2[0][3] = fmaf(s0, v.w, o2[0][3]);
            o2[1][0] = fmaf(s1, v.x, o2[1][0]); o2[1][1] = fmaf(s1, v.y, o2[1][1]);
            o2[1][2] = fmaf(s1, v.z, o2[1][2]); o2[1][3] = fmaf(s1, v.w, o2[1][3]);
            o2[2][0] = fmaf(s2, v.x, o2[2][0]); o2[2][1] = fmaf(s2, v.y, o2[2][1]);
            o2[2][2] = fmaf(s2, v.z, o2[2][2]); o2[2][3] = fmaf(s2, v.w, o2[2][3]);
            o2[3][0] = fmaf(s3, v.x, o2[3][0]); o2[3][1] = fmaf(s3, v.y, o2[3][1]);
            o2[3][2] = fmaf(s3, v.z, o2[3][2]); o2[3][3] = fmaf(s3, v.w, o2[3][3]);
        }
#pragma unroll
        for (int i = 0; i < 4; i++) {
            int n = ty * 4 + i;
            size_t off = base_v + (size_t)(n * 32 + t0) * Dn + tx * 4;
            *(uint2*)&ATTh[off] = make_uint2(h2bits(o2[i][0], o2[i][1]),
                                             h2bits(o2[i][2], o2[i][3]));
        }
    }
}

// ------------------------------------------------------------------
// LayerNorm
// ------------------------------------------------------------------
__global__ void ln_partial(const float* __restrict__ Y1, float2* __restrict__ part) {
    const int c = blockIdx.x, b = blockIdx.y;
    const float* p = Y1 + (size_t)b * 1048576 + (size_t)c * 32768;
    float s = 0.f, s2 = 0.f;
    for (int i = threadIdx.x; i < 32768; i += 256) {
        float v = p[i];
        s += v; s2 += v * v;
    }
    __shared__ float rs[256], rs2[256];
    rs[threadIdx.x] = s; rs2[threadIdx.x] = s2;
    __syncthreads();
    for (int o = 128; o; o >>= 1) {
        if (threadIdx.x < o) {
            rs[threadIdx.x] += rs[threadIdx.x + o];
            rs2[threadIdx.x] += rs2[threadIdx.x + o];
        }
        __syncthreads();
    }
    if (threadIdx.x == 0) part[b * 32 + c] = make_float2(rs[0], rs2[0]);
}

__global__ void ln_final(const float2* __restrict__ part, float2* __restrict__ stats) {
    int b = threadIdx.x;
    if (b < Bn) {
        float s = 0.f, s2 = 0.f;
        for (int c = 0; c < 32; c++) {
            float2 p = part[b * 32 + c];
            s += p.x; s2 += p.y;
        }
        const float invN = 1.0f / 1048576.0f;
        float mean = s * invN;
        float var = s2 * invN - mean * mean;
        stats[b] = make_float2(mean, rsqrtf(var + LN_EPS));
    }
}

__global__ void ln_apply(const float* __restrict__ Y1, const float2* __restrict__ stats,
                         const float* __restrict__ g1, const float* __restrict__ be1,
                         float* __restrict__ X1, __nv_bfloat16* __restrict__ X1h) {
    size_t e = ((size_t)blockIdx.x * blockDim.x + threadIdx.x) * 4;
    float2 st = stats[e >> 20];
    size_t gi = e & 1048575;
    float4 y = *(const float4*)&Y1[e];
    float4 g = *(const float4*)&g1[gi];
    float4 be = *(const float4*)&be1[gi];
    float4 o;
    o.x = (y.x - st.x) * st.y * g.x + be.x;
    o.y = (y.y - st.x) * st.y * g.y + be.y;
    o.z = (y.z - st.x) * st.y * g.z + be.z;
    o.w = (y.w - st.x) * st.y * g.w + be.w;
    *(float4*)&X1[e] = o;
    *(uint2*)&X1h[e] = make_uint2(h2bits(o.x, o.y), h2bits(o.z, o.w));
}

// ------------------------------------------------------------------
extern "C" void kernel_launch(void* const* d_in, const int* in_sizes, int n_in,
                              void* d_out, int out_size) {
    const float* x   = (const float*)d_in[0];
    const float* Wq  = (const float*)d_in[1];
    const float* bq  = (const float*)d_in[2];
    const float* Wk  = (const float*)d_in[3];
    const float* bk  = (const float*)d_in[4];
    const float* Wv  = (const float*)d_in[5];
    const float* bv  = (const float*)d_in[6];
    const float* Wo  = (const float*)d_in[7];
    const float* bo  = (const float*)d_in[8];
    const float* W1  = (const float*)d_in[9];
    const float* b1  = (const float*)d_in[10];
    const float* W2  = (const float*)d_in[11];
    const float* b2  = (const float*)d_in[12];
    const float* g1  = (const float*)d_in[13];
    const float* be1 = (const float*)d_in[14];
    const float* adj = (const float*)d_in[15];
    const float* hw  = (const float*)d_in[16];
    const float* pe  = (const float*)d_in[17];
    float* out = (float*)d_out;

#define GETP(sym, ty, name) ty* name; { void* _p; cudaGetSymbolAddress(&_p, sym); name = (ty*)_p; }
    GETP(g_XR, float, XR) GETP(g_Y1, float, Y1) GETP(g_X1, float, X1) GETP(g_FF, float, FFo)
    GETP(g_QKh, __nv_bfloat16, QKh)
    GETP(g_Vmh, __nv_bfloat16, Vmh)
    GETP(g_XRh, __nv_bfloat16, XRh)
    GETP(g_XPEh, __nv_bfloat16, XPEh)
    GETP(g_ATTh, __nv_bfloat16, ATTh)
    GETP(g_X1h, __nv_bfloat16, X1h)
    GETP(g_Hh, __nv_bfloat16, Hh)
    GETP(g_Wqkh, __nv_bfloat16, Wqkh)
    GETP(g_Wvh, __nv_bfloat16, Wvh)
    GETP(g_Woh, __nv_bfloat16, Woh)
    GETP(g_W1h, __nv_bfloat16, W1h)
    GETP(g_W2h, __nv_bfloat16, W2h)
    GETP(g_bqk, float, bqk)
    GETP(g_part, float2, part) GETP(g_stats, float2, stats)
#undef GETP

    cudaFuncSetAttribute(gemm_mma<true, false, false, 2>,
                         cudaFuncAttributeMaxDynamicSharedMemorySize, GEMM_DSMEM);
    cudaFuncSetAttribute(gemm_mma<true, true, false, 2>,
                         cudaFuncAttributeMaxDynamicSharedMemorySize, GEMM_DSMEM);
    cudaFuncSetAttribute(gemm_mma<true, false, true, 0>,
                         cudaFuncAttributeMaxDynamicSharedMemorySize, GEMM_DSMEM);

    // 0. weight conversion
    conv_all<<<3073, 256>>>(Wq, Wk, Wv, Wo, W1, W2, bq, bk);

    // 1. transpose + fp16 conversion
    dim3 trGrid(16, 2, Bn * Tn);
    dim3 trBlk(32, 8);
    prep_xr<<<trGrid, trBlk>>>(x, pe, XR, XRh, XPEh);

    // 2. fused Q+K projection, V projection (fp16 out)
    dim3 gQK(1024 / 128, MTOT / 256);
    gemm_mma<true, false, false, 2><<<gQK, 256, GEMM_DSMEM>>>(
        XPEh, Wqkh, bqk, nullptr, nullptr, QKh, 1024, Dn);
    dim3 gD(Dn / 128, MTOT / 256);
    gemm_mma<true, false, false, 2><<<gD, 256, GEMM_DSMEM>>>(
        XRh, Wvh, bv, nullptr, nullptr, Vmh, Dn, Dn);

    // 3. attention
    attn_kernel<<<Bn * Hn, 256>>>(QKh, Vmh, adj, hw, ATTh);

    // 4. output projection + residual (profiled launch)
    gemm_mma<true, false, true, 0><<<gD, 256, GEMM_DSMEM>>>(
        ATTh, Woh, bo, XR, Y1, nullptr, Dn, Dn);

    // 5. layernorm
    ln_partial<<<dim3(32, Bn), 256>>>(Y1, part);
    ln_final<<<1, 32>>>(part, stats);
    ln_apply<<<(MTOT * (size_t)Dn / 4) / 256, 256>>>(Y1, stats, g1, be1, X1, X1h);

    // 6. FFN
    dim3 gF1(FFn / 128, MTOT / 256);
    gemm_mma<true, true, false, 2><<<gF1, 256, GEMM_DSMEM>>>(
        X1h, W1h, b1, nullptr, nullptr, Hh, FFn, Dn);
    gemm_mma<true, false, true, 0><<<gD, 256, GEMM_DSMEM>>>(
        Hh, W2h, b2, X1, FFo, nullptr, Dn, FFn);

    // 7. output transpose
    out_tr<<<trGrid, trBlk>>>(FFo, out);
}

// round 13
// speedup vs baseline: 6.9783x; 1.1961x over previous
#include <cuda_runtime.h>
#include <cuda_bf16.h>
#include <cuda_fp16.h>
#include <cstdint>
#include <math.h>

#define Bn 32
#define Dn 512
#define Tn 32
#define Nn 64
#define Hn 8
#define DKn 64
#define FFn 2048
#define MTOT (Bn * Nn * Tn)
#define SCALE_F 0.022097086912079608f
#define LN_EPS 1e-5f

// ------------------------------------------------------------------
// Scratch. bf16-typed half buffers hold FP16 bits.
// ------------------------------------------------------------------
__device__ float g_XR[(size_t)MTOT * Dn];
__device__ float g_Y1[(size_t)MTOT * Dn];
__device__ float g_X1[(size_t)MTOT * Dn];
__device__ float g_FF[(size_t)MTOT * Dn];
__device__ __nv_bfloat16 g_QKh[(size_t)MTOT * 1024];    // fp16
__device__ __nv_bfloat16 g_Vmh[(size_t)MTOT * Dn];      // fp16
__device__ __nv_bfloat16 g_XRh[(size_t)MTOT * Dn];      // fp16
__device__ __nv_bfloat16 g_XPEh[(size_t)MTOT * Dn];     // fp16
__device__ __nv_bfloat16 g_ATTh[(size_t)MTOT * Dn];     // fp16
__device__ __nv_bfloat16 g_X1h[(size_t)MTOT * Dn];      // fp16
__device__ __nv_bfloat16 g_Hh[(size_t)MTOT * FFn];      // fp16
__device__ __nv_bfloat16 g_Wqkh[1024 * Dn];             // fp16
__device__ __nv_bfloat16 g_Wvh[Dn * Dn];                // fp16
__device__ __nv_bfloat16 g_Woh[Dn * Dn];                // fp16
__device__ __nv_bfloat16 g_W1h[FFn * Dn];               // fp16
__device__ __nv_bfloat16 g_W2h[Dn * FFn];               // fp16
__device__ float g_bqk[1024];
__device__ float2 g_part[Bn * 32];
__device__ float2 g_stats[Bn];

// ------------------------------------------------------------------
__device__ __forceinline__ uint32_t smem_u32(const void* p) {
    uint32_t a;
    asm("{ .reg .u64 t; cvta.to.shared.u64 t, %1; cvt.u32.u64 %0, t; }" : "=r"(a) : "l"(p));
    return a;
}
__device__ __forceinline__ void cpasync16(uint32_t dst, const void* src) {
    asm volatile("cp.async.cg.shared.global [%0], [%1], 16;" :: "r"(dst), "l"(src));
}
#define CP_COMMIT() asm volatile("cp.async.commit_group;" ::: "memory")
#define CP_WAIT0() asm volatile("cp.async.wait_group 0;" ::: "memory")

#define LDSM4(r0, r1, r2, r3, addr) \
    asm volatile("ldmatrix.sync.aligned.m8n8.x4.shared.b16 {%0,%1,%2,%3}, [%4];" \
                 : "=r"(r0), "=r"(r1), "=r"(r2), "=r"(r3) : "r"(addr))

#define LDSM4T(r0, r1, r2, r3, addr) \
    asm volatile("ldmatrix.sync.aligned.m8n8.x4.trans.shared.b16 {%0,%1,%2,%3}, [%4];" \
                 : "=r"(r0), "=r"(r1), "=r"(r2), "=r"(r3) : "r"(addr))

#define MMA_F16(d, a, b) \
    asm volatile("mma.sync.aligned.m16n8k16.row.col.f32.f16.f16.f32 " \
                 "{%0,%1,%2,%3}, {%4,%5,%6,%7}, {%8,%9}, {%0,%1,%2,%3};" \
                 : "+f"((d)[0]), "+f"((d)[1]), "+f"((d)[2]), "+f"((d)[3]) \
                 : "r"((a)[0]), "r"((a)[1]), "r"((a)[2]), "r"((a)[3]), \
                   "r"((b)[0]), "r"((b)[1]))

__device__ __forceinline__ uint32_t h2bits(float a, float b) {
    __half2 h = __floats2half2_rn(a, b);
    return *(uint32_t*)&h;
}

// ------------------------------------------------------------------
// weight conversion -> fp16; bias concat
// ------------------------------------------------------------------
__global__ void conv_all(const float* __restrict__ Wq, const float* __restrict__ Wk,
                         const float* __restrict__ Wv, const float* __restrict__ Wo,
                         const float* __restrict__ W1, const float* __restrict__ W2,
                         const float* __restrict__ bq, const float* __restrict__ bk) {
    long i4 = (long)blockIdx.x * 256 + threadIdx.x;
    if (i4 >= 786432) {
        int t = threadIdx.x;
        if (blockIdx.x == 3072) {
            g_bqk[t] = bq[t];
            g_bqk[t + 256] = bq[t + 256];
            g_bqk[t + 512] = bk[t];
            g_bqk[t + 768] = bk[t + 256];
        }
        return;
    }
    const float* src;
    __nv_bfloat16* dh;
    long o;
    if (i4 < 65536)       { src = Wq; dh = g_Wqkh;          o = i4; }
    else if (i4 < 131072) { src = Wk; dh = g_Wqkh + 262144; o = i4 - 65536; }
    else if (i4 < 196608) { src = Wv; dh = g_Wvh;           o = i4 - 131072; }
    else if (i4 < 262144) { src = Wo; dh = g_Woh;           o = i4 - 196608; }
    else if (i4 < 524288) { src = W1; dh = g_W1h;           o = i4 - 262144; }
    else                  { src = W2; dh = g_W2h;           o = i4 - 524288; }
    long e = o * 4;
    float4 v = *(const float4*)&src[e];
    *(uint2*)&dh[e] = make_uint2(h2bits(v.x, v.y), h2bits(v.z, v.w));
}

// ------------------------------------------------------------------
__global__ void prep_xr(const float* __restrict__ x, const float* __restrict__ pe,
                        float* __restrict__ XR,
                        __nv_bfloat16* __restrict__ XRh, __nv_bfloat16* __restrict__ XPEh) {
    __shared__ float tile[32][33];
    int bt = blockIdx.z;
    int b = bt >> 5, t = bt & 31;
    int d0 = blockIdx.x * 32, n0 = blockIdx.y * 32;
    size_t bbase = (size_t)b * (Dn * Tn * Nn);
#pragma unroll
    for (int i = 0; i < 4; i++) {
        int d = d0 + threadIdx.y + i * 8;
        tile[threadIdx.y + i * 8][threadIdx.x] =
            x[bbase + (size_t)d * (Tn * Nn) + t * Nn + n0 + threadIdx.x];
    }
    __syncthreads();
    int d = d0 + threadIdx.x;
#pragma unroll
    for (int i = 0; i < 4; i++) {
        int n = n0 + threadIdx.y + i * 8;
        float v = tile[threadIdx.x][threadIdx.y + i * 8];
        size_t idx = bbase + (size_t)n * (Tn * Dn) + t * Dn + d;
        XR[idx] = v;
        __half hv = __float2half_rn(v);
        *(uint16_t*)&XRh[idx] = *(uint16_t*)&hv;
        __half hp = __float2half_rn(v + pe[n * Dn + d]);
        *(uint16_t*)&XPEh[idx] = *(uint16_t*)&hp;
    }
}

__global__ void out_tr(const float* __restrict__ FF, float* __restrict__ out) {
    __shared__ float tile[32][33];
    int bt = blockIdx.z;
    int b = bt >> 5, t = bt & 31;
    int d0 = blockIdx.x * 32, n0 = blockIdx.y * 32;
    size_t bbase = (size_t)b * (Dn * Tn * Nn);
#pragma unroll
    for (int i = 0; i < 4; i++) {
        int n = n0 + threadIdx.y + i * 8;
        tile[threadIdx.y + i * 8][threadIdx.x] =
            FF[bbase + (size_t)n * (Tn * Dn) + t * Dn + d0 + threadIdx.x];
    }
    __syncthreads();
#pragma unroll
    for (int i = 0; i < 4; i++) {
        int d = d0 + threadIdx.y + i * 8;
        out[bbase + (size_t)d * (Tn * Nn) + t * Nn + n0 + threadIdx.x] =
            tile[threadIdx.x][threadIdx.y + i * 8];
    }
}

// ------------------------------------------------------------------
// fp16 GEMM: 256x128 tile, warp 64x64, BK=128, 2-stage, 1 barrier/iter,
// pitch-272 smem, prefetch spread over 6 kc.  OUTM_: 0=float, 2=fp16
// ------------------------------------------------------------------
#define PITCHB 272
#define STG_B (384 * PITCHB)            // 104448
#define GEMM_DSMEM (2 * STG_B)          // 208896

template <bool BIAS_, bool RELU_, bool RESID_, int OUTM_>
__global__ void __launch_bounds__(256, 1)
gemm_mma(const __nv_bfloat16* __restrict__ Ah, const __nv_bfloat16* __restrict__ Wh,
         const float* __restrict__ bias, const float* __restrict__ Rsd,
         float* __restrict__ Cf, __nv_bfloat16* __restrict__ Ch,
         int Ncols, int K) {
    constexpr uint32_t oAH = 0;
    constexpr uint32_t oBH = 256 * PITCHB;

    extern __shared__ char smraw[];
    const uint32_t sb = smem_u32(smraw);
    const int tid = threadIdx.x;
    const int wid = tid >> 5;
    const int lane = tid & 31;
    const size_t rowBase = (size_t)blockIdx.y * 256;
    const int colBase = blockIdx.x * 128;
    const int wm = (wid >> 1) * 64;
    const int wn = (wid & 1) * 64;

    float acc[4][8][4];
#pragma unroll
    for (int mt = 0; mt < 4; mt++)
#pragma unroll
        for (int nt = 0; nt < 8; nt++)
#pragma unroll
            for (int q = 0; q < 4; q++) acc[mt][nt][q] = 0.f;

    const int KIT = K >> 7;

    auto load64 = [&](uint32_t sdst, const __nv_bfloat16* g, size_t row0, int k0, int r0) {
        const char* gbase = (const char*)(g + (row0 + r0) * (size_t)K + k0);
        size_t rs = (size_t)K * 2;
#pragma unroll
        for (int q = 0; q < 4; q++) {
            int ch = tid + q * 256;
            int r = ch >> 4, c = ch & 15;
            cpasync16(sdst + (r0 + r) * PITCHB + c * 16, gbase + (size_t)r * rs + c * 16);
        }
    };

#pragma unroll
    for (int r0 = 0; r0 < 256; r0 += 64) load64(sb + oAH, Ah, rowBase, 0, r0);
    load64(sb + oBH, Wh, (size_t)colBase, 0, 0);
    load64(sb + oBH, Wh, (size_t)colBase, 0, 64);
    CP_COMMIT();

    const int arow = lane & 15;
    const int ainc = lane >> 4;
    const int brow = (lane & 7) + ((lane >> 4) << 3);
    const int binc = (lane >> 3) & 1;

    for (int it = 0; it < KIT; ++it) {
        CP_WAIT0();
        __syncthreads();
        const bool pf = (it + 1 < KIT);
        const uint32_t stn = sb + ((it + 1) & 1) * STG_B;
        const int k0n = (it + 1) * 128;
        const uint32_t stb = sb + (it & 1) * STG_B;
#pragma unroll
        for (int kc = 0; kc < 8; kc++) {
            uint32_t ah[4][4], bh[8][2];
#pragma unroll
            for (int mt = 0; mt < 4; mt++) {
                uint32_t ad = stb + oAH + (wm + mt * 16 + arow) * PITCHB + kc * 32 + ainc * 16;
                LDSM4(ah[mt][0], ah[mt][1], ah[mt][2], ah[mt][3], ad);
            }
#pragma unroll
            for (int bt = 0; bt < 4; bt++) {
                uint32_t bd = stb + oBH + (wn + bt * 16 + brow) * PITCHB + kc * 32 + binc * 16;
                uint32_t r0, r1, r2, r3;
                LDSM4(r0, r1, r2, r3, bd);
                bh[2 * bt][0] = r0; bh[2 * bt][1] = r1;
                bh[2 * bt + 1][0] = r2; bh[2 * bt + 1][1] = r3;
            }
            if (pf) {
                if (kc < 4)       load64(stn + oAH, Ah, rowBase, k0n, kc * 64);
                else if (kc == 4) load64(stn + oBH, Wh, (size_t)colBase, k0n, 0);
                else if (kc == 5) load64(stn + oBH, Wh, (size_t)colBase, k0n, 64);
            }
#pragma unroll
            for (int mt = 0; mt < 4; mt++) {
#pragma unroll
                for (int nt = 0; nt < 8; nt++) {
                    MMA_F16(acc[mt][nt], ah[mt], bh[nt]);
                }
            }
        }
        CP_COMMIT();
    }

#pragma unroll
    for (int mt = 0; mt < 4; mt++) {
#pragma unroll
        for (int nt = 0; nt < 8; nt++) {
            const int col = colBase + wn + nt * 8 + (lane & 3) * 2;
#pragma unroll
            for (int half = 0; half < 2; half++) {
                const size_t row = rowBase + wm + mt * 16 + (lane >> 2) + half * 8;
                float vx = acc[mt][nt][half * 2 + 0];
                float vy = acc[mt][nt][half * 2 + 1];
                if (BIAS_) {
                    float2 bv = *(const float2*)&bias[col];
                    vx += bv.x; vy += bv.y;
                }
                if (RELU_) { vx = fmaxf(vx, 0.f); vy = fmaxf(vy, 0.f); }
                if (RESID_) {
                    float2 rv = *(const float2*)&Rsd[row * Ncols + col];
                    vx += rv.x; vy += rv.y;
                }
                if (OUTM_ == 0) {
                    *(float2*)&Cf[row * Ncols + col] = make_float2(vx, vy);
                } else {
                    *(uint32_t*)&Ch[row * Ncols + col] = h2bits(vx, vy);
                }
            }
        }
    }
}

// ------------------------------------------------------------------
// Tensor-core attention: one CTA per (b,h). fp16 mma for S=QK^T and O=AV.
// S warp tile 16x32 (8 warps 4x2). smem pitch 144 for fp16 tiles.
// ------------------------------------------------------------------
#define AP 144
__global__ void __launch_bounds__(256)
attn_tc(const __nv_bfloat16* __restrict__ QKh, const __nv_bfloat16* __restrict__ Vmh,
        const float* __restrict__ adj, const float* __restrict__ hw,
        __nv_bfloat16* __restrict__ ATTh) {
    __shared__ __align__(16) char sQ[64 * AP];
    __shared__ __align__(16) char sK[64 * AP];   // also V in phase 2
    __shared__ __align__(16) char sA[64 * AP];   // attn weights fp16
    __shared__ float sS[64][68];

    const int b = blockIdx.x >> 3;
    const int h = blockIdx.x & 7;
    const int tid = threadIdx.x;
    const int wid = tid >> 5;
    const int lane = tid & 31;
    const int wm = (wid >> 1) * 16;   // q tile
    const int wn = (wid & 1) * 32;    // m tile (phase1) / dk tile (phase2)
    const uint32_t uQ = smem_u32(sQ);
    const uint32_t uK = smem_u32(sK);
    const uint32_t uA = smem_u32(sA);

    const int arow = lane & 15;
    const int ainc = lane >> 4;
    const int brow = (lane & 7) + ((lane >> 4) << 3);
    const int binc = (lane >> 3) & 1;
    // trans-B addressing (phase 2)
    const int tkrow = (lane & 7) + (((lane >> 3) & 1) << 3);
    const int tncol = (lane >> 4) * 8;

    const size_t tokBase = (size_t)b * 2048;
    const int lr = tid >> 3;       // 0..31 (two rows per pass)
    const int lc = tid & 7;        // 16B chunk in row

    float acc[4][4];
#pragma unroll
    for (int nt = 0; nt < 4; nt++)
#pragma unroll
        for (int q = 0; q < 4; q++) acc[nt][q] = 0.f;

    // ---- phase 1: S = Q K^T over 32 feature chunks ----
    for (int t0 = 0; t0 < 32; t0++) {
        __syncthreads();
#pragma unroll
        for (int j = 0; j < 2; j++) {
            int r = lr + j * 32;
            const __nv_bfloat16* qsrc = QKh + (tokBase + r * 32 + t0) * 1024 + h * DKn;
            cpasync16(uQ + r * AP + lc * 16, (const char*)qsrc + lc * 16);
            cpasync16(uK + r * AP + lc * 16, (const char*)(qsrc + 512) + lc * 16);
        }
        CP_COMMIT();
        CP_WAIT0();
        __syncthreads();
#pragma unroll
        for (int kc = 0; kc < 4; kc++) {
            uint32_t a[4], bf[4][2];
            LDSM4(a[0], a[1], a[2], a[3], uQ + (wm + arow) * AP + kc * 32 + ainc * 16);
#pragma unroll
            for (int bt = 0; bt < 2; bt++) {
                uint32_t r0, r1, r2, r3;
                LDSM4(r0, r1, r2, r3, uK + (wn + bt * 16 + brow) * AP + kc * 32 + binc * 16);
                bf[2 * bt][0] = r0; bf[2 * bt][1] = r1;
                bf[2 * bt + 1][0] = r2; bf[2 * bt + 1][1] = r3;
            }
#pragma unroll
            for (int nt = 0; nt < 4; nt++) MMA_F16(acc[nt], a, bf[nt]);
        }
    }

    // S -> smem (scaled)
    __syncthreads();
#pragma unroll
    for (int nt = 0; nt < 4; nt++) {
        int col = wn + nt * 8 + (lane & 3) * 2;
#pragma unroll
        for (int half = 0; half < 2; half++) {
            int row = wm + (lane >> 2) + half * 8;
            sS[row][col] = acc[nt][half * 2] * SCALE_F;
            sS[row][col + 1] = acc[nt][half * 2 + 1] * SCALE_F;
        }
    }
    __syncthreads();

    // softmax * hw + adj
    {
        const int w = wid, ln2 = lane;
        const float hwv = hw[h];
        for (int rr = 0; rr < 8; rr++) {
            int row = w * 8 + rr;
            float v0 = sS[row][ln2];
            float v1 = sS[row][ln2 + 32];
            float mx = fmaxf(v0, v1);
#pragma unroll
            for (int o = 16; o; o >>= 1) mx = fmaxf(mx, __shfl_xor_sync(0xffffffffu, mx, o));
            float e0 = __expf(v0 - mx), e1 = __expf(v1 - mx);
            float s = e0 + e1;
#pragma unroll
            for (int o = 16; o; o >>= 1) s += __shfl_xor_sync(0xffffffffu, s, o);
            float inv = 1.f / s;
            size_t ab = (size_t)h * 4096 + row * 64;
            sS[row][ln2]      = e0 * inv * hwv + adj[ab + ln2];
            sS[row][ln2 + 32] = e1 * inv * hwv + adj[ab + 32 + ln2];
        }
    }
    __syncthreads();

    // convert weights to fp16 tile sA[q][m]
    {
        int q = tid >> 2, mb = (tid & 3) * 16;
#pragma unroll
        for (int m = 0; m < 16; m += 2) {
            *(uint32_t*)(sA + q * AP + (mb + m) * 2) = h2bits(sS[q][mb + m], sS[q][mb + m + 1]);
        }
    }

    // ---- phase 2: O = A V per feature chunk ----
    for (int t0 = 0; t0 < 32; t0++) {
        __syncthreads();
#pragma unroll
        for (int j = 0; j < 2; j++) {
            int r = lr + j * 32;
            const __nv_bfloat16* vsrc = Vmh + (tokBase + r * 32 + t0) * 512 + h * DKn;
            cpasync16(uK + r * AP + lc * 16, (const char*)vsrc + lc * 16);
        }
        CP_COMMIT();
        CP_WAIT0();
        __syncthreads();
        float o2[4][4];
#pragma unroll
        for (int nt = 0; nt < 4; nt++)
#pragma unroll
            for (int q = 0; q < 4; q++) o2[nt][q] = 0.f;
#pragma unroll
        for (int kc = 0; kc < 4; kc++) {   // m16 steps
            uint32_t a[4], bf[4][2];
            LDSM4(a[0], a[1], a[2], a[3], uA + (wm + arow) * AP + kc * 32 + ainc * 16);
#pragma unroll
            for (int bt = 0; bt < 2; bt++) {
                uint32_t r0, r1, r2, r3;
                LDSM4T(r0, r1, r2, r3,
                       uK + (kc * 16 + tkrow) * AP + (wn + bt * 16 + tncol) * 2);
                bf[2 * bt][0] = r0; bf[2 * bt][1] = r1;
                bf[2 * bt + 1][0] = r2; bf[2 * bt + 1][1] = r3;
            }
#pragma unroll
            for (int nt = 0; nt < 4; nt++) MMA_F16(o2[nt], a, bf[nt]);
        }
        // write O chunk (fp16)
#pragma unroll
        for (int nt = 0; nt < 4; nt++) {
            int dk = wn + nt * 8 + (lane & 3) * 2;
#pragma unroll
            for (int half = 0; half < 2; half++) {
                int qrow = wm + (lane >> 2) + half * 8;
                size_t off = (tokBase + qrow * 32 + t0) * 512 + h * DKn + dk;
                *(uint32_t*)&ATTh[off] = h2bits(o2[nt][half * 2], o2[nt][half * 2 + 1]);
            }
        }
    }
}

// ------------------------------------------------------------------
// LayerNorm
// ------------------------------------------------------------------
__global__ void ln_partial(const float* __restrict__ Y1, float2* __restrict__ part) {
    const int c = blockIdx.x, b = blockIdx.y;
    const float* p = Y1 + (size_t)b * 1048576 + (size_t)c * 32768;
    float s = 0.f, s2 = 0.f;
    for (int i = threadIdx.x; i < 32768; i += 256) {
        float v = p[i];
        s += v; s2 += v * v;
    }
    __shared__ float rs[256], rs2[256];
    rs[threadIdx.x] = s; rs2[threadIdx.x] = s2;
    __syncthreads();
    for (int o = 128; o; o >>= 1) {
        if (threadIdx.x < o) {
            rs[threadIdx.x] += rs[threadIdx.x + o];
            rs2[threadIdx.x] += rs2[threadIdx.x + o];
        }
        __syncthreads();
    }
    if (threadIdx.x == 0) part[b * 32 + c] = make_float2(rs[0], rs2[0]);
}

__global__ void ln_final(const float2* __restrict__ part, float2* __restrict__ stats) {
    int b = threadIdx.x;
    if (b < Bn) {
        float s = 0.f, s2 = 0.f;
        for (int c = 0; c < 32; c++) {
            float2 p = part[b * 32 + c];
            s += p.x; s2 += p.y;
        }
        const float invN = 1.0f / 1048576.0f;
        float mean = s * invN;
        float var = s2 * invN - mean * mean;
        stats[b] = make_float2(mean, rsqrtf(var + LN_EPS));
    }
}

__global__ void ln_apply(const float* __restrict__ Y1, const float2* __restrict__ stats,
                         const float* __restrict__ g1, const float* __restrict__ be1,
                         float* __restrict__ X1, __nv_bfloat16* __restrict__ X1h) {
    size_t e = ((size_t)blockIdx.x * blockDim.x + threadIdx.x) * 4;
    float2 st = stats[e >> 20];
    size_t gi = e & 1048575;
    float4 y = *(const float4*)&Y1[e];
    float4 g = *(const float4*)&g1[gi];
    float4 be = *(const float4*)&be1[gi];
    float4 o;
    o.x = (y.x - st.x) * st.y * g.x + be.x;
    o.y = (y.y - st.x) * st.y * g.y + be.y;
    o.z = (y.z - st.x) * st.y * g.z + be.z;
    o.w = (y.w - st.x) * st.y * g.w + be.w;
    *(float4*)&X1[e] = o;
    *(uint2*)&X1h[e] = make_uint2(h2bits(o.x, o.y), h2bits(o.z, o.w));
}

// ------------------------------------------------------------------
extern "C" void kernel_launch(void* const* d_in, const int* in_sizes, int n_in,
                              void* d_out, int out_size) {
    const float* x   = (const float*)d_in[0];
    const float* Wq  = (const float*)d_in[1];
    const float* bq  = (const float*)d_in[2];
    const float* Wk  = (const float*)d_in[3];
    const float* bk  = (const float*)d_in[4];
    const float* Wv  = (const float*)d_in[5];
    const float* bv  = (const float*)d_in[6];
    const float* Wo  = (const float*)d_in[7];
    const float* bo  = (const float*)d_in[8];
    const float* W1  = (const float*)d_in[9];
    const float* b1  = (const float*)d_in[10];
    const float* W2  = (const float*)d_in[11];
    const float* b2  = (const float*)d_in[12];
    const float* g1  = (const float*)d_in[13];
    const float* be1 = (const float*)d_in[14];
    const float* adj = (const float*)d_in[15];
    const float* hw  = (const float*)d_in[16];
    const float* pe  = (const float*)d_in[17];
    float* out = (float*)d_out;

#define GETP(sym, ty, name) ty* name; { void* _p; cudaGetSymbolAddress(&_p, sym); name = (ty*)_p; }
    GETP(g_XR, float, XR) GETP(g_Y1, float, Y1) GETP(g_X1, float, X1) GETP(g_FF, float, FFo)
    GETP(g_QKh, __nv_bfloat16, QKh)
    GETP(g_Vmh, __nv_bfloat16, Vmh)
    GETP(g_XRh, __nv_bfloat16, XRh)
    GETP(g_XPEh, __nv_bfloat16, XPEh)
    GETP(g_ATTh, __nv_bfloat16, ATTh)
    GETP(g_X1h, __nv_bfloat16, X1h)
    GETP(g_Hh, __nv_bfloat16, Hh)
    GETP(g_Wqkh, __nv_bfloat16, Wqkh)
    GETP(g_Wvh, __nv_bfloat16, Wvh)
    GETP(g_Woh, __nv_bfloat16, Woh)
    GETP(g_W1h, __nv_bfloat16, W1h)
    GETP(g_W2h, __nv_bfloat16, W2h)
    GETP(g_bqk, float, bqk)
    GETP(g_part, float2, part) GETP(g_stats, float2, stats)
#undef GETP

    cudaFuncSetAttribute(gemm_mma<true, false, false, 2>,
                         cudaFuncAttributeMaxDynamicSharedMemorySize, GEMM_DSMEM);
    cudaFuncSetAttribute(gemm_mma<true, true, false, 2>,
                         cudaFuncAttributeMaxDynamicSharedMemorySize, GEMM_DSMEM);
    cudaFuncSetAttribute(gemm_mma<true, false, true, 0>,
                         cudaFuncAttributeMaxDynamicSharedMemorySize, GEMM_DSMEM);

    // 0. weight conversion
    conv_all<<<3073, 256>>>(Wq, Wk, Wv, Wo, W1, W2, bq, bk);

    // 1. transpose + fp16 conversion
    dim3 trGrid(16, 2, Bn * Tn);
    dim3 trBlk(32, 8);
    prep_xr<<<trGrid, trBlk>>>(x, pe, XR, XRh, XPEh);

    // 2. fused Q+K projection, V projection (fp16 out)
    dim3 gQK(1024 / 128, MTOT / 256);
    gemm_mma<true, false, false, 2><<<gQK, 256, GEMM_DSMEM>>>(
        XPEh, Wqkh, bqk, nullptr, nullptr, QKh, 1024, Dn);
    dim3 gD(Dn / 128, MTOT / 256);
    gemm_mma<true, false, false, 2><<<gD, 256, GEMM_DSMEM>>>(
        XRh, Wvh, bv, nullptr, nullptr, Vmh, Dn, Dn);

    // 3. attention (tensor core)
    attn_tc<<<Bn * Hn, 256>>>(QKh, Vmh, adj, hw, ATTh);

    // 4. output projection + residual
    gemm_mma<true, false, true, 0><<<gD, 256, GEMM_DSMEM>>>(
        ATTh, Woh, bo, XR, Y1, nullptr, Dn, Dn);

    // 5. layernorm
    ln_partial<<<dim3(32, Bn), 256>>>(Y1, part);
    ln_final<<<1, 32>>>(part, stats);
    ln_apply<<<(MTOT * (size_t)Dn / 4) / 256, 256>>>(Y1, stats, g1, be1, X1, X1h);

    // 6. FFN
    dim3 gF1(FFn / 128, MTOT / 256);
    gemm_mma<true, true, false, 2><<<gF1, 256, GEMM_DSMEM>>>(
        X1h, W1h, b1, nullptr, nullptr, Hh, FFn, Dn);
    gemm_mma<true, false, true, 0><<<gD, 256, GEMM_DSMEM>>>(
        Hh, W2h, b2, X1, FFo, nullptr, Dn, FFn);

    // 7. output transpose
    out_tr<<<trGrid, trBlk>>>(FFo, out);
}